// round 11
// baseline (speedup 1.0000x reference)
#include <cuda_runtime.h>
#include <cuda_bf16.h>
#include <math.h>
#include <stdint.h>

#define B_  2
#define L_  2048
#define C_  1024
#define H_  16
#define HD_ 64
#define G_  32
#define CG_ 32
#define N3C (3 * C_)
#define ML  (B_ * L_)   // 4096 rows

typedef __nv_bfloat16 bf16;

// ---------------- scratch (static device globals) ----------------
__device__ float g_stats[B_ * G_ * 2];
__device__ float g_xn[(size_t)ML * C_];           // normalized input fp32 (fallback only)
__device__ bf16  g_xn_bf[(size_t)ML * C_];        // normalized input bf16
__device__ float g_qkv[(size_t)ML * N3C];         // qkv fp32 (fallback only)
__device__ bf16  g_qkv_bf[(size_t)ML * N3C];      // qkv bf16 (feature path)
__device__ float g_att[(size_t)ML * C_];          // attention out fp32 (fallback only)
__device__ bf16  g_att_bf[(size_t)ML * C_];       // attention out bf16
__device__ bf16  g_wqT[(size_t)N3C * C_];         // qkv_w^T bf16 [N,K]
__device__ bf16  g_wpT[(size_t)C_ * C_];          // proj_w^T bf16 [N,K]
__device__ bf16  g_vT[(size_t)B_ * H_ * HD_ * L_]; // V^T [bh][d][key] bf16

// ---------------- helpers ----------------
__device__ __forceinline__ uint32_t smem_u32(const void* p) {
    return (uint32_t)__cvta_generic_to_shared(p);
}

#ifdef __CUDA_ARCH_FEAT_SM103_ALL
__device__ __forceinline__ uint32_t elect_one() {
    uint32_t pred;
    asm volatile("{\n\t.reg .pred p;\n\telect.sync _|p, 0xFFFFFFFF;\n\t"
                 "selp.b32 %0, 1, 0, p;\n\t}" : "=r"(pred));
    return pred;
}
#define TC_ALLOC(smem_addr, ncols) \
    asm volatile("tcgen05.alloc.cta_group::1.sync.aligned.shared::cta.b32 [%0], %1;" \
                 :: "r"(smem_addr), "r"(ncols) : "memory")
#define TC_DEALLOC(tmem, ncols) \
    asm volatile("tcgen05.dealloc.cta_group::1.sync.aligned.b32 %0, %1;" :: "r"(tmem), "r"(ncols))
#define TC_RELINQ() \
    asm volatile("tcgen05.relinquish_alloc_permit.cta_group::1.sync.aligned;")
#define TC_COMMIT(mbar) \
    asm volatile("tcgen05.commit.cta_group::1.mbarrier::arrive::one.shared::cluster.b64 [%0];" \
                 :: "r"(mbar) : "memory")
#define TC_FENCE_AFTER()  asm volatile("tcgen05.fence::after_thread_sync;" ::: "memory")
#define TC_FENCE_BEFORE() asm volatile("tcgen05.fence::before_thread_sync;" ::: "memory")
#define TC_WAIT_LD()      asm volatile("tcgen05.wait::ld.sync.aligned;" ::: "memory")
#define TC_WAIT_ST()      asm volatile("tcgen05.wait::st.sync.aligned;" ::: "memory")
#define MBAR_INIT(mbar, cnt) \
    asm volatile("mbarrier.init.shared.b64 [%0], %1;" :: "r"(mbar), "r"(cnt) : "memory")
#define MBAR_INVAL(mbar) \
    asm volatile("mbarrier.inval.shared.b64 [%0];" :: "r"(mbar) : "memory")
#define FENCE_ASYNC_SHARED() asm volatile("fence.proxy.async.shared::cta;" ::: "memory")

__device__ __forceinline__ void mbar_wait(uint32_t mbar, uint32_t parity) {
    asm volatile(
        "{\n\t.reg .pred P1;\n\t"
        "WAIT_LOOP_%=:\n\t"
        "mbarrier.try_wait.parity.acquire.cta.shared::cta.b64 P1, [%0], %1, 0x989680;\n\t"
        "@P1 bra.uni WAIT_DONE_%=;\n\t"
        "bra.uni WAIT_LOOP_%=;\n\t"
        "WAIT_DONE_%=:\n\t}"
        :: "r"(mbar), "r"(parity) : "memory");
}

__device__ __forceinline__ void tc_mma_f16_ss(uint32_t d_tmem, uint64_t a_desc,
                                              uint64_t b_desc, uint32_t idesc,
                                              uint32_t enable) {
    asm volatile(
        "{\n\t.reg .pred p;\n\tsetp.ne.u32 p, %5, 0;\n\t"
        "tcgen05.mma.cta_group::1.kind::f16 [%0], %1, %2, %3, {%4,%4,%4,%4}, p;\n\t}"
        :: "r"(d_tmem), "l"(a_desc), "l"(b_desc), "r"(idesc), "r"(0u), "r"(enable)
        : "memory");
}
__device__ __forceinline__ void tc_mma_f16_ts(uint32_t d_tmem, uint32_t a_tmem,
                                              uint64_t b_desc, uint32_t idesc,
                                              uint32_t enable) {
    asm volatile(
        "{\n\t.reg .pred p;\n\tsetp.ne.u32 p, %5, 0;\n\t"
        "tcgen05.mma.cta_group::1.kind::f16 [%0], [%1], %2, %3, {%4,%4,%4,%4}, p;\n\t}"
        :: "r"(d_tmem), "r"(a_tmem), "l"(b_desc), "r"(idesc), "r"(0u), "r"(enable)
        : "memory");
}

__device__ __forceinline__ void tc_ld_x32(uint32_t* r, uint32_t tmem_addr) {
    asm volatile(
        "tcgen05.ld.sync.aligned.32x32b.x32.b32 "
        "{%0, %1, %2, %3, %4, %5, %6, %7, %8, %9, %10, %11, %12, %13, %14, %15, "
        " %16, %17, %18, %19, %20, %21, %22, %23, %24, %25, %26, %27, %28, %29, %30, %31}, [%32];"
        : "=r"(r[0]), "=r"(r[1]), "=r"(r[2]), "=r"(r[3]), "=r"(r[4]), "=r"(r[5]),
          "=r"(r[6]), "=r"(r[7]), "=r"(r[8]), "=r"(r[9]), "=r"(r[10]), "=r"(r[11]),
          "=r"(r[12]), "=r"(r[13]), "=r"(r[14]), "=r"(r[15]), "=r"(r[16]), "=r"(r[17]),
          "=r"(r[18]), "=r"(r[19]), "=r"(r[20]), "=r"(r[21]), "=r"(r[22]), "=r"(r[23]),
          "=r"(r[24]), "=r"(r[25]), "=r"(r[26]), "=r"(r[27]), "=r"(r[28]), "=r"(r[29]),
          "=r"(r[30]), "=r"(r[31])
        : "r"(tmem_addr));
}

__device__ __forceinline__ void tc_st_x32(uint32_t tmem_addr, const uint32_t* r) {
    asm volatile(
        "tcgen05.st.sync.aligned.32x32b.x32.b32 [%0], "
        "{%1, %2, %3, %4, %5, %6, %7, %8, %9, %10, %11, %12, %13, %14, %15, %16, "
        " %17, %18, %19, %20, %21, %22, %23, %24, %25, %26, %27, %28, %29, %30, %31, %32};"
        :: "r"(tmem_addr),
           "r"(r[0]), "r"(r[1]), "r"(r[2]), "r"(r[3]), "r"(r[4]), "r"(r[5]),
           "r"(r[6]), "r"(r[7]), "r"(r[8]), "r"(r[9]), "r"(r[10]), "r"(r[11]),
           "r"(r[12]), "r"(r[13]), "r"(r[14]), "r"(r[15]), "r"(r[16]), "r"(r[17]),
           "r"(r[18]), "r"(r[19]), "r"(r[20]), "r"(r[21]), "r"(r[22]), "r"(r[23]),
           "r"(r[24]), "r"(r[25]), "r"(r[26]), "r"(r[27]), "r"(r[28]), "r"(r[29]),
           "r"(r[30]), "r"(r[31])
        : "memory");
}

#define SW128(off) ((off) ^ (((off) >> 3) & 0x70))
__device__ __forceinline__ uint64_t make_desc_sw128(uint32_t base_addr) {
    const uint64_t BASE =
        (uint64_t(2) << 61) | (uint64_t(1) << 46) | (uint64_t(64) << 32) | (uint64_t(1) << 16);
    return BASE | ((uint64_t)(base_addr >> 4) & 0x3FFF);
}
#define IDESC_F16(Mv, Nv) ((1u << 4) | (1u << 7) | (1u << 10) | (((Nv) / 8) << 17) | (((Mv) / 16) << 24))
#define IDESC_128x128 IDESC_F16(128, 128)
#endif  // __CUDA_ARCH_FEAT_SM103_ALL

// ---------------- kernel 1: GroupNorm statistics ----------------
__global__ void gn_stats_kernel(const float* __restrict__ x) {
    int bg = blockIdx.x;
    int b = bg / G_;
    int g = bg % G_;
    const float* xp = x + (size_t)b * L_ * C_ + g * CG_;

    float s = 0.f, s2 = 0.f;
    for (int i = threadIdx.x; i < L_ * CG_ / 4; i += 256) {
        int l = i >> 3;
        int c4 = (i & 7) * 4;
        float4 v = *(const float4*)(xp + (size_t)l * C_ + c4);
        s  += v.x + v.y + v.z + v.w;
        s2 += v.x * v.x + v.y * v.y + v.z * v.z + v.w * v.w;
    }
    #pragma unroll
    for (int o = 16; o > 0; o >>= 1) {
        s  += __shfl_down_sync(0xFFFFFFFFu, s, o);
        s2 += __shfl_down_sync(0xFFFFFFFFu, s2, o);
    }
    __shared__ float sh[2][8];
    int w = threadIdx.x >> 5, ln = threadIdx.x & 31;
    if (ln == 0) { sh[0][w] = s; sh[1][w] = s2; }
    __syncthreads();
    if (w == 0) {
        s  = (ln < 8) ? sh[0][ln] : 0.f;
        s2 = (ln < 8) ? sh[1][ln] : 0.f;
        #pragma unroll
        for (int o = 4; o > 0; o >>= 1) {
            s  += __shfl_down_sync(0xFFFFFFFFu, s, o);
            s2 += __shfl_down_sync(0xFFFFFFFFu, s2, o);
        }
        if (ln == 0) {
            const float inv_n = 1.0f / (float)(L_ * CG_);
            float mu  = s * inv_n;
            float var = s2 * inv_n - mu * mu;
            g_stats[bg * 2 + 0] = mu;
            g_stats[bg * 2 + 1] = rsqrtf(var + 1e-6f);
        }
    }
}

// ---------------- kernel 2: apply GroupNorm ----------------
__global__ void gn_apply_kernel(const float* __restrict__ x,
                                const float* __restrict__ gamma,
                                const float* __restrict__ beta) {
    size_t i = (size_t)blockIdx.x * blockDim.x + threadIdx.x;
    size_t base = i * 4;
    if (base >= (size_t)ML * C_) return;
    int c  = (int)(base % C_);
    int bl = (int)(base / C_);
    int b  = bl >> 11;
    int g  = c >> 5;
    float mu = g_stats[(b * G_ + g) * 2 + 0];
    float rs = g_stats[(b * G_ + g) * 2 + 1];
    float4 xv = *(const float4*)(x + base);
    float4 gv = *(const float4*)(gamma + c);
    float4 bv = *(const float4*)(beta + c);
    float4 r;
    r.x = (xv.x - mu) * rs * gv.x + bv.x;
    r.y = (xv.y - mu) * rs * gv.y + bv.y;
    r.z = (xv.z - mu) * rs * gv.z + bv.z;
    r.w = (xv.w - mu) * rs * gv.w + bv.w;
#ifndef __CUDA_ARCH_FEAT_SM103_ALL
    *(float4*)(g_xn + base) = r;     // fallback GEMM input only
#endif
    ((__nv_bfloat162*)g_xn_bf)[2 * i]     = __floats2bfloat162_rn(r.x, r.y);
    ((__nv_bfloat162*)g_xn_bf)[2 * i + 1] = __floats2bfloat162_rn(r.z, r.w);
}

// ---------------- weight transpose + convert ----------------
__global__ void wtrans_kernel(const float* __restrict__ src, int K, int N, int which) {
    __shared__ float tile[32][33];
    int n0 = blockIdx.x * 32, k0 = blockIdx.y * 32;
    int tx = threadIdx.x, ty = threadIdx.y;
    #pragma unroll
    for (int i = 0; i < 32; i += 8)
        tile[ty + i][tx] = src[(size_t)(k0 + ty + i) * N + n0 + tx];
    __syncthreads();
    bf16* dst = which ? g_wpT : g_wqT;
    #pragma unroll
    for (int i = 0; i < 32; i += 8)
        dst[(size_t)(n0 + ty + i) * K + k0 + tx] = __float2bfloat16(tile[tx][ty + i]);
}

// ---------------- V^T transpose (feature path) ----------------
__global__ void vtrans_kernel() {
#ifdef __CUDA_ARCH_FEAT_SM103_ALL
    __shared__ unsigned short tile[32][33];
    int l0 = blockIdx.x * 32;
    int d0 = blockIdx.y * 32;
    int bh = blockIdx.z;
    int b = bh >> 4, h = bh & 15;
    int tx = threadIdx.x, ty = threadIdx.y;
    const unsigned short* src = (const unsigned short*)g_qkv_bf
        + (size_t)b * L_ * N3C + h * (3 * HD_) + 2 * HD_;
    #pragma unroll
    for (int i = 0; i < 32; i += 8)
        tile[ty + i][tx] = src[(size_t)(l0 + ty + i) * N3C + d0 + tx];
    __syncthreads();
    unsigned short* dst = (unsigned short*)g_vT + (size_t)bh * HD_ * L_;
    #pragma unroll
    for (int i = 0; i < 32; i += 8)
        dst[(size_t)(d0 + ty + i) * L_ + l0 + tx] = tile[tx][ty + i];
#endif
}

// ---------------- kernel 3/5: GEMM, dual path ----------------
template <int EPI>
__global__ __launch_bounds__(256) void gemm_kernel(
    const float* __restrict__ W,
    const float* __restrict__ bias,
    const float* __restrict__ resid,
    float*       __restrict__ OutParam,
    int N, int K)
{
    const float rsqrt2 = 0.70710678118654752f;
    int tid = threadIdx.x;
    int bm = blockIdx.y * 128;
    int bn = blockIdx.x * 128;

#ifdef __CUDA_ARCH_FEAT_SM103_ALL
    __shared__ __align__(1024) bf16 sA[2][128 * 64];
    __shared__ __align__(1024) bf16 sB[2][128 * 64];
    __shared__ float bias_s[128];
    __shared__ __align__(8) uint64_t mbar_store[2];
    __shared__ uint32_t tmem_ptr_store;

    const bf16* A  = (EPI == 0) ? g_xn_bf : g_att_bf;
    const bf16* WT = (EPI == 0) ? g_wqT   : g_wpT;

    int wid = tid >> 5;
    int lane = tid & 31;
    uint32_t mbar0 = smem_u32(&mbar_store[0]);
    uint32_t mbar1 = smem_u32(&mbar_store[1]);
    uint32_t tptr_addr = smem_u32(&tmem_ptr_store);

    if (wid == 0) TC_ALLOC(tptr_addr, 128);
    if (tid == 0) { MBAR_INIT(mbar0, 1); MBAR_INIT(mbar1, 1); }
    if (tid < 128) bias_s[tid] = bias[bn + tid];
    __syncthreads();
    uint32_t tmem_base;
    asm volatile("ld.shared.b32 %0, [%1];" : "=r"(tmem_base) : "r"(tptr_addr));

    uint64_t a_desc[2] = { make_desc_sw128(smem_u32(sA[0])), make_desc_sw128(smem_u32(sA[1])) };
    uint64_t b_desc[2] = { make_desc_sw128(smem_u32(sB[0])), make_desc_sw128(smem_u32(sB[1])) };

    const int NCHUNK = K / 64;
    for (int ch = 0; ch < NCHUNK; ch++) {
        int buf = ch & 1;
        uint32_t mb = buf ? mbar1 : mbar0;
        if (ch >= 2) mbar_wait(mb, (uint32_t)(((ch >> 1) - 1) & 1));

        int k0 = ch * 64;
        #pragma unroll
        for (int t = 0; t < 4; t++) {
            int i = t * 256 + tid;
            int r = i >> 3;
            int c8 = (i & 7) * 8;
            uint32_t sw = SW128((uint32_t)(r * 128 + c8 * 2));
            *(uint4*)((char*)sA[buf] + sw) = *(const uint4*)(A  + (size_t)(bm + r) * K + k0 + c8);
            *(uint4*)((char*)sB[buf] + sw) = *(const uint4*)(WT + (size_t)(bn + r) * K + k0 + c8);
        }
        FENCE_ASYNC_SHARED();
        __syncthreads();

        if (wid == 0 && elect_one()) {
            #pragma unroll
            for (int ks = 0; ks < 4; ks++) {
                uint32_t en = (ch > 0 || ks > 0) ? 1u : 0u;
                tc_mma_f16_ss(tmem_base, a_desc[buf] + ks * 2, b_desc[buf] + ks * 2,
                              IDESC_128x128, en);
            }
            TC_COMMIT(mb);
        }
    }

    mbar_wait(mbar1, 1u);
    TC_FENCE_AFTER();

    {
        int row = bm + (wid & 3) * 32 + lane;
        int chalf = (wid >> 2) * 64;
        #pragma unroll
        for (int cc = 0; cc < 2; cc++) {
            uint32_t d[32];
            tc_ld_x32(d, tmem_base + chalf + cc * 32);
            TC_WAIT_LD();
            int colbase = bn + chalf + cc * 32;
            #pragma unroll
            for (int j = 0; j < 8; j++) {
                float4 v;
                v.x = __uint_as_float(d[4 * j + 0]) + bias_s[chalf + cc * 32 + 4 * j + 0];
                v.y = __uint_as_float(d[4 * j + 1]) + bias_s[chalf + cc * 32 + 4 * j + 1];
                v.z = __uint_as_float(d[4 * j + 2]) + bias_s[chalf + cc * 32 + 4 * j + 2];
                v.w = __uint_as_float(d[4 * j + 3]) + bias_s[chalf + cc * 32 + 4 * j + 3];
                if (EPI == 1) {
                    float4 rv = *(const float4*)(resid + (size_t)row * N + colbase + 4 * j);
                    v.x = (v.x + rv.x) * rsqrt2;
                    v.y = (v.y + rv.y) * rsqrt2;
                    v.z = (v.z + rv.z) * rsqrt2;
                    v.w = (v.w + rv.w) * rsqrt2;
                    *(float4*)(OutParam + (size_t)row * N + colbase + 4 * j) = v;
                } else {
                    __nv_bfloat162 lo = __floats2bfloat162_rn(v.x, v.y);
                    __nv_bfloat162 hi = __floats2bfloat162_rn(v.z, v.w);
                    uint2 pk = make_uint2(*(uint32_t*)&lo, *(uint32_t*)&hi);
                    *(uint2*)(g_qkv_bf + (size_t)row * N + colbase + 4 * j) = pk;
                }
            }
        }
    }
    TC_FENCE_BEFORE();
    __syncthreads();
    if (tid == 0) { MBAR_INVAL(mbar0); MBAR_INVAL(mbar1); }
    __syncthreads();
    if (wid == 0) {
        TC_RELINQ();
        TC_DEALLOC(tmem_base, 128);
    }
#else
    // fp32 FFMA fallback (R3-proven)
    const float* A = (EPI == 0) ? g_xn : g_att;
    float* Cout    = (EPI == 0) ? g_qkv : OutParam;

    __shared__ float As[8][128];
    __shared__ float Bs[8][128];

    int tx = tid & 15;
    int ty = tid >> 4;

    float acc[8][8];
    #pragma unroll
    for (int i = 0; i < 8; i++)
        #pragma unroll
        for (int j = 0; j < 8; j++) acc[i][j] = 0.f;

    int arow = tid >> 1;
    int acol = (tid & 1) * 4;
    int brow = tid >> 5;
    int bcol = (tid & 31) * 4;

    const float* Aptr = A + (size_t)(bm + arow) * K + acol;
    const float* Bptr = W + (size_t)brow * N + bn + bcol;

    for (int k0 = 0; k0 < K; k0 += 8) {
        float4 av = *(const float4*)(Aptr + k0);
        float4 bv = *(const float4*)(Bptr + (size_t)k0 * N);
        As[acol + 0][arow] = av.x;
        As[acol + 1][arow] = av.y;
        As[acol + 2][arow] = av.z;
        As[acol + 3][arow] = av.w;
        *(float4*)&Bs[brow][bcol] = bv;
        __syncthreads();
        #pragma unroll
        for (int kk = 0; kk < 8; kk++) {
            float a[8], b[8];
            #pragma unroll
            for (int i = 0; i < 8; i++) a[i] = As[kk][ty * 8 + i];
            #pragma unroll
            for (int i = 0; i < 8; i++) b[i] = Bs[kk][tx * 8 + i];
            #pragma unroll
            for (int i = 0; i < 8; i++)
                #pragma unroll
                for (int j = 0; j < 8; j++)
                    acc[i][j] += a[i] * b[j];
        }
        __syncthreads();
    }

    #pragma unroll
    for (int i = 0; i < 8; i++) {
        int row = bm + ty * 8 + i;
        #pragma unroll
        for (int j = 0; j < 8; j += 4) {
            int col = bn + tx * 8 + j;
            float4 bb = *(const float4*)(bias + col);
            float4 v;
            v.x = acc[i][j + 0] + bb.x;
            v.y = acc[i][j + 1] + bb.y;
            v.z = acc[i][j + 2] + bb.z;
            v.w = acc[i][j + 3] + bb.w;
            if (EPI == 1) {
                float4 rv = *(const float4*)(resid + (size_t)row * N + col);
                v.x = (v.x + rv.x) * rsqrt2;
                v.y = (v.y + rv.y) * rsqrt2;
                v.z = (v.z + rv.z) * rsqrt2;
                v.w = (v.w + rv.w) * rsqrt2;
            }
            *(float4*)(Cout + (size_t)row * N + col) = v;
        }
    }
#endif
}

// ---------------- kernel 4: flash attention, dual path ----------------
__global__ __launch_bounds__(128) void flash_kernel() {
    int bh = blockIdx.y;
    int b = bh >> 4;
    int h = bh & 15;
    int tid = threadIdx.x;

#ifdef __CUDA_ARCH_FEAT_SM103_ALL
    // ============ tcgen05 attention: SS Q, 256 TMEM cols -> 2 CTAs/SM ============
    __shared__ __align__(1024) bf16 sQ[128 * 64];    // Q [rows][dims] SW128
    __shared__ __align__(1024) bf16 sK[128 * 64];    // K chunk [keys][dims] SW128
    __shared__ __align__(1024) bf16 sV[64 * 128];    // V^T chunk [dims][keys] blocked SW128
    __shared__ __align__(8) uint64_t mbar_store[2];  // S, O
    __shared__ uint32_t tmem_ptr_store;

    int wid = tid >> 5;
    int bm = blockIdx.x * 128;

    uint32_t mbarS = smem_u32(&mbar_store[0]);
    uint32_t mbarO = smem_u32(&mbar_store[1]);
    uint32_t tptr_addr = smem_u32(&tmem_ptr_store);

    if (wid == 0) TC_ALLOC(tptr_addr, 256);
    if (tid == 0) { MBAR_INIT(mbarS, 1); MBAR_INIT(mbarO, 1); }
    __syncthreads();
    uint32_t tmem_base;
    asm volatile("ld.shared.b32 %0, [%1];" : "=r"(tmem_base) : "r"(tptr_addr));

    const uint32_t S0 = tmem_base + 0;      // S: 128 cols fp32
    const uint32_t P0 = tmem_base + 128;    // P: 64 cols bf16x2
    const uint32_t O0 = tmem_base + 192;    // O: 64 cols fp32

    const bf16* qkvb = g_qkv_bf + (size_t)b * L_ * N3C + h * (3 * HD_);

    uint64_t q_desc = make_desc_sw128(smem_u32(sQ));
    uint64_t k_desc = make_desc_sw128(smem_u32(sK));
    uint64_t v_desc = make_desc_sw128(smem_u32(sV));
    const uint32_t IDESC_S = IDESC_F16(128, 128);
    const uint32_t IDESC_O = IDESC_F16(128, 64);

    // ---- prologue: load Q + K[0], issue S(0) ----
    #pragma unroll
    for (int t = 0; t < 8; t++) {
        int i = t * 128 + tid;
        int r = i >> 3;
        int c8 = (i & 7) * 8;
        uint32_t sw = SW128((uint32_t)(r * 128 + c8 * 2));
        *(uint4*)((char*)sQ + sw) = *(const uint4*)(qkvb + (size_t)(bm + r) * N3C + c8);
        *(uint4*)((char*)sK + sw) = *(const uint4*)(qkvb + HD_ + (size_t)r * N3C + c8);
    }
    FENCE_ASYNC_SHARED();
    __syncthreads();
    if (wid == 0 && elect_one()) {
        #pragma unroll
        for (int ks = 0; ks < 4; ks++)
            tc_mma_f16_ss(S0, q_desc + ks * 2, k_desc + ks * 2, IDESC_S, ks > 0);
        TC_COMMIT(mbarS);
    }

    float lsum = 0.f;
    const unsigned short* vT = (const unsigned short*)g_vT + (size_t)bh * HD_ * L_;
    const float SCALE_LOG2E = 0.125f * 1.44269504088896f;
    uint32_t woff = (uint32_t)wid << 21;

    for (int ch = 0; ch < 16; ch++) {
        // ---- S(ch) ready ----
        mbar_wait(mbarS, (uint32_t)(ch & 1));
        TC_FENCE_AFTER();

        // ---- half 0: LDTM cols 0..63 ----
        uint32_t p0[32];
        {
            uint32_t sr0[64];
            tc_ld_x32(sr0, S0);
            tc_ld_x32(sr0 + 32, S0 + 32);
            TC_WAIT_LD();

            // O(ch-1) guard before sV / P overwrite; V LDGs in flight during exp
            if (ch > 0) mbar_wait(mbarO, (uint32_t)((ch - 1) & 1));
            #pragma unroll
            for (int t = 0; t < 8; t++) {
                int i = t * 128 + tid;
                int d = i >> 4;
                int kk = (i & 15) * 8;
                int atom_col = kk >> 6;
                int inner_col = kk & 63;
                uint32_t off = (uint32_t)(((d >> 3) + atom_col * 8) * 1024 + (d & 7) * 128 + inner_col * 2);
                uint32_t sw = SW128(off);
                *(uint4*)((char*)sV + sw) = *(const uint4*)(vT + (size_t)d * L_ + ch * 128 + kk);
            }

            #pragma unroll
            for (int j = 0; j < 32; j++) {
                float e0 = exp2f(__uint_as_float(sr0[2 * j + 0]) * SCALE_LOG2E);
                float e1 = exp2f(__uint_as_float(sr0[2 * j + 1]) * SCALE_LOG2E);
                lsum += e0 + e1;
                __nv_bfloat162 pk = __floats2bfloat162_rn(e0, e1);
                p0[j] = *(uint32_t*)&pk;
            }
        }

        // ---- half 1: LDTM cols 64..127 ----
        uint32_t p1[32];
        {
            uint32_t sr1[64];
            tc_ld_x32(sr1, S0 + 64);
            tc_ld_x32(sr1 + 32, S0 + 96);
            TC_WAIT_LD();
            #pragma unroll
            for (int j = 0; j < 32; j++) {
                float e0 = exp2f(__uint_as_float(sr1[2 * j + 0]) * SCALE_LOG2E);
                float e1 = exp2f(__uint_as_float(sr1[2 * j + 1]) * SCALE_LOG2E);
                lsum += e0 + e1;
                __nv_bfloat162 pk = __floats2bfloat162_rn(e0, e1);
                p1[j] = *(uint32_t*)&pk;
            }
        }

        // ---- K[ch+1] load + issue S(ch+1): S fully read by all warps by next sync ----
        if (ch < 15) {
            #pragma unroll
            for (int t = 0; t < 8; t++) {
                int i = t * 128 + tid;
                int r = i >> 3;
                int c8 = (i & 7) * 8;
                uint32_t sw = SW128((uint32_t)(r * 128 + c8 * 2));
                *(uint4*)((char*)sK + sw) =
                    *(const uint4*)(qkvb + HD_ + (size_t)((ch + 1) * 128 + r) * N3C + c8);
            }
            FENCE_ASYNC_SHARED();
            __syncthreads();
            if (wid == 0 && elect_one()) {
                #pragma unroll
                for (int ks = 0; ks < 4; ks++)
                    tc_mma_f16_ss(S0, q_desc + ks * 2, k_desc + ks * 2, IDESC_S, ks > 0);
                TC_COMMIT(mbarS);
            }
        }

        // ---- P to TMEM, O += P @ V^T ----
        tc_st_x32(P0 + woff, p0);
        tc_st_x32(P0 + 32 + woff, p1);
        TC_WAIT_ST();
        FENCE_ASYNC_SHARED();
        TC_FENCE_BEFORE();
        __syncthreads();
        if (wid == 0 && elect_one()) {
            TC_FENCE_AFTER();
            #pragma unroll
            for (int s8 = 0; s8 < 8; s8++) {
                uint64_t boff = (uint64_t)((s8 >> 2) * 512 + (s8 & 3) * 2);
                tc_mma_f16_ts(O0, P0 + s8 * 8, v_desc + boff, IDESC_O,
                              (ch > 0 || s8 > 0));
            }
            TC_COMMIT(mbarO);
        }
        __syncthreads();
    }

    // ---- epilogue ----
    mbar_wait(mbarO, 1u);
    TC_FENCE_AFTER();
    {
        uint32_t d0[32], d1[32];
        tc_ld_x32(d0, O0);
        tc_ld_x32(d1, O0 + 32);
        TC_WAIT_LD();
        float inv = 1.f / lsum;
        bf16* op = g_att_bf + (size_t)(b * L_ + bm + tid) * C_ + h * HD_;
        #pragma unroll
        for (int j = 0; j < 16; j++) {
            __nv_bfloat162 a = __floats2bfloat162_rn(
                __uint_as_float(d0[2 * j]) * inv, __uint_as_float(d0[2 * j + 1]) * inv);
            ((__nv_bfloat162*)op)[j] = a;
        }
        #pragma unroll
        for (int j = 0; j < 16; j++) {
            __nv_bfloat162 a = __floats2bfloat162_rn(
                __uint_as_float(d1[2 * j]) * inv, __uint_as_float(d1[2 * j + 1]) * inv);
            ((__nv_bfloat162*)op)[16 + j] = a;
        }
    }
    TC_FENCE_BEFORE();
    __syncthreads();
    if (tid == 0) { MBAR_INVAL(mbarS); MBAR_INVAL(mbarO); }
    __syncthreads();
    if (wid == 0) {
        TC_RELINQ();
        TC_DEALLOC(tmem_base, 256);
    }
#else
    // ============ scalar fallback (R3-proven) ============
    __shared__ float Ks[32 * 64];
    __shared__ float Vs[32 * 64];

    int qrow = blockIdx.x * 128 + tid;

    const float* base = g_qkv + (size_t)b * L_ * N3C;
    const float* qptr = base + (size_t)qrow * N3C + h * (3 * HD_);
    const float* kbase = base + h * (3 * HD_) + HD_;
    const float* vbase = base + h * (3 * HD_) + 2 * HD_;

    float q[HD_];
    #pragma unroll
    for (int d4 = 0; d4 < HD_ / 4; d4++) {
        float4 t = *(const float4*)(qptr + d4 * 4);
        q[4 * d4 + 0] = t.x * 0.125f;
        q[4 * d4 + 1] = t.y * 0.125f;
        q[4 * d4 + 2] = t.z * 0.125f;
        q[4 * d4 + 3] = t.w * 0.125f;
    }
    float o[HD_];
    #pragma unroll
    for (int d = 0; d < HD_; d++) o[d] = 0.f;
    float m = -1e30f, l = 0.f;

    for (int kb = 0; kb < L_ / 32; kb++) {
        __syncthreads();
        #pragma unroll
        for (int t = 0; t < 4; t++) {
            int idx = t * 128 + tid;
            int r = idx >> 4;
            int c4 = (idx & 15) * 4;
            size_t goff = (size_t)(kb * 32 + r) * N3C + c4;
            *(float4*)&Ks[r * 64 + c4] = *(const float4*)(kbase + goff);
            *(float4*)&Vs[r * 64 + c4] = *(const float4*)(vbase + goff);
        }
        __syncthreads();

        float s[32];
        #pragma unroll
        for (int j = 0; j < 32; j++) {
            float accv = 0.f;
            #pragma unroll
            for (int d = 0; d < HD_; d++) accv += q[d] * Ks[j * 64 + d];
            s[j] = accv;
        }
        float mnew = m;
        #pragma unroll
        for (int j = 0; j < 32; j++) mnew = fmaxf(mnew, s[j]);
        float corr = __expf(m - mnew);
        l *= corr;
        #pragma unroll
        for (int d = 0; d < HD_; d++) o[d] *= corr;
        #pragma unroll
        for (int j = 0; j < 32; j++) {
            float pp = __expf(s[j] - mnew);
            l += pp;
            #pragma unroll
            for (int d = 0; d < HD_; d++) o[d] += pp * Vs[j * 64 + d];
        }
        m = mnew;
    }

    float inv = 1.f / l;
    size_t obase = (size_t)(b * L_ + qrow) * C_ + h * HD_;
    float* opf = g_att + obase;
    bf16* opb = g_att_bf + obase;
    #pragma unroll
    for (int d4 = 0; d4 < HD_ / 4; d4++) {
        float4 t;
        t.x = o[4 * d4 + 0] * inv;
        t.y = o[4 * d4 + 1] * inv;
        t.z = o[4 * d4 + 2] * inv;
        t.w = o[4 * d4 + 3] * inv;
        *(float4*)(opf + 4 * d4) = t;
        ((__nv_bfloat162*)opb)[2 * d4]     = __floats2bfloat162_rn(t.x, t.y);
        ((__nv_bfloat162*)opb)[2 * d4 + 1] = __floats2bfloat162_rn(t.z, t.w);
    }
#endif
}

// ---------------- launcher ----------------
extern "C" void kernel_launch(void* const* d_in, const int* in_sizes, int n_in,
                              void* d_out, int out_size) {
    const float* x        = (const float*)d_in[0];
    const float* gn_scale = (const float*)d_in[1];
    const float* gn_bias  = (const float*)d_in[2];
    const float* qkv_w    = (const float*)d_in[3];
    const float* qkv_b    = (const float*)d_in[4];
    const float* proj_w   = (const float*)d_in[5];
    const float* proj_b   = (const float*)d_in[6];
    float* out = (float*)d_out;

    // 0) transpose+convert weights
    {
        dim3 blk(32, 8);
        dim3 gq(N3C / 32, C_ / 32);
        wtrans_kernel<<<gq, blk>>>(qkv_w, C_, N3C, 0);
        dim3 gp(C_ / 32, C_ / 32);
        wtrans_kernel<<<gp, blk>>>(proj_w, C_, C_, 1);
    }

    // 1) GroupNorm stats
    gn_stats_kernel<<<B_ * G_, 256>>>(x);

    // 2) apply GroupNorm
    {
        int total4 = ML * C_ / 4;
        gn_apply_kernel<<<(total4 + 255) / 256, 256>>>(x, gn_scale, gn_bias);
    }

    // 3) QKV GEMM
    {
        dim3 grid(N3C / 128, ML / 128);
        gemm_kernel<0><<<grid, 256>>>(qkv_w, qkv_b, nullptr, nullptr, N3C, C_);
    }

    // 3.5) V^T transpose (feature path)
    {
        dim3 blk(32, 8);
        dim3 gv(L_ / 32, HD_ / 32, B_ * H_);
        vtrans_kernel<<<gv, blk>>>();
    }

    // 4) flash attention
    {
        dim3 grid(L_ / 128, B_ * H_);
        flash_kernel<<<grid, 128>>>();
    }

    // 5) proj GEMM + residual
    {
        dim3 grid(C_ / 128, ML / 128);
        gemm_kernel<1><<<grid, 256>>>(proj_w, proj_b, x, out, C_, C_);
    }
}

// round 12
// speedup vs baseline: 1.1125x; 1.1125x over previous
#include <cuda_runtime.h>
#include <cuda_bf16.h>
#include <math.h>
#include <stdint.h>

#define B_  2
#define L_  2048
#define C_  1024
#define H_  16
#define HD_ 64
#define G_  32
#define CG_ 32
#define N3C (3 * C_)
#define ML  (B_ * L_)   // 4096 rows

typedef __nv_bfloat16 bf16;

// ---------------- scratch (static device globals) ----------------
__device__ float g_stats[B_ * G_ * 2];
__device__ float g_xn[(size_t)ML * C_];           // normalized input fp32 (fallback only)
__device__ bf16  g_xn_bf[(size_t)ML * C_];        // normalized input bf16
__device__ float g_qkv[(size_t)ML * N3C];         // qkv fp32 (fallback only)
__device__ bf16  g_qkv_bf[(size_t)ML * N3C];      // qkv bf16 (feature path)
__device__ float g_att[(size_t)ML * C_];          // attention out fp32 (fallback only)
__device__ bf16  g_att_bf[(size_t)ML * C_];       // attention out bf16
__device__ bf16  g_wqT[(size_t)N3C * C_];         // qkv_w^T bf16 [N,K]
__device__ bf16  g_wpT[(size_t)C_ * C_];          // proj_w^T bf16 [N,K]
__device__ bf16  g_vT[(size_t)B_ * H_ * HD_ * L_]; // V^T [bh][d][key] bf16

// ---------------- helpers ----------------
__device__ __forceinline__ uint32_t smem_u32(const void* p) {
    return (uint32_t)__cvta_generic_to_shared(p);
}

#ifdef __CUDA_ARCH_FEAT_SM103_ALL
__device__ __forceinline__ uint32_t elect_one() {
    uint32_t pred;
    asm volatile("{\n\t.reg .pred p;\n\telect.sync _|p, 0xFFFFFFFF;\n\t"
                 "selp.b32 %0, 1, 0, p;\n\t}" : "=r"(pred));
    return pred;
}
#define TC_ALLOC(smem_addr, ncols) \
    asm volatile("tcgen05.alloc.cta_group::1.sync.aligned.shared::cta.b32 [%0], %1;" \
                 :: "r"(smem_addr), "r"(ncols) : "memory")
#define TC_DEALLOC(tmem, ncols) \
    asm volatile("tcgen05.dealloc.cta_group::1.sync.aligned.b32 %0, %1;" :: "r"(tmem), "r"(ncols))
#define TC_RELINQ() \
    asm volatile("tcgen05.relinquish_alloc_permit.cta_group::1.sync.aligned;")
#define TC_COMMIT(mbar) \
    asm volatile("tcgen05.commit.cta_group::1.mbarrier::arrive::one.shared::cluster.b64 [%0];" \
                 :: "r"(mbar) : "memory")
#define TC_FENCE_AFTER()  asm volatile("tcgen05.fence::after_thread_sync;" ::: "memory")
#define TC_FENCE_BEFORE() asm volatile("tcgen05.fence::before_thread_sync;" ::: "memory")
#define TC_WAIT_LD()      asm volatile("tcgen05.wait::ld.sync.aligned;" ::: "memory")
#define TC_WAIT_ST()      asm volatile("tcgen05.wait::st.sync.aligned;" ::: "memory")
#define MBAR_INIT(mbar, cnt) \
    asm volatile("mbarrier.init.shared.b64 [%0], %1;" :: "r"(mbar), "r"(cnt) : "memory")
#define MBAR_INVAL(mbar) \
    asm volatile("mbarrier.inval.shared.b64 [%0];" :: "r"(mbar) : "memory")
#define FENCE_ASYNC_SHARED() asm volatile("fence.proxy.async.shared::cta;" ::: "memory")

__device__ __forceinline__ void mbar_wait(uint32_t mbar, uint32_t parity) {
    asm volatile(
        "{\n\t.reg .pred P1;\n\t"
        "WAIT_LOOP_%=:\n\t"
        "mbarrier.try_wait.parity.acquire.cta.shared::cta.b64 P1, [%0], %1, 0x989680;\n\t"
        "@P1 bra.uni WAIT_DONE_%=;\n\t"
        "bra.uni WAIT_LOOP_%=;\n\t"
        "WAIT_DONE_%=:\n\t}"
        :: "r"(mbar), "r"(parity) : "memory");
}

__device__ __forceinline__ void tc_mma_f16_ss(uint32_t d_tmem, uint64_t a_desc,
                                              uint64_t b_desc, uint32_t idesc,
                                              uint32_t enable) {
    asm volatile(
        "{\n\t.reg .pred p;\n\tsetp.ne.u32 p, %5, 0;\n\t"
        "tcgen05.mma.cta_group::1.kind::f16 [%0], %1, %2, %3, {%4,%4,%4,%4}, p;\n\t}"
        :: "r"(d_tmem), "l"(a_desc), "l"(b_desc), "r"(idesc), "r"(0u), "r"(enable)
        : "memory");
}
__device__ __forceinline__ void tc_mma_f16_ts(uint32_t d_tmem, uint32_t a_tmem,
                                              uint64_t b_desc, uint32_t idesc,
                                              uint32_t enable) {
    asm volatile(
        "{\n\t.reg .pred p;\n\tsetp.ne.u32 p, %5, 0;\n\t"
        "tcgen05.mma.cta_group::1.kind::f16 [%0], [%1], %2, %3, {%4,%4,%4,%4}, p;\n\t}"
        :: "r"(d_tmem), "r"(a_tmem), "l"(b_desc), "r"(idesc), "r"(0u), "r"(enable)
        : "memory");
}

__device__ __forceinline__ void tc_ld_x32(uint32_t* r, uint32_t tmem_addr) {
    asm volatile(
        "tcgen05.ld.sync.aligned.32x32b.x32.b32 "
        "{%0, %1, %2, %3, %4, %5, %6, %7, %8, %9, %10, %11, %12, %13, %14, %15, "
        " %16, %17, %18, %19, %20, %21, %22, %23, %24, %25, %26, %27, %28, %29, %30, %31}, [%32];"
        : "=r"(r[0]), "=r"(r[1]), "=r"(r[2]), "=r"(r[3]), "=r"(r[4]), "=r"(r[5]),
          "=r"(r[6]), "=r"(r[7]), "=r"(r[8]), "=r"(r[9]), "=r"(r[10]), "=r"(r[11]),
          "=r"(r[12]), "=r"(r[13]), "=r"(r[14]), "=r"(r[15]), "=r"(r[16]), "=r"(r[17]),
          "=r"(r[18]), "=r"(r[19]), "=r"(r[20]), "=r"(r[21]), "=r"(r[22]), "=r"(r[23]),
          "=r"(r[24]), "=r"(r[25]), "=r"(r[26]), "=r"(r[27]), "=r"(r[28]), "=r"(r[29]),
          "=r"(r[30]), "=r"(r[31])
        : "r"(tmem_addr));
}

__device__ __forceinline__ void tc_st_x32(uint32_t tmem_addr, const uint32_t* r) {
    asm volatile(
        "tcgen05.st.sync.aligned.32x32b.x32.b32 [%0], "
        "{%1, %2, %3, %4, %5, %6, %7, %8, %9, %10, %11, %12, %13, %14, %15, %16, "
        " %17, %18, %19, %20, %21, %22, %23, %24, %25, %26, %27, %28, %29, %30, %31, %32};"
        :: "r"(tmem_addr),
           "r"(r[0]), "r"(r[1]), "r"(r[2]), "r"(r[3]), "r"(r[4]), "r"(r[5]),
           "r"(r[6]), "r"(r[7]), "r"(r[8]), "r"(r[9]), "r"(r[10]), "r"(r[11]),
           "r"(r[12]), "r"(r[13]), "r"(r[14]), "r"(r[15]), "r"(r[16]), "r"(r[17]),
           "r"(r[18]), "r"(r[19]), "r"(r[20]), "r"(r[21]), "r"(r[22]), "r"(r[23]),
           "r"(r[24]), "r"(r[25]), "r"(r[26]), "r"(r[27]), "r"(r[28]), "r"(r[29]),
           "r"(r[30]), "r"(r[31])
        : "memory");
}

#define SW128(off) ((off) ^ (((off) >> 3) & 0x70))
__device__ __forceinline__ uint64_t make_desc_sw128(uint32_t base_addr) {
    const uint64_t BASE =
        (uint64_t(2) << 61) | (uint64_t(1) << 46) | (uint64_t(64) << 32) | (uint64_t(1) << 16);
    return BASE | ((uint64_t)(base_addr >> 4) & 0x3FFF);
}
#define IDESC_F16(Mv, Nv) ((1u << 4) | (1u << 7) | (1u << 10) | (((Nv) / 8) << 17) | (((Mv) / 16) << 24))
#define IDESC_128x128 IDESC_F16(128, 128)
#endif  // __CUDA_ARCH_FEAT_SM103_ALL

// ---------------- kernel 1: GroupNorm statistics ----------------
__global__ void gn_stats_kernel(const float* __restrict__ x) {
    int bg = blockIdx.x;
    int b = bg / G_;
    int g = bg % G_;
    const float* xp = x + (size_t)b * L_ * C_ + g * CG_;

    float s = 0.f, s2 = 0.f;
    for (int i = threadIdx.x; i < L_ * CG_ / 4; i += 256) {
        int l = i >> 3;
        int c4 = (i & 7) * 4;
        float4 v = *(const float4*)(xp + (size_t)l * C_ + c4);
        s  += v.x + v.y + v.z + v.w;
        s2 += v.x * v.x + v.y * v.y + v.z * v.z + v.w * v.w;
    }
    #pragma unroll
    for (int o = 16; o > 0; o >>= 1) {
        s  += __shfl_down_sync(0xFFFFFFFFu, s, o);
        s2 += __shfl_down_sync(0xFFFFFFFFu, s2, o);
    }
    __shared__ float sh[2][8];
    int w = threadIdx.x >> 5, ln = threadIdx.x & 31;
    if (ln == 0) { sh[0][w] = s; sh[1][w] = s2; }
    __syncthreads();
    if (w == 0) {
        s  = (ln < 8) ? sh[0][ln] : 0.f;
        s2 = (ln < 8) ? sh[1][ln] : 0.f;
        #pragma unroll
        for (int o = 4; o > 0; o >>= 1) {
            s  += __shfl_down_sync(0xFFFFFFFFu, s, o);
            s2 += __shfl_down_sync(0xFFFFFFFFu, s2, o);
        }
        if (ln == 0) {
            const float inv_n = 1.0f / (float)(L_ * CG_);
            float mu  = s * inv_n;
            float var = s2 * inv_n - mu * mu;
            g_stats[bg * 2 + 0] = mu;
            g_stats[bg * 2 + 1] = rsqrtf(var + 1e-6f);
        }
    }
}

// ---------------- kernel 2: apply GroupNorm ----------------
__global__ void gn_apply_kernel(const float* __restrict__ x,
                                const float* __restrict__ gamma,
                                const float* __restrict__ beta) {
    size_t i = (size_t)blockIdx.x * blockDim.x + threadIdx.x;
    size_t base = i * 4;
    if (base >= (size_t)ML * C_) return;
    int c  = (int)(base % C_);
    int bl = (int)(base / C_);
    int b  = bl >> 11;
    int g  = c >> 5;
    float mu = g_stats[(b * G_ + g) * 2 + 0];
    float rs = g_stats[(b * G_ + g) * 2 + 1];
    float4 xv = *(const float4*)(x + base);
    float4 gv = *(const float4*)(gamma + c);
    float4 bv = *(const float4*)(beta + c);
    float4 r;
    r.x = (xv.x - mu) * rs * gv.x + bv.x;
    r.y = (xv.y - mu) * rs * gv.y + bv.y;
    r.z = (xv.z - mu) * rs * gv.z + bv.z;
    r.w = (xv.w - mu) * rs * gv.w + bv.w;
#ifndef __CUDA_ARCH_FEAT_SM103_ALL
    *(float4*)(g_xn + base) = r;     // fallback GEMM input only
#endif
    ((__nv_bfloat162*)g_xn_bf)[2 * i]     = __floats2bfloat162_rn(r.x, r.y);
    ((__nv_bfloat162*)g_xn_bf)[2 * i + 1] = __floats2bfloat162_rn(r.z, r.w);
}

// ---------------- weight transpose + convert ----------------
__global__ void wtrans_kernel(const float* __restrict__ src, int K, int N, int which) {
    __shared__ float tile[32][33];
    int n0 = blockIdx.x * 32, k0 = blockIdx.y * 32;
    int tx = threadIdx.x, ty = threadIdx.y;
    #pragma unroll
    for (int i = 0; i < 32; i += 8)
        tile[ty + i][tx] = src[(size_t)(k0 + ty + i) * N + n0 + tx];
    __syncthreads();
    bf16* dst = which ? g_wpT : g_wqT;
    #pragma unroll
    for (int i = 0; i < 32; i += 8)
        dst[(size_t)(n0 + ty + i) * K + k0 + tx] = __float2bfloat16(tile[tx][ty + i]);
}

// ---------------- V^T transpose (feature path) ----------------
__global__ void vtrans_kernel() {
#ifdef __CUDA_ARCH_FEAT_SM103_ALL
    __shared__ unsigned short tile[32][33];
    int l0 = blockIdx.x * 32;
    int d0 = blockIdx.y * 32;
    int bh = blockIdx.z;
    int b = bh >> 4, h = bh & 15;
    int tx = threadIdx.x, ty = threadIdx.y;
    const unsigned short* src = (const unsigned short*)g_qkv_bf
        + (size_t)b * L_ * N3C + h * (3 * HD_) + 2 * HD_;
    #pragma unroll
    for (int i = 0; i < 32; i += 8)
        tile[ty + i][tx] = src[(size_t)(l0 + ty + i) * N3C + d0 + tx];
    __syncthreads();
    unsigned short* dst = (unsigned short*)g_vT + (size_t)bh * HD_ * L_;
    #pragma unroll
    for (int i = 0; i < 32; i += 8)
        dst[(size_t)(d0 + ty + i) * L_ + l0 + tx] = tile[tx][ty + i];
#endif
}

// ---------------- kernel 3/5: GEMM, dual path ----------------
template <int EPI>
__global__ __launch_bounds__(256) void gemm_kernel(
    const float* __restrict__ W,
    const float* __restrict__ bias,
    const float* __restrict__ resid,
    float*       __restrict__ OutParam,
    int N, int K)
{
    const float rsqrt2 = 0.70710678118654752f;
    int tid = threadIdx.x;
    int bm = blockIdx.y * 128;
    int bn = blockIdx.x * 128;

#ifdef __CUDA_ARCH_FEAT_SM103_ALL
    __shared__ __align__(1024) bf16 sA[2][128 * 64];
    __shared__ __align__(1024) bf16 sB[2][128 * 64];
    __shared__ float bias_s[128];
    __shared__ __align__(8) uint64_t mbar_store[2];
    __shared__ uint32_t tmem_ptr_store;

    const bf16* A  = (EPI == 0) ? g_xn_bf : g_att_bf;
    const bf16* WT = (EPI == 0) ? g_wqT   : g_wpT;

    int wid = tid >> 5;
    int lane = tid & 31;
    uint32_t mbar0 = smem_u32(&mbar_store[0]);
    uint32_t mbar1 = smem_u32(&mbar_store[1]);
    uint32_t tptr_addr = smem_u32(&tmem_ptr_store);

    if (wid == 0) TC_ALLOC(tptr_addr, 128);
    if (tid == 0) { MBAR_INIT(mbar0, 1); MBAR_INIT(mbar1, 1); }
    if (tid < 128) bias_s[tid] = bias[bn + tid];
    __syncthreads();
    uint32_t tmem_base;
    asm volatile("ld.shared.b32 %0, [%1];" : "=r"(tmem_base) : "r"(tptr_addr));

    uint64_t a_desc[2] = { make_desc_sw128(smem_u32(sA[0])), make_desc_sw128(smem_u32(sA[1])) };
    uint64_t b_desc[2] = { make_desc_sw128(smem_u32(sB[0])), make_desc_sw128(smem_u32(sB[1])) };

    const int NCHUNK = K / 64;
    for (int ch = 0; ch < NCHUNK; ch++) {
        int buf = ch & 1;
        uint32_t mb = buf ? mbar1 : mbar0;
        if (ch >= 2) mbar_wait(mb, (uint32_t)(((ch >> 1) - 1) & 1));

        int k0 = ch * 64;
        #pragma unroll
        for (int t = 0; t < 4; t++) {
            int i = t * 256 + tid;
            int r = i >> 3;
            int c8 = (i & 7) * 8;
            uint32_t sw = SW128((uint32_t)(r * 128 + c8 * 2));
            *(uint4*)((char*)sA[buf] + sw) = *(const uint4*)(A  + (size_t)(bm + r) * K + k0 + c8);
            *(uint4*)((char*)sB[buf] + sw) = *(const uint4*)(WT + (size_t)(bn + r) * K + k0 + c8);
        }
        FENCE_ASYNC_SHARED();
        __syncthreads();

        if (wid == 0 && elect_one()) {
            #pragma unroll
            for (int ks = 0; ks < 4; ks++) {
                uint32_t en = (ch > 0 || ks > 0) ? 1u : 0u;
                tc_mma_f16_ss(tmem_base, a_desc[buf] + ks * 2, b_desc[buf] + ks * 2,
                              IDESC_128x128, en);
            }
            TC_COMMIT(mb);
        }
    }

    mbar_wait(mbar1, 1u);
    TC_FENCE_AFTER();

    {
        int row = bm + (wid & 3) * 32 + lane;
        int chalf = (wid >> 2) * 64;
        #pragma unroll
        for (int cc = 0; cc < 2; cc++) {
            uint32_t d[32];
            tc_ld_x32(d, tmem_base + chalf + cc * 32);
            TC_WAIT_LD();
            int colbase = bn + chalf + cc * 32;
            #pragma unroll
            for (int j = 0; j < 8; j++) {
                float4 v;
                v.x = __uint_as_float(d[4 * j + 0]) + bias_s[chalf + cc * 32 + 4 * j + 0];
                v.y = __uint_as_float(d[4 * j + 1]) + bias_s[chalf + cc * 32 + 4 * j + 1];
                v.z = __uint_as_float(d[4 * j + 2]) + bias_s[chalf + cc * 32 + 4 * j + 2];
                v.w = __uint_as_float(d[4 * j + 3]) + bias_s[chalf + cc * 32 + 4 * j + 3];
                if (EPI == 1) {
                    float4 rv = *(const float4*)(resid + (size_t)row * N + colbase + 4 * j);
                    v.x = (v.x + rv.x) * rsqrt2;
                    v.y = (v.y + rv.y) * rsqrt2;
                    v.z = (v.z + rv.z) * rsqrt2;
                    v.w = (v.w + rv.w) * rsqrt2;
                    *(float4*)(OutParam + (size_t)row * N + colbase + 4 * j) = v;
                } else {
                    __nv_bfloat162 lo = __floats2bfloat162_rn(v.x, v.y);
                    __nv_bfloat162 hi = __floats2bfloat162_rn(v.z, v.w);
                    uint2 pk = make_uint2(*(uint32_t*)&lo, *(uint32_t*)&hi);
                    *(uint2*)(g_qkv_bf + (size_t)row * N + colbase + 4 * j) = pk;
                }
            }
        }
    }
    TC_FENCE_BEFORE();
    __syncthreads();
    if (tid == 0) { MBAR_INVAL(mbar0); MBAR_INVAL(mbar1); }
    __syncthreads();
    if (wid == 0) {
        TC_RELINQ();
        TC_DEALLOC(tmem_base, 128);
    }
#else
    // fp32 FFMA fallback (R3-proven)
    const float* A = (EPI == 0) ? g_xn : g_att;
    float* Cout    = (EPI == 0) ? g_qkv : OutParam;

    __shared__ float As[8][128];
    __shared__ float Bs[8][128];

    int tx = tid & 15;
    int ty = tid >> 4;

    float acc[8][8];
    #pragma unroll
    for (int i = 0; i < 8; i++)
        #pragma unroll
        for (int j = 0; j < 8; j++) acc[i][j] = 0.f;

    int arow = tid >> 1;
    int acol = (tid & 1) * 4;
    int brow = tid >> 5;
    int bcol = (tid & 31) * 4;

    const float* Aptr = A + (size_t)(bm + arow) * K + acol;
    const float* Bptr = W + (size_t)brow * N + bn + bcol;

    for (int k0 = 0; k0 < K; k0 += 8) {
        float4 av = *(const float4*)(Aptr + k0);
        float4 bv = *(const float4*)(Bptr + (size_t)k0 * N);
        As[acol + 0][arow] = av.x;
        As[acol + 1][arow] = av.y;
        As[acol + 2][arow] = av.z;
        As[acol + 3][arow] = av.w;
        *(float4*)&Bs[brow][bcol] = bv;
        __syncthreads();
        #pragma unroll
        for (int kk = 0; kk < 8; kk++) {
            float a[8], b[8];
            #pragma unroll
            for (int i = 0; i < 8; i++) a[i] = As[kk][ty * 8 + i];
            #pragma unroll
            for (int i = 0; i < 8; i++) b[i] = Bs[kk][tx * 8 + i];
            #pragma unroll
            for (int i = 0; i < 8; i++)
                #pragma unroll
                for (int j = 0; j < 8; j++)
                    acc[i][j] += a[i] * b[j];
        }
        __syncthreads();
    }

    #pragma unroll
    for (int i = 0; i < 8; i++) {
        int row = bm + ty * 8 + i;
        #pragma unroll
        for (int j = 0; j < 8; j += 4) {
            int col = bn + tx * 8 + j;
            float4 bb = *(const float4*)(bias + col);
            float4 v;
            v.x = acc[i][j + 0] + bb.x;
            v.y = acc[i][j + 1] + bb.y;
            v.z = acc[i][j + 2] + bb.z;
            v.w = acc[i][j + 3] + bb.w;
            if (EPI == 1) {
                float4 rv = *(const float4*)(resid + (size_t)row * N + col);
                v.x = (v.x + rv.x) * rsqrt2;
                v.y = (v.y + rv.y) * rsqrt2;
                v.z = (v.z + rv.z) * rsqrt2;
                v.w = (v.w + rv.w) * rsqrt2;
            }
            *(float4*)(Cout + (size_t)row * N + col) = v;
        }
    }
#endif
}

// ---------------- kernel 4: flash attention, dual path ----------------
__global__ __launch_bounds__(128) void flash_kernel() {
    int bh = blockIdx.y;
    int b = bh >> 4;
    int h = bh & 15;
    int tid = threadIdx.x;

#ifdef __CUDA_ARCH_FEAT_SM103_ALL
    // ============ tcgen05 attention (R10 config + LDTM/exp interleave) ============
    __shared__ __align__(1024) bf16 sK[128 * 64];    // K chunk [keys][dims] SW128
    __shared__ __align__(1024) bf16 sV[64 * 128];    // V^T chunk [dims][keys] blocked SW128
    __shared__ __align__(8) uint64_t mbar_store[2];  // S, O
    __shared__ uint32_t tmem_ptr_store;

    int wid = tid >> 5;
    int bm = blockIdx.x * 128;

    uint32_t mbarS = smem_u32(&mbar_store[0]);
    uint32_t mbarO = smem_u32(&mbar_store[1]);
    uint32_t tptr_addr = smem_u32(&tmem_ptr_store);

    if (wid == 0) TC_ALLOC(tptr_addr, 512);
    if (tid == 0) { MBAR_INIT(mbarS, 1); MBAR_INIT(mbarO, 1); }
    __syncthreads();
    uint32_t tmem_base;
    asm volatile("ld.shared.b32 %0, [%1];" : "=r"(tmem_base) : "r"(tptr_addr));

    const uint32_t Q0 = tmem_base + 0;      // Q: 32 cols bf16x2
    const uint32_t S0 = tmem_base + 128;    // S: 128 cols fp32
    const uint32_t P0 = tmem_base + 256;    // P: 64 cols bf16x2
    const uint32_t O0 = tmem_base + 320;    // O: 64 cols fp32

    const bf16* qkvb = g_qkv_bf + (size_t)b * L_ * N3C + h * (3 * HD_);

    // ---- Q into TMEM (TS-mode A operand) ----
    {
        uint32_t qr[32];
        const uint32_t* qsrc = (const uint32_t*)(qkvb + (size_t)(bm + tid) * N3C);
        #pragma unroll
        for (int i = 0; i < 32; i++) qr[i] = qsrc[i];
        uint32_t woff0 = (uint32_t)wid << 21;
        tc_st_x32(Q0 + woff0, qr);
        TC_WAIT_ST();
    }

    uint64_t k_desc = make_desc_sw128(smem_u32(sK));
    uint64_t v_desc = make_desc_sw128(smem_u32(sV));
    const uint32_t IDESC_S = IDESC_F16(128, 128);
    const uint32_t IDESC_O = IDESC_F16(128, 64);

    // ---- prologue: load K[0], issue S(0) ----
    #pragma unroll
    for (int t = 0; t < 8; t++) {
        int i = t * 128 + tid;
        int r = i >> 3;
        int c8 = (i & 7) * 8;
        uint32_t sw = SW128((uint32_t)(r * 128 + c8 * 2));
        *(uint4*)((char*)sK + sw) = *(const uint4*)(qkvb + HD_ + (size_t)r * N3C + c8);
    }
    FENCE_ASYNC_SHARED();
    TC_FENCE_BEFORE();
    __syncthreads();
    if (wid == 0 && elect_one()) {
        #pragma unroll
        for (int ks = 0; ks < 4; ks++)
            tc_mma_f16_ts(S0, Q0 + ks * 8, k_desc + ks * 2, IDESC_S, ks > 0);
        TC_COMMIT(mbarS);
    }

    float lsum = 0.f;
    const unsigned short* vT = (const unsigned short*)g_vT + (size_t)bh * HD_ * L_;
    const float SCALE_LOG2E = 0.125f * 1.44269504088896f;
    uint32_t woff = (uint32_t)wid << 21;

    for (int ch = 0; ch < 16; ch++) {
        // ---- S(ch) ready ----
        mbar_wait(mbarS, (uint32_t)(ch & 1));
        TC_FENCE_AFTER();

        // ---- LDTM half 0, wait; LDTM half 1 left outstanding ----
        uint32_t sr0[64], sr1[64];
        tc_ld_x32(sr0, S0);
        tc_ld_x32(sr0 + 32, S0 + 32);
        TC_WAIT_LD();
        tc_ld_x32(sr1, S0 + 64);
        tc_ld_x32(sr1 + 32, S0 + 96);

        // ---- K[ch+1] load issue (LDG latency overlaps exp half 0) ----
        if (ch < 15) {
            #pragma unroll
            for (int t = 0; t < 8; t++) {
                int i = t * 128 + tid;
                int r = i >> 3;
                int c8 = (i & 7) * 8;
                uint32_t sw = SW128((uint32_t)(r * 128 + c8 * 2));
                *(uint4*)((char*)sK + sw) =
                    *(const uint4*)(qkvb + HD_ + (size_t)((ch + 1) * 128 + r) * N3C + c8);
            }
        }

        // ---- exp half 0 (overlaps LDTM half 1 + K loads) ----
        uint32_t p[64];
        #pragma unroll
        for (int j = 0; j < 32; j++) {
            float e0 = exp2f(__uint_as_float(sr0[2 * j + 0]) * SCALE_LOG2E);
            float e1 = exp2f(__uint_as_float(sr0[2 * j + 1]) * SCALE_LOG2E);
            lsum += e0 + e1;
            __nv_bfloat162 pk = __floats2bfloat162_rn(e0, e1);
            p[j] = *(uint32_t*)&pk;
        }

        // ---- half 1 ready; S fully read -> sync + issue S(ch+1) ----
        TC_WAIT_LD();
        if (ch < 15) {
            FENCE_ASYNC_SHARED();
            __syncthreads();            // all warps done LDTM + K stores
            if (wid == 0 && elect_one()) {
                #pragma unroll
                for (int ks = 0; ks < 4; ks++)
                    tc_mma_f16_ts(S0, Q0 + ks * 8, k_desc + ks * 2, IDESC_S, ks > 0);
                TC_COMMIT(mbarS);
            }
        }

        // ---- wait O(ch-1) (short), then load V[ch] ----
        if (ch > 0) mbar_wait(mbarO, (uint32_t)((ch - 1) & 1));
        #pragma unroll
        for (int t = 0; t < 8; t++) {
            int i = t * 128 + tid;
            int d = i >> 4;
            int kk = (i & 15) * 8;
            int atom_col = kk >> 6;
            int inner_col = kk & 63;
            uint32_t off = (uint32_t)(((d >> 3) + atom_col * 8) * 1024 + (d & 7) * 128 + inner_col * 2);
            uint32_t sw = SW128(off);
            *(uint4*)((char*)sV + sw) = *(const uint4*)(vT + (size_t)d * L_ + ch * 128 + kk);
        }

        // ---- exp half 1 (overlaps V loads) ----
        uint32_t p2[32];
        #pragma unroll
        for (int j = 0; j < 32; j++) {
            float e0 = exp2f(__uint_as_float(sr1[2 * j + 0]) * SCALE_LOG2E);
            float e1 = exp2f(__uint_as_float(sr1[2 * j + 1]) * SCALE_LOG2E);
            lsum += e0 + e1;
            __nv_bfloat162 pk = __floats2bfloat162_rn(e0, e1);
            p2[j] = *(uint32_t*)&pk;
        }

        // ---- P to TMEM, O += P @ V^T ----
        tc_st_x32(P0 + woff, p);
        tc_st_x32(P0 + 32 + woff, p2);
        TC_WAIT_ST();
        FENCE_ASYNC_SHARED();
        TC_FENCE_BEFORE();
        __syncthreads();
        if (wid == 0 && elect_one()) {
            TC_FENCE_AFTER();
            #pragma unroll
            for (int s8 = 0; s8 < 8; s8++) {
                uint64_t boff = (uint64_t)((s8 >> 2) * 512 + (s8 & 3) * 2);
                tc_mma_f16_ts(O0, P0 + s8 * 8, v_desc + boff, IDESC_O,
                              (ch > 0 || s8 > 0));
            }
            TC_COMMIT(mbarO);
        }
        __syncthreads();
    }

    // ---- epilogue ----
    mbar_wait(mbarO, 1u);
    TC_FENCE_AFTER();
    {
        uint32_t d0[32], d1[32];
        tc_ld_x32(d0, O0);
        tc_ld_x32(d1, O0 + 32);
        TC_WAIT_LD();
        float inv = 1.f / lsum;
        bf16* op = g_att_bf + (size_t)(b * L_ + bm + tid) * C_ + h * HD_;
        #pragma unroll
        for (int j = 0; j < 16; j++) {
            __nv_bfloat162 a = __floats2bfloat162_rn(
                __uint_as_float(d0[2 * j]) * inv, __uint_as_float(d0[2 * j + 1]) * inv);
            ((__nv_bfloat162*)op)[j] = a;
        }
        #pragma unroll
        for (int j = 0; j < 16; j++) {
            __nv_bfloat162 a = __floats2bfloat162_rn(
                __uint_as_float(d1[2 * j]) * inv, __uint_as_float(d1[2 * j + 1]) * inv);
            ((__nv_bfloat162*)op)[16 + j] = a;
        }
    }
    TC_FENCE_BEFORE();
    __syncthreads();
    if (tid == 0) { MBAR_INVAL(mbarS); MBAR_INVAL(mbarO); }
    __syncthreads();
    if (wid == 0) {
        TC_RELINQ();
        TC_DEALLOC(tmem_base, 512);
    }
#else
    // ============ scalar fallback (R3-proven) ============
    __shared__ float Ks[32 * 64];
    __shared__ float Vs[32 * 64];

    int qrow = blockIdx.x * 128 + tid;

    const float* base = g_qkv + (size_t)b * L_ * N3C;
    const float* qptr = base + (size_t)qrow * N3C + h * (3 * HD_);
    const float* kbase = base + h * (3 * HD_) + HD_;
    const float* vbase = base + h * (3 * HD_) + 2 * HD_;

    float q[HD_];
    #pragma unroll
    for (int d4 = 0; d4 < HD_ / 4; d4++) {
        float4 t = *(const float4*)(qptr + d4 * 4);
        q[4 * d4 + 0] = t.x * 0.125f;
        q[4 * d4 + 1] = t.y * 0.125f;
        q[4 * d4 + 2] = t.z * 0.125f;
        q[4 * d4 + 3] = t.w * 0.125f;
    }
    float o[HD_];
    #pragma unroll
    for (int d = 0; d < HD_; d++) o[d] = 0.f;
    float m = -1e30f, l = 0.f;

    for (int kb = 0; kb < L_ / 32; kb++) {
        __syncthreads();
        #pragma unroll
        for (int t = 0; t < 4; t++) {
            int idx = t * 128 + tid;
            int r = idx >> 4;
            int c4 = (idx & 15) * 4;
            size_t goff = (size_t)(kb * 32 + r) * N3C + c4;
            *(float4*)&Ks[r * 64 + c4] = *(const float4*)(kbase + goff);
            *(float4*)&Vs[r * 64 + c4] = *(const float4*)(vbase + goff);
        }
        __syncthreads();

        float s[32];
        #pragma unroll
        for (int j = 0; j < 32; j++) {
            float accv = 0.f;
            #pragma unroll
            for (int d = 0; d < HD_; d++) accv += q[d] * Ks[j * 64 + d];
            s[j] = accv;
        }
        float mnew = m;
        #pragma unroll
        for (int j = 0; j < 32; j++) mnew = fmaxf(mnew, s[j]);
        float corr = __expf(m - mnew);
        l *= corr;
        #pragma unroll
        for (int d = 0; d < HD_; d++) o[d] *= corr;
        #pragma unroll
        for (int j = 0; j < 32; j++) {
            float pp = __expf(s[j] - mnew);
            l += pp;
            #pragma unroll
            for (int d = 0; d < HD_; d++) o[d] += pp * Vs[j * 64 + d];
        }
        m = mnew;
    }

    float inv = 1.f / l;
    size_t obase = (size_t)(b * L_ + qrow) * C_ + h * HD_;
    float* opf = g_att + obase;
    bf16* opb = g_att_bf + obase;
    #pragma unroll
    for (int d4 = 0; d4 < HD_ / 4; d4++) {
        float4 t;
        t.x = o[4 * d4 + 0] * inv;
        t.y = o[4 * d4 + 1] * inv;
        t.z = o[4 * d4 + 2] * inv;
        t.w = o[4 * d4 + 3] * inv;
        *(float4*)(opf + 4 * d4) = t;
        ((__nv_bfloat162*)opb)[2 * d4]     = __floats2bfloat162_rn(t.x, t.y);
        ((__nv_bfloat162*)opb)[2 * d4 + 1] = __floats2bfloat162_rn(t.z, t.w);
    }
#endif
}

// ---------------- launcher ----------------
extern "C" void kernel_launch(void* const* d_in, const int* in_sizes, int n_in,
                              void* d_out, int out_size) {
    const float* x        = (const float*)d_in[0];
    const float* gn_scale = (const float*)d_in[1];
    const float* gn_bias  = (const float*)d_in[2];
    const float* qkv_w    = (const float*)d_in[3];
    const float* qkv_b    = (const float*)d_in[4];
    const float* proj_w   = (const float*)d_in[5];
    const float* proj_b   = (const float*)d_in[6];
    float* out = (float*)d_out;

    // 0) transpose+convert weights
    {
        dim3 blk(32, 8);
        dim3 gq(N3C / 32, C_ / 32);
        wtrans_kernel<<<gq, blk>>>(qkv_w, C_, N3C, 0);
        dim3 gp(C_ / 32, C_ / 32);
        wtrans_kernel<<<gp, blk>>>(proj_w, C_, C_, 1);
    }

    // 1) GroupNorm stats
    gn_stats_kernel<<<B_ * G_, 256>>>(x);

    // 2) apply GroupNorm
    {
        int total4 = ML * C_ / 4;
        gn_apply_kernel<<<(total4 + 255) / 256, 256>>>(x, gn_scale, gn_bias);
    }

    // 3) QKV GEMM
    {
        dim3 grid(N3C / 128, ML / 128);
        gemm_kernel<0><<<grid, 256>>>(qkv_w, qkv_b, nullptr, nullptr, N3C, C_);
    }

    // 3.5) V^T transpose (feature path)
    {
        dim3 blk(32, 8);
        dim3 gv(L_ / 32, HD_ / 32, B_ * H_);
        vtrans_kernel<<<gv, blk>>>();
    }

    // 4) flash attention
    {
        dim3 grid(L_ / 128, B_ * H_);
        flash_kernel<<<grid, 128>>>();
    }

    // 5) proj GEMM + residual
    {
        dim3 grid(C_ / 128, ML / 128);
        gemm_kernel<1><<<grid, 256>>>(proj_w, proj_b, x, out, C_, C_);
    }
}

// round 14
// speedup vs baseline: 1.1492x; 1.0329x over previous
#include <cuda_runtime.h>
#include <cuda_bf16.h>
#include <math.h>
#include <stdint.h>

#define B_  2
#define L_  2048
#define C_  1024
#define H_  16
#define HD_ 64
#define G_  32
#define CG_ 32
#define N3C (3 * C_)
#define ML  (B_ * L_)   // 4096 rows

typedef __nv_bfloat16 bf16;

// ---------------- scratch (static device globals) ----------------
__device__ float g_stats[B_ * G_ * 2];
__device__ float g_part[B_ * G_ * 8 * 2];         // two-phase GN partials
__device__ float g_xn[(size_t)ML * C_];           // normalized input fp32 (fallback only)
__device__ bf16  g_xn_bf[(size_t)ML * C_];        // normalized input bf16
__device__ float g_qkv[(size_t)ML * N3C];         // qkv fp32 (fallback only)
__device__ bf16  g_qkv_bf[(size_t)ML * N3C];      // qkv bf16 (feature path)
__device__ float g_att[(size_t)ML * C_];          // attention out fp32 (fallback only)
__device__ bf16  g_att_bf[(size_t)ML * C_];       // attention out bf16
__device__ bf16  g_wqT[(size_t)N3C * C_];         // qkv_w^T bf16 [N,K]
__device__ bf16  g_wpT[(size_t)C_ * C_];          // proj_w^T bf16 [N,K]
__device__ bf16  g_vT[(size_t)B_ * H_ * HD_ * L_]; // V^T [bh][d][key] bf16

// ---------------- helpers ----------------
__device__ __forceinline__ uint32_t smem_u32(const void* p) {
    return (uint32_t)__cvta_generic_to_shared(p);
}

#ifdef __CUDA_ARCH_FEAT_SM103_ALL
__device__ __forceinline__ uint32_t elect_one() {
    uint32_t pred;
    asm volatile("{\n\t.reg .pred p;\n\telect.sync _|p, 0xFFFFFFFF;\n\t"
                 "selp.b32 %0, 1, 0, p;\n\t}" : "=r"(pred));
    return pred;
}
#define TC_ALLOC(smem_addr, ncols) \
    asm volatile("tcgen05.alloc.cta_group::1.sync.aligned.shared::cta.b32 [%0], %1;" \
                 :: "r"(smem_addr), "r"(ncols) : "memory")
#define TC_DEALLOC(tmem, ncols) \
    asm volatile("tcgen05.dealloc.cta_group::1.sync.aligned.b32 %0, %1;" :: "r"(tmem), "r"(ncols))
#define TC_RELINQ() \
    asm volatile("tcgen05.relinquish_alloc_permit.cta_group::1.sync.aligned;")
#define TC_COMMIT(mbar) \
    asm volatile("tcgen05.commit.cta_group::1.mbarrier::arrive::one.shared::cluster.b64 [%0];" \
                 :: "r"(mbar) : "memory")
#define TC_FENCE_AFTER()  asm volatile("tcgen05.fence::after_thread_sync;" ::: "memory")
#define TC_FENCE_BEFORE() asm volatile("tcgen05.fence::before_thread_sync;" ::: "memory")
#define TC_WAIT_LD()      asm volatile("tcgen05.wait::ld.sync.aligned;" ::: "memory")
#define TC_WAIT_ST()      asm volatile("tcgen05.wait::st.sync.aligned;" ::: "memory")
#define MBAR_INIT(mbar, cnt) \
    asm volatile("mbarrier.init.shared.b64 [%0], %1;" :: "r"(mbar), "r"(cnt) : "memory")
#define MBAR_INVAL(mbar) \
    asm volatile("mbarrier.inval.shared.b64 [%0];" :: "r"(mbar) : "memory")
#define FENCE_ASYNC_SHARED() asm volatile("fence.proxy.async.shared::cta;" ::: "memory")

__device__ __forceinline__ void mbar_wait(uint32_t mbar, uint32_t parity) {
    asm volatile(
        "{\n\t.reg .pred P1;\n\t"
        "WAIT_LOOP_%=:\n\t"
        "mbarrier.try_wait.parity.acquire.cta.shared::cta.b64 P1, [%0], %1, 0x989680;\n\t"
        "@P1 bra.uni WAIT_DONE_%=;\n\t"
        "bra.uni WAIT_LOOP_%=;\n\t"
        "WAIT_DONE_%=:\n\t}"
        :: "r"(mbar), "r"(parity) : "memory");
}

__device__ __forceinline__ void tc_mma_f16_ss(uint32_t d_tmem, uint64_t a_desc,
                                              uint64_t b_desc, uint32_t idesc,
                                              uint32_t enable) {
    asm volatile(
        "{\n\t.reg .pred p;\n\tsetp.ne.u32 p, %5, 0;\n\t"
        "tcgen05.mma.cta_group::1.kind::f16 [%0], %1, %2, %3, {%4,%4,%4,%4}, p;\n\t}"
        :: "r"(d_tmem), "l"(a_desc), "l"(b_desc), "r"(idesc), "r"(0u), "r"(enable)
        : "memory");
}
__device__ __forceinline__ void tc_mma_f16_ts(uint32_t d_tmem, uint32_t a_tmem,
                                              uint64_t b_desc, uint32_t idesc,
                                              uint32_t enable) {
    asm volatile(
        "{\n\t.reg .pred p;\n\tsetp.ne.u32 p, %5, 0;\n\t"
        "tcgen05.mma.cta_group::1.kind::f16 [%0], [%1], %2, %3, {%4,%4,%4,%4}, p;\n\t}"
        :: "r"(d_tmem), "r"(a_tmem), "l"(b_desc), "r"(idesc), "r"(0u), "r"(enable)
        : "memory");
}

__device__ __forceinline__ void tc_ld_x32(uint32_t* r, uint32_t tmem_addr) {
    asm volatile(
        "tcgen05.ld.sync.aligned.32x32b.x32.b32 "
        "{%0, %1, %2, %3, %4, %5, %6, %7, %8, %9, %10, %11, %12, %13, %14, %15, "
        " %16, %17, %18, %19, %20, %21, %22, %23, %24, %25, %26, %27, %28, %29, %30, %31}, [%32];"
        : "=r"(r[0]), "=r"(r[1]), "=r"(r[2]), "=r"(r[3]), "=r"(r[4]), "=r"(r[5]),
          "=r"(r[6]), "=r"(r[7]), "=r"(r[8]), "=r"(r[9]), "=r"(r[10]), "=r"(r[11]),
          "=r"(r[12]), "=r"(r[13]), "=r"(r[14]), "=r"(r[15]), "=r"(r[16]), "=r"(r[17]),
          "=r"(r[18]), "=r"(r[19]), "=r"(r[20]), "=r"(r[21]), "=r"(r[22]), "=r"(r[23]),
          "=r"(r[24]), "=r"(r[25]), "=r"(r[26]), "=r"(r[27]), "=r"(r[28]), "=r"(r[29]),
          "=r"(r[30]), "=r"(r[31])
        : "r"(tmem_addr));
}

__device__ __forceinline__ void tc_st_x32(uint32_t tmem_addr, const uint32_t* r) {
    asm volatile(
        "tcgen05.st.sync.aligned.32x32b.x32.b32 [%0], "
        "{%1, %2, %3, %4, %5, %6, %7, %8, %9, %10, %11, %12, %13, %14, %15, %16, "
        " %17, %18, %19, %20, %21, %22, %23, %24, %25, %26, %27, %28, %29, %30, %31, %32};"
        :: "r"(tmem_addr),
           "r"(r[0]), "r"(r[1]), "r"(r[2]), "r"(r[3]), "r"(r[4]), "r"(r[5]),
           "r"(r[6]), "r"(r[7]), "r"(r[8]), "r"(r[9]), "r"(r[10]), "r"(r[11]),
           "r"(r[12]), "r"(r[13]), "r"(r[14]), "r"(r[15]), "r"(r[16]), "r"(r[17]),
           "r"(r[18]), "r"(r[19]), "r"(r[20]), "r"(r[21]), "r"(r[22]), "r"(r[23]),
           "r"(r[24]), "r"(r[25]), "r"(r[26]), "r"(r[27]), "r"(r[28]), "r"(r[29]),
           "r"(r[30]), "r"(r[31])
        : "memory");
}

#define SW128(off) ((off) ^ (((off) >> 3) & 0x70))
__device__ __forceinline__ uint64_t make_desc_sw128(uint32_t base_addr) {
    const uint64_t BASE =
        (uint64_t(2) << 61) | (uint64_t(1) << 46) | (uint64_t(64) << 32) | (uint64_t(1) << 16);
    return BASE | ((uint64_t)(base_addr >> 4) & 0x3FFF);
}
#define IDESC_F16(Mv, Nv) ((1u << 4) | (1u << 7) | (1u << 10) | (((Nv) / 8) << 17) | (((Mv) / 16) << 24))
#define IDESC_128x128 IDESC_F16(128, 128)
#endif  // __CUDA_ARCH_FEAT_SM103_ALL

// ---------------- kernel 1a: GroupNorm partial sums (512 blocks) ----------------
// grid = (B*G, 8). Block (bg, part) reduces rows [part*256, (part+1)*256) of group bg.
__global__ void gn_part_kernel(const float* __restrict__ x) {
    int bg = blockIdx.x;
    int part = blockIdx.y;
    int b = bg / G_;
    int g = bg % G_;
    const float* xp = x + (size_t)b * L_ * C_ + g * CG_;

    // 256 rows x 32 ch = 2048 float4; 256 threads x 8 each
    float s = 0.f, s2 = 0.f;
    #pragma unroll
    for (int t = 0; t < 8; t++) {
        int i = t * 256 + threadIdx.x;      // float4 idx in this part
        int l = part * 256 + (i >> 3);
        int c4 = (i & 7) * 4;
        float4 v = *(const float4*)(xp + (size_t)l * C_ + c4);
        s  += v.x + v.y + v.z + v.w;
        s2 += v.x * v.x + v.y * v.y + v.z * v.z + v.w * v.w;
    }
    #pragma unroll
    for (int o = 16; o > 0; o >>= 1) {
        s  += __shfl_down_sync(0xFFFFFFFFu, s, o);
        s2 += __shfl_down_sync(0xFFFFFFFFu, s2, o);
    }
    __shared__ float sh[2][8];
    int w = threadIdx.x >> 5, ln = threadIdx.x & 31;
    if (ln == 0) { sh[0][w] = s; sh[1][w] = s2; }
    __syncthreads();
    if (w == 0) {
        s  = (ln < 8) ? sh[0][ln] : 0.f;
        s2 = (ln < 8) ? sh[1][ln] : 0.f;
        #pragma unroll
        for (int o = 4; o > 0; o >>= 1) {
            s  += __shfl_down_sync(0xFFFFFFFFu, s, o);
            s2 += __shfl_down_sync(0xFFFFFFFFu, s2, o);
        }
        if (ln == 0) {
            g_part[(bg * 8 + part) * 2 + 0] = s;
            g_part[(bg * 8 + part) * 2 + 1] = s2;
        }
    }
}

// ---------------- kernel 1b: finalize stats (64 blocks x 32 threads) ----------------
__global__ void gn_stats_kernel() {
    int bg = blockIdx.x;
    int ln = threadIdx.x;
    float s  = (ln < 8) ? g_part[(bg * 8 + ln) * 2 + 0] : 0.f;
    float s2 = (ln < 8) ? g_part[(bg * 8 + ln) * 2 + 1] : 0.f;
    #pragma unroll
    for (int o = 4; o > 0; o >>= 1) {
        s  += __shfl_down_sync(0xFFFFFFFFu, s, o);
        s2 += __shfl_down_sync(0xFFFFFFFFu, s2, o);
    }
    if (ln == 0) {
        const float inv_n = 1.0f / (float)(L_ * CG_);
        float mu  = s * inv_n;
        float var = s2 * inv_n - mu * mu;
        g_stats[bg * 2 + 0] = mu;
        g_stats[bg * 2 + 1] = rsqrtf(var + 1e-6f);
    }
}

// ---------------- kernel 2: apply GroupNorm ----------------
__global__ void gn_apply_kernel(const float* __restrict__ x,
                                const float* __restrict__ gamma,
                                const float* __restrict__ beta) {
    size_t i = (size_t)blockIdx.x * blockDim.x + threadIdx.x;
    size_t base = i * 4;
    if (base >= (size_t)ML * C_) return;
    int c  = (int)(base % C_);
    int bl = (int)(base / C_);
    int b  = bl >> 11;
    int g  = c >> 5;
    float mu = g_stats[(b * G_ + g) * 2 + 0];
    float rs = g_stats[(b * G_ + g) * 2 + 1];
    float4 xv = *(const float4*)(x + base);
    float4 gv = *(const float4*)(gamma + c);
    float4 bv = *(const float4*)(beta + c);
    float4 r;
    r.x = (xv.x - mu) * rs * gv.x + bv.x;
    r.y = (xv.y - mu) * rs * gv.y + bv.y;
    r.z = (xv.z - mu) * rs * gv.z + bv.z;
    r.w = (xv.w - mu) * rs * gv.w + bv.w;
#ifndef __CUDA_ARCH_FEAT_SM103_ALL
    *(float4*)(g_xn + base) = r;     // fallback GEMM input only
#endif
    ((__nv_bfloat162*)g_xn_bf)[2 * i]     = __floats2bfloat162_rn(r.x, r.y);
    ((__nv_bfloat162*)g_xn_bf)[2 * i + 1] = __floats2bfloat162_rn(r.z, r.w);
}

// ---------------- weight transpose + convert ----------------
__global__ void wtrans_kernel(const float* __restrict__ src, int K, int N, int which) {
    __shared__ float tile[32][33];
    int n0 = blockIdx.x * 32, k0 = blockIdx.y * 32;
    int tx = threadIdx.x, ty = threadIdx.y;
    #pragma unroll
    for (int i = 0; i < 32; i += 8)
        tile[ty + i][tx] = src[(size_t)(k0 + ty + i) * N + n0 + tx];
    __syncthreads();
    bf16* dst = which ? g_wpT : g_wqT;
    #pragma unroll
    for (int i = 0; i < 32; i += 8)
        dst[(size_t)(n0 + ty + i) * K + k0 + tx] = __float2bfloat16(tile[tx][ty + i]);
}

// ---------------- V^T transpose (feature path) ----------------
__global__ void vtrans_kernel() {
#ifdef __CUDA_ARCH_FEAT_SM103_ALL
    __shared__ unsigned short tile[32][33];
    int l0 = blockIdx.x * 32;
    int d0 = blockIdx.y * 32;
    int bh = blockIdx.z;
    int b = bh >> 4, h = bh & 15;
    int tx = threadIdx.x, ty = threadIdx.y;
    const unsigned short* src = (const unsigned short*)g_qkv_bf
        + (size_t)b * L_ * N3C + h * (3 * HD_) + 2 * HD_;
    #pragma unroll
    for (int i = 0; i < 32; i += 8)
        tile[ty + i][tx] = src[(size_t)(l0 + ty + i) * N3C + d0 + tx];
    __syncthreads();
    unsigned short* dst = (unsigned short*)g_vT + (size_t)bh * HD_ * L_;
    #pragma unroll
    for (int i = 0; i < 32; i += 8)
        dst[(size_t)(d0 + ty + i) * L_ + l0 + tx] = tile[tx][ty + i];
#endif
}

// ---------------- kernel 3/5: GEMM, dual path ----------------
template <int EPI>
__global__ __launch_bounds__(256) void gemm_kernel(
    const float* __restrict__ W,
    const float* __restrict__ bias,
    const float* __restrict__ resid,
    float*       __restrict__ OutParam,
    int N, int K)
{
    const float rsqrt2 = 0.70710678118654752f;
    int tid = threadIdx.x;
    int bm = blockIdx.y * 128;
    int bn = blockIdx.x * 128;

#ifdef __CUDA_ARCH_FEAT_SM103_ALL
    __shared__ __align__(1024) bf16 sA[2][128 * 64];
    __shared__ __align__(1024) bf16 sB[2][128 * 64];
    __shared__ float bias_s[128];
    __shared__ __align__(8) uint64_t mbar_store[2];
    __shared__ uint32_t tmem_ptr_store;

    const bf16* A  = (EPI == 0) ? g_xn_bf : g_att_bf;
    const bf16* WT = (EPI == 0) ? g_wqT   : g_wpT;

    int wid = tid >> 5;
    int lane = tid & 31;
    uint32_t mbar0 = smem_u32(&mbar_store[0]);
    uint32_t mbar1 = smem_u32(&mbar_store[1]);
    uint32_t tptr_addr = smem_u32(&tmem_ptr_store);

    if (wid == 0) TC_ALLOC(tptr_addr, 128);
    if (tid == 0) { MBAR_INIT(mbar0, 1); MBAR_INIT(mbar1, 1); }
    if (tid < 128) bias_s[tid] = bias[bn + tid];
    __syncthreads();
    uint32_t tmem_base;
    asm volatile("ld.shared.b32 %0, [%1];" : "=r"(tmem_base) : "r"(tptr_addr));

    uint64_t a_desc[2] = { make_desc_sw128(smem_u32(sA[0])), make_desc_sw128(smem_u32(sA[1])) };
    uint64_t b_desc[2] = { make_desc_sw128(smem_u32(sB[0])), make_desc_sw128(smem_u32(sB[1])) };

    const int NCHUNK = K / 64;
    for (int ch = 0; ch < NCHUNK; ch++) {
        int buf = ch & 1;
        uint32_t mb = buf ? mbar1 : mbar0;
        if (ch >= 2) mbar_wait(mb, (uint32_t)(((ch >> 1) - 1) & 1));

        int k0 = ch * 64;
        #pragma unroll
        for (int t = 0; t < 4; t++) {
            int i = t * 256 + tid;
            int r = i >> 3;
            int c8 = (i & 7) * 8;
            uint32_t sw = SW128((uint32_t)(r * 128 + c8 * 2));
            *(uint4*)((char*)sA[buf] + sw) = *(const uint4*)(A  + (size_t)(bm + r) * K + k0 + c8);
            *(uint4*)((char*)sB[buf] + sw) = *(const uint4*)(WT + (size_t)(bn + r) * K + k0 + c8);
        }
        FENCE_ASYNC_SHARED();
        __syncthreads();

        if (wid == 0 && elect_one()) {
            #pragma unroll
            for (int ks = 0; ks < 4; ks++) {
                uint32_t en = (ch > 0 || ks > 0) ? 1u : 0u;
                tc_mma_f16_ss(tmem_base, a_desc[buf] + ks * 2, b_desc[buf] + ks * 2,
                              IDESC_128x128, en);
            }
            TC_COMMIT(mb);
        }
    }

    mbar_wait(mbar1, 1u);
    TC_FENCE_AFTER();

    {
        int row = bm + (wid & 3) * 32 + lane;
        int chalf = (wid >> 2) * 64;
        #pragma unroll
        for (int cc = 0; cc < 2; cc++) {
            uint32_t d[32];
            tc_ld_x32(d, tmem_base + chalf + cc * 32);
            TC_WAIT_LD();
            int colbase = bn + chalf + cc * 32;
            #pragma unroll
            for (int j = 0; j < 8; j++) {
                float4 v;
                v.x = __uint_as_float(d[4 * j + 0]) + bias_s[chalf + cc * 32 + 4 * j + 0];
                v.y = __uint_as_float(d[4 * j + 1]) + bias_s[chalf + cc * 32 + 4 * j + 1];
                v.z = __uint_as_float(d[4 * j + 2]) + bias_s[chalf + cc * 32 + 4 * j + 2];
                v.w = __uint_as_float(d[4 * j + 3]) + bias_s[chalf + cc * 32 + 4 * j + 3];
                if (EPI == 1) {
                    float4 rv = *(const float4*)(resid + (size_t)row * N + colbase + 4 * j);
                    v.x = (v.x + rv.x) * rsqrt2;
                    v.y = (v.y + rv.y) * rsqrt2;
                    v.z = (v.z + rv.z) * rsqrt2;
                    v.w = (v.w + rv.w) * rsqrt2;
                    *(float4*)(OutParam + (size_t)row * N + colbase + 4 * j) = v;
                } else {
                    __nv_bfloat162 lo = __floats2bfloat162_rn(v.x, v.y);
                    __nv_bfloat162 hi = __floats2bfloat162_rn(v.z, v.w);
                    uint2 pk = make_uint2(*(uint32_t*)&lo, *(uint32_t*)&hi);
                    *(uint2*)(g_qkv_bf + (size_t)row * N + colbase + 4 * j) = pk;
                }
            }
        }
    }
    TC_FENCE_BEFORE();
    __syncthreads();
    if (tid == 0) { MBAR_INVAL(mbar0); MBAR_INVAL(mbar1); }
    __syncthreads();
    if (wid == 0) {
        TC_RELINQ();
        TC_DEALLOC(tmem_base, 128);
    }
#else
    // fp32 FFMA fallback (R3-proven)
    const float* A = (EPI == 0) ? g_xn : g_att;
    float* Cout    = (EPI == 0) ? g_qkv : OutParam;

    __shared__ float As[8][128];
    __shared__ float Bs[8][128];

    int tx = tid & 15;
    int ty = tid >> 4;

    float acc[8][8];
    #pragma unroll
    for (int i = 0; i < 8; i++)
        #pragma unroll
        for (int j = 0; j < 8; j++) acc[i][j] = 0.f;

    int arow = tid >> 1;
    int acol = (tid & 1) * 4;
    int brow = tid >> 5;
    int bcol = (tid & 31) * 4;

    const float* Aptr = A + (size_t)(bm + arow) * K + acol;
    const float* Bptr = W + (size_t)brow * N + bn + bcol;

    for (int k0 = 0; k0 < K; k0 += 8) {
        float4 av = *(const float4*)(Aptr + k0);
        float4 bv = *(const float4*)(Bptr + (size_t)k0 * N);
        As[acol + 0][arow] = av.x;
        As[acol + 1][arow] = av.y;
        As[acol + 2][arow] = av.z;
        As[acol + 3][arow] = av.w;
        *(float4*)&Bs[brow][bcol] = bv;
        __syncthreads();
        #pragma unroll
        for (int kk = 0; kk < 8; kk++) {
            float a[8], b[8];
            #pragma unroll
            for (int i = 0; i < 8; i++) a[i] = As[kk][ty * 8 + i];
            #pragma unroll
            for (int i = 0; i < 8; i++) b[i] = Bs[kk][tx * 8 + i];
            #pragma unroll
            for (int i = 0; i < 8; i++)
                #pragma unroll
                for (int j = 0; j < 8; j++)
                    acc[i][j] += a[i] * b[j];
        }
        __syncthreads();
    }

    #pragma unroll
    for (int i = 0; i < 8; i++) {
        int row = bm + ty * 8 + i;
        #pragma unroll
        for (int j = 0; j < 8; j += 4) {
            int col = bn + tx * 8 + j;
            float4 bb = *(const float4*)(bias + col);
            float4 v;
            v.x = acc[i][j + 0] + bb.x;
            v.y = acc[i][j + 1] + bb.y;
            v.z = acc[i][j + 2] + bb.z;
            v.w = acc[i][j + 3] + bb.w;
            if (EPI == 1) {
                float4 rv = *(const float4*)(resid + (size_t)row * N + col);
                v.x = (v.x + rv.x) * rsqrt2;
                v.y = (v.y + rv.y) * rsqrt2;
                v.z = (v.z + rv.z) * rsqrt2;
                v.w = (v.w + rv.w) * rsqrt2;
            }
            *(float4*)(Cout + (size_t)row * N + col) = v;
        }
    }
#endif
}

// ---------------- kernel 4: flash attention, dual path (R10 champion config) ----------------
__global__ __launch_bounds__(128) void flash_kernel() {
    int bh = blockIdx.y;
    int b = bh >> 4;
    int h = bh & 15;
    int tid = threadIdx.x;

#ifdef __CUDA_ARCH_FEAT_SM103_ALL
    // ============ tcgen05 attention, pipelined ============
    __shared__ __align__(1024) bf16 sK[128 * 64];    // K chunk [keys][dims] SW128
    __shared__ __align__(1024) bf16 sV[64 * 128];    // V^T chunk [dims][keys] blocked SW128
    __shared__ __align__(8) uint64_t mbar_store[2];  // S, O
    __shared__ uint32_t tmem_ptr_store;

    int wid = tid >> 5;
    int bm = blockIdx.x * 128;

    uint32_t mbarS = smem_u32(&mbar_store[0]);
    uint32_t mbarO = smem_u32(&mbar_store[1]);
    uint32_t tptr_addr = smem_u32(&tmem_ptr_store);

    if (wid == 0) TC_ALLOC(tptr_addr, 512);
    if (tid == 0) { MBAR_INIT(mbarS, 1); MBAR_INIT(mbarO, 1); }
    __syncthreads();
    uint32_t tmem_base;
    asm volatile("ld.shared.b32 %0, [%1];" : "=r"(tmem_base) : "r"(tptr_addr));

    const uint32_t Q0 = tmem_base + 0;      // Q: 32 cols bf16x2
    const uint32_t S0 = tmem_base + 128;    // S: 128 cols fp32
    const uint32_t P0 = tmem_base + 256;    // P: 64 cols bf16x2
    const uint32_t O0 = tmem_base + 320;    // O: 64 cols fp32

    const bf16* qkvb = g_qkv_bf + (size_t)b * L_ * N3C + h * (3 * HD_);

    // ---- Q into TMEM (TS-mode A operand) ----
    {
        uint32_t qr[32];
        const uint32_t* qsrc = (const uint32_t*)(qkvb + (size_t)(bm + tid) * N3C);
        #pragma unroll
        for (int i = 0; i < 32; i++) qr[i] = qsrc[i];
        uint32_t woff = (uint32_t)wid << 21;
        tc_st_x32(Q0 + woff, qr);
        TC_WAIT_ST();
    }

    uint64_t k_desc = make_desc_sw128(smem_u32(sK));
    uint64_t v_desc = make_desc_sw128(smem_u32(sV));
    const uint32_t IDESC_S = IDESC_F16(128, 128);
    const uint32_t IDESC_O = IDESC_F16(128, 64);

    // ---- prologue: load K[0], issue S(0) ----
    #pragma unroll
    for (int t = 0; t < 8; t++) {
        int i = t * 128 + tid;
        int r = i >> 3;
        int c8 = (i & 7) * 8;
        uint32_t sw = SW128((uint32_t)(r * 128 + c8 * 2));
        *(uint4*)((char*)sK + sw) = *(const uint4*)(qkvb + HD_ + (size_t)r * N3C + c8);
    }
    FENCE_ASYNC_SHARED();
    TC_FENCE_BEFORE();
    __syncthreads();
    if (wid == 0 && elect_one()) {
        #pragma unroll
        for (int ks = 0; ks < 4; ks++)
            tc_mma_f16_ts(S0, Q0 + ks * 8, k_desc + ks * 2, IDESC_S, ks > 0);
        TC_COMMIT(mbarS);
    }

    float lsum = 0.f;
    const unsigned short* vT = (const unsigned short*)g_vT + (size_t)bh * HD_ * L_;
    const float SCALE_LOG2E = 0.125f * 1.44269504088896f;
    uint32_t woff = (uint32_t)wid << 21;

    for (int ch = 0; ch < 16; ch++) {
        // ---- S(ch) ready? read it ----
        mbar_wait(mbarS, (uint32_t)(ch & 1));
        TC_FENCE_AFTER();
        uint32_t sr[128];
        #pragma unroll
        for (int cc = 0; cc < 4; cc++) tc_ld_x32(sr + cc * 32, S0 + cc * 32);
        TC_WAIT_LD();

        // ---- load K[ch+1] and issue S(ch+1): overlaps with softmax below ----
        if (ch < 15) {
            #pragma unroll
            for (int t = 0; t < 8; t++) {
                int i = t * 128 + tid;
                int r = i >> 3;
                int c8 = (i & 7) * 8;
                uint32_t sw = SW128((uint32_t)(r * 128 + c8 * 2));
                *(uint4*)((char*)sK + sw) =
                    *(const uint4*)(qkvb + HD_ + (size_t)((ch + 1) * 128 + r) * N3C + c8);
            }
            FENCE_ASYNC_SHARED();
            __syncthreads();            // all warps done LDTM + K stores
            if (wid == 0 && elect_one()) {
                #pragma unroll
                for (int ks = 0; ks < 4; ks++)
                    tc_mma_f16_ts(S0, Q0 + ks * 8, k_desc + ks * 2, IDESC_S, ks > 0);
                TC_COMMIT(mbarS);
            }
        }

        // ---- wait O(ch-1) (short), then load V[ch] ----
        if (ch > 0) mbar_wait(mbarO, (uint32_t)((ch - 1) & 1));
        #pragma unroll
        for (int t = 0; t < 8; t++) {
            int i = t * 128 + tid;
            int d = i >> 4;
            int kk = (i & 15) * 8;
            int atom_col = kk >> 6;
            int inner_col = kk & 63;
            uint32_t off = (uint32_t)(((d >> 3) + atom_col * 8) * 1024 + (d & 7) * 128 + inner_col * 2);
            uint32_t sw = SW128(off);
            *(uint4*)((char*)sV + sw) = *(const uint4*)(vT + (size_t)d * L_ + ch * 128 + kk);
        }

        // ---- softmax (no max-sub), overlapped with S(ch+1) on tensor pipe ----
        uint32_t p[64];
        #pragma unroll
        for (int j = 0; j < 64; j++) {
            float e0 = exp2f(__uint_as_float(sr[2 * j + 0]) * SCALE_LOG2E);
            float e1 = exp2f(__uint_as_float(sr[2 * j + 1]) * SCALE_LOG2E);
            lsum += e0 + e1;
            __nv_bfloat162 pk = __floats2bfloat162_rn(e0, e1);
            p[j] = *(uint32_t*)&pk;
        }

        // ---- P to TMEM, O += P @ V^T ----
        {
            tc_st_x32(P0 + woff, p);
            tc_st_x32(P0 + 32 + woff, p + 32);
            TC_WAIT_ST();
        }
        FENCE_ASYNC_SHARED();
        TC_FENCE_BEFORE();
        __syncthreads();
        if (wid == 0 && elect_one()) {
            TC_FENCE_AFTER();
            #pragma unroll
            for (int s8 = 0; s8 < 8; s8++) {
                uint64_t boff = (uint64_t)((s8 >> 2) * 512 + (s8 & 3) * 2);
                tc_mma_f16_ts(O0, P0 + s8 * 8, v_desc + boff, IDESC_O,
                              (ch > 0 || s8 > 0));
            }
            TC_COMMIT(mbarO);
        }
        __syncthreads();
    }

    // ---- epilogue ----
    mbar_wait(mbarO, 1u);
    TC_FENCE_AFTER();
    {
        uint32_t d0[32], d1[32];
        tc_ld_x32(d0, O0);
        tc_ld_x32(d1, O0 + 32);
        TC_WAIT_LD();
        float inv = 1.f / lsum;
        bf16* op = g_att_bf + (size_t)(b * L_ + bm + tid) * C_ + h * HD_;
        #pragma unroll
        for (int j = 0; j < 16; j++) {
            __nv_bfloat162 a = __floats2bfloat162_rn(
                __uint_as_float(d0[2 * j]) * inv, __uint_as_float(d0[2 * j + 1]) * inv);
            ((__nv_bfloat162*)op)[j] = a;
        }
        #pragma unroll
        for (int j = 0; j < 16; j++) {
            __nv_bfloat162 a = __floats2bfloat162_rn(
                __uint_as_float(d1[2 * j]) * inv, __uint_as_float(d1[2 * j + 1]) * inv);
            ((__nv_bfloat162*)op)[16 + j] = a;
        }
    }
    TC_FENCE_BEFORE();
    __syncthreads();
    if (tid == 0) { MBAR_INVAL(mbarS); MBAR_INVAL(mbarO); }
    __syncthreads();
    if (wid == 0) {
        TC_RELINQ();
        TC_DEALLOC(tmem_base, 512);
    }
#else
    // ============ scalar fallback (R3-proven) ============
    __shared__ float Ks[32 * 64];
    __shared__ float Vs[32 * 64];

    int qrow = blockIdx.x * 128 + tid;

    const float* base = g_qkv + (size_t)b * L_ * N3C;
    const float* qptr = base + (size_t)qrow * N3C + h * (3 * HD_);
    const float* kbase = base + h * (3 * HD_) + HD_;
    const float* vbase = base + h * (3 * HD_) + 2 * HD_;

    float q[HD_];
    #pragma unroll
    for (int d4 = 0; d4 < HD_ / 4; d4++) {
        float4 t = *(const float4*)(qptr + d4 * 4);
        q[4 * d4 + 0] = t.x * 0.125f;
        q[4 * d4 + 1] = t.y * 0.125f;
        q[4 * d4 + 2] = t.z * 0.125f;
        q[4 * d4 + 3] = t.w * 0.125f;
    }
    float o[HD_];
    #pragma unroll
    for (int d = 0; d < HD_; d++) o[d] = 0.f;
    float m = -1e30f, l = 0.f;

    for (int kb = 0; kb < L_ / 32; kb++) {
        __syncthreads();
        #pragma unroll
        for (int t = 0; t < 4; t++) {
            int idx = t * 128 + tid;
            int r = idx >> 4;
            int c4 = (idx & 15) * 4;
            size_t goff = (size_t)(kb * 32 + r) * N3C + c4;
            *(float4*)&Ks[r * 64 + c4] = *(const float4*)(kbase + goff);
            *(float4*)&Vs[r * 64 + c4] = *(const float4*)(vbase + goff);
        }
        __syncthreads();

        float s[32];
        #pragma unroll
        for (int j = 0; j < 32; j++) {
            float accv = 0.f;
            #pragma unroll
            for (int d = 0; d < HD_; d++) accv += q[d] * Ks[j * 64 + d];
            s[j] = accv;
        }
        float mnew = m;
        #pragma unroll
        for (int j = 0; j < 32; j++) mnew = fmaxf(mnew, s[j]);
        float corr = __expf(m - mnew);
        l *= corr;
        #pragma unroll
        for (int d = 0; d < HD_; d++) o[d] *= corr;
        #pragma unroll
        for (int j = 0; j < 32; j++) {
            float pp = __expf(s[j] - mnew);
            l += pp;
            #pragma unroll
            for (int d = 0; d < HD_; d++) o[d] += pp * Vs[j * 64 + d];
        }
        m = mnew;
    }

    float inv = 1.f / l;
    size_t obase = (size_t)(b * L_ + qrow) * C_ + h * HD_;
    float* opf = g_att + obase;
    bf16* opb = g_att_bf + obase;
    #pragma unroll
    for (int d4 = 0; d4 < HD_ / 4; d4++) {
        float4 t;
        t.x = o[4 * d4 + 0] * inv;
        t.y = o[4 * d4 + 1] * inv;
        t.z = o[4 * d4 + 2] * inv;
        t.w = o[4 * d4 + 3] * inv;
        *(float4*)(opf + 4 * d4) = t;
        ((__nv_bfloat162*)opb)[2 * d4]     = __floats2bfloat162_rn(t.x, t.y);
        ((__nv_bfloat162*)opb)[2 * d4 + 1] = __floats2bfloat162_rn(t.z, t.w);
    }
#endif
}

// ---------------- launcher ----------------
extern "C" void kernel_launch(void* const* d_in, const int* in_sizes, int n_in,
                              void* d_out, int out_size) {
    const float* x        = (const float*)d_in[0];
    const float* gn_scale = (const float*)d_in[1];
    const float* gn_bias  = (const float*)d_in[2];
    const float* qkv_w    = (const float*)d_in[3];
    const float* qkv_b    = (const float*)d_in[4];
    const float* proj_w   = (const float*)d_in[5];
    const float* proj_b   = (const float*)d_in[6];
    float* out = (float*)d_out;

    // 0) transpose+convert weights
    {
        dim3 blk(32, 8);
        dim3 gq(N3C / 32, C_ / 32);
        wtrans_kernel<<<gq, blk>>>(qkv_w, C_, N3C, 0);
        dim3 gp(C_ / 32, C_ / 32);
        wtrans_kernel<<<gp, blk>>>(proj_w, C_, C_, 1);
    }

    // 1) GroupNorm stats (two-phase)
    {
        dim3 gpart(B_ * G_, 8);
        gn_part_kernel<<<gpart, 256>>>(x);
        gn_stats_kernel<<<B_ * G_, 32>>>();
    }

    // 2) apply GroupNorm
    {
        int total4 = ML * C_ / 4;
        gn_apply_kernel<<<(total4 + 255) / 256, 256>>>(x, gn_scale, gn_bias);
    }

    // 3) QKV GEMM
    {
        dim3 grid(N3C / 128, ML / 128);
        gemm_kernel<0><<<grid, 256>>>(qkv_w, qkv_b, nullptr, nullptr, N3C, C_);
    }

    // 3.5) V^T transpose (feature path)
    {
        dim3 blk(32, 8);
        dim3 gv(L_ / 32, HD_ / 32, B_ * H_);
        vtrans_kernel<<<gv, blk>>>();
    }

    // 4) flash attention
    {
        dim3 grid(L_ / 128, B_ * H_);
        flash_kernel<<<grid, 128>>>();
    }

    // 5) proj GEMM + residual
    {
        dim3 grid(C_ / 128, ML / 128);
        gemm_kernel<1><<<grid, 256>>>(proj_w, proj_b, x, out, C_, C_);
    }
}

// round 15
// speedup vs baseline: 1.1815x; 1.0281x over previous
#include <cuda_runtime.h>
#include <cuda_bf16.h>
#include <math.h>
#include <stdint.h>

#define B_  2
#define L_  2048
#define C_  1024
#define H_  16
#define HD_ 64
#define G_  32
#define CG_ 32
#define N3C (3 * C_)
#define ML  (B_ * L_)   // 4096 rows

typedef __nv_bfloat16 bf16;

// ---------------- scratch (static device globals) ----------------
__device__ float g_stats[B_ * G_ * 2];
__device__ float g_part[B_ * G_ * 8 * 2];         // two-phase GN partials
__device__ int   g_cnt[B_ * G_];                  // finalize counters (self-resetting)
__device__ float g_xn[(size_t)ML * C_];           // normalized input fp32 (fallback only)
__device__ bf16  g_xn_bf[(size_t)ML * C_];        // normalized input bf16
__device__ float g_qkv[(size_t)ML * N3C];         // qkv fp32 (fallback only)
__device__ bf16  g_qkv_bf[(size_t)ML * N3C];      // qkv bf16 (feature path)
__device__ float g_att[(size_t)ML * C_];          // attention out fp32 (fallback only)
__device__ bf16  g_att_bf[(size_t)ML * C_];       // attention out bf16
__device__ bf16  g_wqT[(size_t)N3C * C_];         // qkv_w^T bf16 [N,K]
__device__ bf16  g_wpT[(size_t)C_ * C_];          // proj_w^T bf16 [N,K]
__device__ bf16  g_vT[(size_t)B_ * H_ * HD_ * L_]; // V^T [bh][d][key] bf16

// ---------------- helpers ----------------
__device__ __forceinline__ uint32_t smem_u32(const void* p) {
    return (uint32_t)__cvta_generic_to_shared(p);
}

#ifdef __CUDA_ARCH_FEAT_SM103_ALL
__device__ __forceinline__ uint32_t elect_one() {
    uint32_t pred;
    asm volatile("{\n\t.reg .pred p;\n\telect.sync _|p, 0xFFFFFFFF;\n\t"
                 "selp.b32 %0, 1, 0, p;\n\t}" : "=r"(pred));
    return pred;
}
#define TC_ALLOC(smem_addr, ncols) \
    asm volatile("tcgen05.alloc.cta_group::1.sync.aligned.shared::cta.b32 [%0], %1;" \
                 :: "r"(smem_addr), "r"(ncols) : "memory")
#define TC_DEALLOC(tmem, ncols) \
    asm volatile("tcgen05.dealloc.cta_group::1.sync.aligned.b32 %0, %1;" :: "r"(tmem), "r"(ncols))
#define TC_RELINQ() \
    asm volatile("tcgen05.relinquish_alloc_permit.cta_group::1.sync.aligned;")
#define TC_COMMIT(mbar) \
    asm volatile("tcgen05.commit.cta_group::1.mbarrier::arrive::one.shared::cluster.b64 [%0];" \
                 :: "r"(mbar) : "memory")
#define TC_FENCE_AFTER()  asm volatile("tcgen05.fence::after_thread_sync;" ::: "memory")
#define TC_FENCE_BEFORE() asm volatile("tcgen05.fence::before_thread_sync;" ::: "memory")
#define TC_WAIT_LD()      asm volatile("tcgen05.wait::ld.sync.aligned;" ::: "memory")
#define TC_WAIT_ST()      asm volatile("tcgen05.wait::st.sync.aligned;" ::: "memory")
#define MBAR_INIT(mbar, cnt) \
    asm volatile("mbarrier.init.shared.b64 [%0], %1;" :: "r"(mbar), "r"(cnt) : "memory")
#define MBAR_INVAL(mbar) \
    asm volatile("mbarrier.inval.shared.b64 [%0];" :: "r"(mbar) : "memory")
#define FENCE_ASYNC_SHARED() asm volatile("fence.proxy.async.shared::cta;" ::: "memory")

__device__ __forceinline__ void mbar_wait(uint32_t mbar, uint32_t parity) {
    asm volatile(
        "{\n\t.reg .pred P1;\n\t"
        "WAIT_LOOP_%=:\n\t"
        "mbarrier.try_wait.parity.acquire.cta.shared::cta.b64 P1, [%0], %1, 0x989680;\n\t"
        "@P1 bra.uni WAIT_DONE_%=;\n\t"
        "bra.uni WAIT_LOOP_%=;\n\t"
        "WAIT_DONE_%=:\n\t}"
        :: "r"(mbar), "r"(parity) : "memory");
}

__device__ __forceinline__ void tc_mma_f16_ss(uint32_t d_tmem, uint64_t a_desc,
                                              uint64_t b_desc, uint32_t idesc,
                                              uint32_t enable) {
    asm volatile(
        "{\n\t.reg .pred p;\n\tsetp.ne.u32 p, %5, 0;\n\t"
        "tcgen05.mma.cta_group::1.kind::f16 [%0], %1, %2, %3, {%4,%4,%4,%4}, p;\n\t}"
        :: "r"(d_tmem), "l"(a_desc), "l"(b_desc), "r"(idesc), "r"(0u), "r"(enable)
        : "memory");
}
__device__ __forceinline__ void tc_mma_f16_ts(uint32_t d_tmem, uint32_t a_tmem,
                                              uint64_t b_desc, uint32_t idesc,
                                              uint32_t enable) {
    asm volatile(
        "{\n\t.reg .pred p;\n\tsetp.ne.u32 p, %5, 0;\n\t"
        "tcgen05.mma.cta_group::1.kind::f16 [%0], [%1], %2, %3, {%4,%4,%4,%4}, p;\n\t}"
        :: "r"(d_tmem), "r"(a_tmem), "l"(b_desc), "r"(idesc), "r"(0u), "r"(enable)
        : "memory");
}

__device__ __forceinline__ void tc_ld_x32(uint32_t* r, uint32_t tmem_addr) {
    asm volatile(
        "tcgen05.ld.sync.aligned.32x32b.x32.b32 "
        "{%0, %1, %2, %3, %4, %5, %6, %7, %8, %9, %10, %11, %12, %13, %14, %15, "
        " %16, %17, %18, %19, %20, %21, %22, %23, %24, %25, %26, %27, %28, %29, %30, %31}, [%32];"
        : "=r"(r[0]), "=r"(r[1]), "=r"(r[2]), "=r"(r[3]), "=r"(r[4]), "=r"(r[5]),
          "=r"(r[6]), "=r"(r[7]), "=r"(r[8]), "=r"(r[9]), "=r"(r[10]), "=r"(r[11]),
          "=r"(r[12]), "=r"(r[13]), "=r"(r[14]), "=r"(r[15]), "=r"(r[16]), "=r"(r[17]),
          "=r"(r[18]), "=r"(r[19]), "=r"(r[20]), "=r"(r[21]), "=r"(r[22]), "=r"(r[23]),
          "=r"(r[24]), "=r"(r[25]), "=r"(r[26]), "=r"(r[27]), "=r"(r[28]), "=r"(r[29]),
          "=r"(r[30]), "=r"(r[31])
        : "r"(tmem_addr));
}

__device__ __forceinline__ void tc_st_x32(uint32_t tmem_addr, const uint32_t* r) {
    asm volatile(
        "tcgen05.st.sync.aligned.32x32b.x32.b32 [%0], "
        "{%1, %2, %3, %4, %5, %6, %7, %8, %9, %10, %11, %12, %13, %14, %15, %16, "
        " %17, %18, %19, %20, %21, %22, %23, %24, %25, %26, %27, %28, %29, %30, %31, %32};"
        :: "r"(tmem_addr),
           "r"(r[0]), "r"(r[1]), "r"(r[2]), "r"(r[3]), "r"(r[4]), "r"(r[5]),
           "r"(r[6]), "r"(r[7]), "r"(r[8]), "r"(r[9]), "r"(r[10]), "r"(r[11]),
           "r"(r[12]), "r"(r[13]), "r"(r[14]), "r"(r[15]), "r"(r[16]), "r"(r[17]),
           "r"(r[18]), "r"(r[19]), "r"(r[20]), "r"(r[21]), "r"(r[22]), "r"(r[23]),
           "r"(r[24]), "r"(r[25]), "r"(r[26]), "r"(r[27]), "r"(r[28]), "r"(r[29]),
           "r"(r[30]), "r"(r[31])
        : "memory");
}

#define SW128(off) ((off) ^ (((off) >> 3) & 0x70))
__device__ __forceinline__ uint64_t make_desc_sw128(uint32_t base_addr) {
    const uint64_t BASE =
        (uint64_t(2) << 61) | (uint64_t(1) << 46) | (uint64_t(64) << 32) | (uint64_t(1) << 16);
    return BASE | ((uint64_t)(base_addr >> 4) & 0x3FFF);
}
#define IDESC_F16(Mv, Nv) ((1u << 4) | (1u << 7) | (1u << 10) | (((Nv) / 8) << 17) | (((Mv) / 16) << 24))
#define IDESC_128x128 IDESC_F16(128, 128)
#endif  // __CUDA_ARCH_FEAT_SM103_ALL

// ---------------- kernel 1: GroupNorm partial sums + fused finalize ----------------
// grid = (B*G, 8). Last-arriving block per group finalizes mu/rstd (fixed sum order).
__global__ void gn_part_kernel(const float* __restrict__ x) {
    int bg = blockIdx.x;
    int part = blockIdx.y;
    int b = bg / G_;
    int g = bg % G_;
    const float* xp = x + (size_t)b * L_ * C_ + g * CG_;

    float s = 0.f, s2 = 0.f;
    #pragma unroll
    for (int t = 0; t < 8; t++) {
        int i = t * 256 + threadIdx.x;
        int l = part * 256 + (i >> 3);
        int c4 = (i & 7) * 4;
        float4 v = *(const float4*)(xp + (size_t)l * C_ + c4);
        s  += v.x + v.y + v.z + v.w;
        s2 += v.x * v.x + v.y * v.y + v.z * v.z + v.w * v.w;
    }
    #pragma unroll
    for (int o = 16; o > 0; o >>= 1) {
        s  += __shfl_down_sync(0xFFFFFFFFu, s, o);
        s2 += __shfl_down_sync(0xFFFFFFFFu, s2, o);
    }
    __shared__ float sh[2][8];
    int w = threadIdx.x >> 5, ln = threadIdx.x & 31;
    if (ln == 0) { sh[0][w] = s; sh[1][w] = s2; }
    __syncthreads();
    if (w == 0 && ln < 8) {
        s = sh[0][ln]; s2 = sh[1][ln];
        #pragma unroll
        for (int o = 4; o > 0; o >>= 1) {
            s  += __shfl_down_sync(0x000000FFu, s, o);
            s2 += __shfl_down_sync(0x000000FFu, s2, o);
        }
        if (ln == 0) {
            g_part[(bg * 8 + part) * 2 + 0] = s;
            g_part[(bg * 8 + part) * 2 + 1] = s2;
            __threadfence();
            int done = atomicAdd(&g_cnt[bg], 1);
            if (done == 7) {
                __threadfence();
                float ts = 0.f, ts2 = 0.f;
                #pragma unroll
                for (int p2 = 0; p2 < 8; p2++) {
                    ts  += g_part[(bg * 8 + p2) * 2 + 0];
                    ts2 += g_part[(bg * 8 + p2) * 2 + 1];
                }
                const float inv_n = 1.0f / (float)(L_ * CG_);
                float mu  = ts * inv_n;
                float var = ts2 * inv_n - mu * mu;
                g_stats[bg * 2 + 0] = mu;
                g_stats[bg * 2 + 1] = rsqrtf(var + 1e-6f);
                g_cnt[bg] = 0;     // reset for graph replay
            }
        }
    }
}

// ---------------- kernel 2: apply GroupNorm ----------------
__global__ void gn_apply_kernel(const float* __restrict__ x,
                                const float* __restrict__ gamma,
                                const float* __restrict__ beta) {
    size_t i = (size_t)blockIdx.x * blockDim.x + threadIdx.x;
    size_t base = i * 4;
    if (base >= (size_t)ML * C_) return;
    int c  = (int)(base % C_);
    int bl = (int)(base / C_);
    int b  = bl >> 11;
    int g  = c >> 5;
    float mu = g_stats[(b * G_ + g) * 2 + 0];
    float rs = g_stats[(b * G_ + g) * 2 + 1];
    float4 xv = *(const float4*)(x + base);
    float4 gv = *(const float4*)(gamma + c);
    float4 bv = *(const float4*)(beta + c);
    float4 r;
    r.x = (xv.x - mu) * rs * gv.x + bv.x;
    r.y = (xv.y - mu) * rs * gv.y + bv.y;
    r.z = (xv.z - mu) * rs * gv.z + bv.z;
    r.w = (xv.w - mu) * rs * gv.w + bv.w;
#ifndef __CUDA_ARCH_FEAT_SM103_ALL
    *(float4*)(g_xn + base) = r;     // fallback GEMM input only
#endif
    ((__nv_bfloat162*)g_xn_bf)[2 * i]     = __floats2bfloat162_rn(r.x, r.y);
    ((__nv_bfloat162*)g_xn_bf)[2 * i + 1] = __floats2bfloat162_rn(r.z, r.w);
}

// ---------------- merged weight transpose + convert (both weights, one launch) ----------------
// grid = (N3C/32 + C_/32, C_/32) = (128, 32), block (32, 8)
__global__ void wtrans_kernel(const float* __restrict__ wq, const float* __restrict__ wp) {
    __shared__ float tile[32][33];
    int bx = blockIdx.x;
    const float* src;
    bf16* dst;
    int N, n0;
    if (bx < N3C / 32) { src = wq; dst = g_wqT; N = N3C; n0 = bx * 32; }
    else               { src = wp; dst = g_wpT; N = C_;  n0 = (bx - N3C / 32) * 32; }
    int k0 = blockIdx.y * 32;
    int tx = threadIdx.x, ty = threadIdx.y;
    #pragma unroll
    for (int i = 0; i < 32; i += 8)
        tile[ty + i][tx] = src[(size_t)(k0 + ty + i) * N + n0 + tx];
    __syncthreads();
    #pragma unroll
    for (int i = 0; i < 32; i += 8)
        dst[(size_t)(n0 + ty + i) * C_ + k0 + tx] = __float2bfloat16(tile[tx][ty + i]);
}

// ---------------- V^T transpose (feature path) ----------------
__global__ void vtrans_kernel() {
#ifdef __CUDA_ARCH_FEAT_SM103_ALL
    __shared__ unsigned short tile[32][33];
    int l0 = blockIdx.x * 32;
    int d0 = blockIdx.y * 32;
    int bh = blockIdx.z;
    int b = bh >> 4, h = bh & 15;
    int tx = threadIdx.x, ty = threadIdx.y;
    const unsigned short* src = (const unsigned short*)g_qkv_bf
        + (size_t)b * L_ * N3C + h * (3 * HD_) + 2 * HD_;
    #pragma unroll
    for (int i = 0; i < 32; i += 8)
        tile[ty + i][tx] = src[(size_t)(l0 + ty + i) * N3C + d0 + tx];
    __syncthreads();
    unsigned short* dst = (unsigned short*)g_vT + (size_t)bh * HD_ * L_;
    #pragma unroll
    for (int i = 0; i < 32; i += 8)
        dst[(size_t)(d0 + ty + i) * L_ + l0 + tx] = tile[tx][ty + i];
#endif
}

// ---------------- kernel 3/5: GEMM, dual path ----------------
template <int EPI>
__global__ __launch_bounds__(256) void gemm_kernel(
    const float* __restrict__ W,
    const float* __restrict__ bias,
    const float* __restrict__ resid,
    float*       __restrict__ OutParam,
    int N, int K)
{
    const float rsqrt2 = 0.70710678118654752f;
    int tid = threadIdx.x;
    int bm = blockIdx.y * 128;
    int bn = blockIdx.x * 128;

#ifdef __CUDA_ARCH_FEAT_SM103_ALL
    __shared__ __align__(1024) bf16 sA[2][128 * 64];
    __shared__ __align__(1024) bf16 sB[2][128 * 64];
    __shared__ float bias_s[128];
    __shared__ __align__(8) uint64_t mbar_store[2];
    __shared__ uint32_t tmem_ptr_store;

    const bf16* A  = (EPI == 0) ? g_xn_bf : g_att_bf;
    const bf16* WT = (EPI == 0) ? g_wqT   : g_wpT;

    int wid = tid >> 5;
    int lane = tid & 31;
    uint32_t mbar0 = smem_u32(&mbar_store[0]);
    uint32_t mbar1 = smem_u32(&mbar_store[1]);
    uint32_t tptr_addr = smem_u32(&tmem_ptr_store);

    if (wid == 0) TC_ALLOC(tptr_addr, 128);
    if (tid == 0) { MBAR_INIT(mbar0, 1); MBAR_INIT(mbar1, 1); }
    if (tid < 128) bias_s[tid] = bias[bn + tid];
    __syncthreads();
    uint32_t tmem_base;
    asm volatile("ld.shared.b32 %0, [%1];" : "=r"(tmem_base) : "r"(tptr_addr));

    uint64_t a_desc[2] = { make_desc_sw128(smem_u32(sA[0])), make_desc_sw128(smem_u32(sA[1])) };
    uint64_t b_desc[2] = { make_desc_sw128(smem_u32(sB[0])), make_desc_sw128(smem_u32(sB[1])) };

    const int NCHUNK = K / 64;
    for (int ch = 0; ch < NCHUNK; ch++) {
        int buf = ch & 1;
        uint32_t mb = buf ? mbar1 : mbar0;
        if (ch >= 2) mbar_wait(mb, (uint32_t)(((ch >> 1) - 1) & 1));

        int k0 = ch * 64;
        #pragma unroll
        for (int t = 0; t < 4; t++) {
            int i = t * 256 + tid;
            int r = i >> 3;
            int c8 = (i & 7) * 8;
            uint32_t sw = SW128((uint32_t)(r * 128 + c8 * 2));
            *(uint4*)((char*)sA[buf] + sw) = *(const uint4*)(A  + (size_t)(bm + r) * K + k0 + c8);
            *(uint4*)((char*)sB[buf] + sw) = *(const uint4*)(WT + (size_t)(bn + r) * K + k0 + c8);
        }
        FENCE_ASYNC_SHARED();
        __syncthreads();

        if (wid == 0 && elect_one()) {
            #pragma unroll
            for (int ks = 0; ks < 4; ks++) {
                uint32_t en = (ch > 0 || ks > 0) ? 1u : 0u;
                tc_mma_f16_ss(tmem_base, a_desc[buf] + ks * 2, b_desc[buf] + ks * 2,
                              IDESC_128x128, en);
            }
            TC_COMMIT(mb);
        }
    }

    mbar_wait(mbar1, 1u);
    TC_FENCE_AFTER();

    {
        int row = bm + (wid & 3) * 32 + lane;
        int chalf = (wid >> 2) * 64;
        #pragma unroll
        for (int cc = 0; cc < 2; cc++) {
            uint32_t d[32];
            tc_ld_x32(d, tmem_base + chalf + cc * 32);
            TC_WAIT_LD();
            int colbase = bn + chalf + cc * 32;
            #pragma unroll
            for (int j = 0; j < 8; j++) {
                float4 v;
                v.x = __uint_as_float(d[4 * j + 0]) + bias_s[chalf + cc * 32 + 4 * j + 0];
                v.y = __uint_as_float(d[4 * j + 1]) + bias_s[chalf + cc * 32 + 4 * j + 1];
                v.z = __uint_as_float(d[4 * j + 2]) + bias_s[chalf + cc * 32 + 4 * j + 2];
                v.w = __uint_as_float(d[4 * j + 3]) + bias_s[chalf + cc * 32 + 4 * j + 3];
                if (EPI == 1) {
                    float4 rv = *(const float4*)(resid + (size_t)row * N + colbase + 4 * j);
                    v.x = (v.x + rv.x) * rsqrt2;
                    v.y = (v.y + rv.y) * rsqrt2;
                    v.z = (v.z + rv.z) * rsqrt2;
                    v.w = (v.w + rv.w) * rsqrt2;
                    *(float4*)(OutParam + (size_t)row * N + colbase + 4 * j) = v;
                } else {
                    __nv_bfloat162 lo = __floats2bfloat162_rn(v.x, v.y);
                    __nv_bfloat162 hi = __floats2bfloat162_rn(v.z, v.w);
                    uint2 pk = make_uint2(*(uint32_t*)&lo, *(uint32_t*)&hi);
                    *(uint2*)(g_qkv_bf + (size_t)row * N + colbase + 4 * j) = pk;
                }
            }
        }
    }
    TC_FENCE_BEFORE();
    __syncthreads();
    if (tid == 0) { MBAR_INVAL(mbar0); MBAR_INVAL(mbar1); }
    __syncthreads();
    if (wid == 0) {
        TC_RELINQ();
        TC_DEALLOC(tmem_base, 128);
    }
#else
    // fp32 FFMA fallback (R3-proven)
    const float* A = (EPI == 0) ? g_xn : g_att;
    float* Cout    = (EPI == 0) ? g_qkv : OutParam;

    __shared__ float As[8][128];
    __shared__ float Bs[8][128];

    int tx = tid & 15;
    int ty = tid >> 4;

    float acc[8][8];
    #pragma unroll
    for (int i = 0; i < 8; i++)
        #pragma unroll
        for (int j = 0; j < 8; j++) acc[i][j] = 0.f;

    int arow = tid >> 1;
    int acol = (tid & 1) * 4;
    int brow = tid >> 5;
    int bcol = (tid & 31) * 4;

    const float* Aptr = A + (size_t)(bm + arow) * K + acol;
    const float* Bptr = W + (size_t)brow * N + bn + bcol;

    for (int k0 = 0; k0 < K; k0 += 8) {
        float4 av = *(const float4*)(Aptr + k0);
        float4 bv = *(const float4*)(Bptr + (size_t)k0 * N);
        As[acol + 0][arow] = av.x;
        As[acol + 1][arow] = av.y;
        As[acol + 2][arow] = av.z;
        As[acol + 3][arow] = av.w;
        *(float4*)&Bs[brow][bcol] = bv;
        __syncthreads();
        #pragma unroll
        for (int kk = 0; kk < 8; kk++) {
            float a[8], bfv[8];
            #pragma unroll
            for (int i = 0; i < 8; i++) a[i] = As[kk][ty * 8 + i];
            #pragma unroll
            for (int i = 0; i < 8; i++) bfv[i] = Bs[kk][tx * 8 + i];
            #pragma unroll
            for (int i = 0; i < 8; i++)
                #pragma unroll
                for (int j = 0; j < 8; j++)
                    acc[i][j] += a[i] * bfv[j];
        }
        __syncthreads();
    }

    #pragma unroll
    for (int i = 0; i < 8; i++) {
        int row = bm + ty * 8 + i;
        #pragma unroll
        for (int j = 0; j < 8; j += 4) {
            int col = bn + tx * 8 + j;
            float4 bb = *(const float4*)(bias + col);
            float4 v;
            v.x = acc[i][j + 0] + bb.x;
            v.y = acc[i][j + 1] + bb.y;
            v.z = acc[i][j + 2] + bb.z;
            v.w = acc[i][j + 3] + bb.w;
            if (EPI == 1) {
                float4 rv = *(const float4*)(resid + (size_t)row * N + col);
                v.x = (v.x + rv.x) * rsqrt2;
                v.y = (v.y + rv.y) * rsqrt2;
                v.z = (v.z + rv.z) * rsqrt2;
                v.w = (v.w + rv.w) * rsqrt2;
            }
            *(float4*)(Cout + (size_t)row * N + col) = v;
        }
    }
#endif
}

// ---------------- kernel 4: flash attention, dual path ----------------
// Feature path: R10 structure, Q moved TMEM->smem (SS mode) => 256 TMEM cols => 2 CTAs/SM.
__global__ __launch_bounds__(128) void flash_kernel() {
    int bh = blockIdx.y;
    int b = bh >> 4;
    int h = bh & 15;
    int tid = threadIdx.x;

#ifdef __CUDA_ARCH_FEAT_SM103_ALL
    __shared__ __align__(1024) bf16 sQ[128 * 64];    // Q [rows][dims] SW128
    __shared__ __align__(1024) bf16 sK[128 * 64];    // K chunk [keys][dims] SW128
    __shared__ __align__(1024) bf16 sV[64 * 128];    // V^T chunk [dims][keys] blocked SW128
    __shared__ __align__(8) uint64_t mbar_store[2];  // S, O
    __shared__ uint32_t tmem_ptr_store;

    int wid = tid >> 5;
    int bm = blockIdx.x * 128;

    uint32_t mbarS = smem_u32(&mbar_store[0]);
    uint32_t mbarO = smem_u32(&mbar_store[1]);
    uint32_t tptr_addr = smem_u32(&tmem_ptr_store);

    if (wid == 0) TC_ALLOC(tptr_addr, 256);
    if (tid == 0) { MBAR_INIT(mbarS, 1); MBAR_INIT(mbarO, 1); }
    __syncthreads();
    uint32_t tmem_base;
    asm volatile("ld.shared.b32 %0, [%1];" : "=r"(tmem_base) : "r"(tptr_addr));

    const uint32_t S0 = tmem_base + 0;      // S: 128 cols fp32
    const uint32_t P0 = tmem_base + 128;    // P: 64 cols bf16x2
    const uint32_t O0 = tmem_base + 192;    // O: 64 cols fp32

    const bf16* qkvb = g_qkv_bf + (size_t)b * L_ * N3C + h * (3 * HD_);

    uint64_t q_desc = make_desc_sw128(smem_u32(sQ));
    uint64_t k_desc = make_desc_sw128(smem_u32(sK));
    uint64_t v_desc = make_desc_sw128(smem_u32(sV));
    const uint32_t IDESC_S = IDESC_F16(128, 128);
    const uint32_t IDESC_O = IDESC_F16(128, 64);

    // ---- prologue: load Q + K[0], issue S(0) ----
    #pragma unroll
    for (int t = 0; t < 8; t++) {
        int i = t * 128 + tid;
        int r = i >> 3;
        int c8 = (i & 7) * 8;
        uint32_t sw = SW128((uint32_t)(r * 128 + c8 * 2));
        *(uint4*)((char*)sQ + sw) = *(const uint4*)(qkvb + (size_t)(bm + r) * N3C + c8);
        *(uint4*)((char*)sK + sw) = *(const uint4*)(qkvb + HD_ + (size_t)r * N3C + c8);
    }
    FENCE_ASYNC_SHARED();
    __syncthreads();
    if (wid == 0 && elect_one()) {
        #pragma unroll
        for (int ks = 0; ks < 4; ks++)
            tc_mma_f16_ss(S0, q_desc + ks * 2, k_desc + ks * 2, IDESC_S, ks > 0);
        TC_COMMIT(mbarS);
    }

    float lsum = 0.f;
    const unsigned short* vT = (const unsigned short*)g_vT + (size_t)bh * HD_ * L_;
    const float SCALE_LOG2E = 0.125f * 1.44269504088896f;
    uint32_t woff = (uint32_t)wid << 21;

    for (int ch = 0; ch < 16; ch++) {
        // ---- S(ch) ready? read it (full, like R10) ----
        mbar_wait(mbarS, (uint32_t)(ch & 1));
        TC_FENCE_AFTER();
        uint32_t sr[128];
        #pragma unroll
        for (int cc = 0; cc < 4; cc++) tc_ld_x32(sr + cc * 32, S0 + cc * 32);
        TC_WAIT_LD();

        // ---- load K[ch+1] and issue S(ch+1): overlaps softmax below ----
        if (ch < 15) {
            #pragma unroll
            for (int t = 0; t < 8; t++) {
                int i = t * 128 + tid;
                int r = i >> 3;
                int c8 = (i & 7) * 8;
                uint32_t sw = SW128((uint32_t)(r * 128 + c8 * 2));
                *(uint4*)((char*)sK + sw) =
                    *(const uint4*)(qkvb + HD_ + (size_t)((ch + 1) * 128 + r) * N3C + c8);
            }
            FENCE_ASYNC_SHARED();
            __syncthreads();            // all warps done LDTM + K stores
            if (wid == 0 && elect_one()) {
                #pragma unroll
                for (int ks = 0; ks < 4; ks++)
                    tc_mma_f16_ss(S0, q_desc + ks * 2, k_desc + ks * 2, IDESC_S, ks > 0);
                TC_COMMIT(mbarS);
            }
        }

        // ---- wait O(ch-1) (short), then load V[ch] ----
        if (ch > 0) mbar_wait(mbarO, (uint32_t)((ch - 1) & 1));
        #pragma unroll
        for (int t = 0; t < 8; t++) {
            int i = t * 128 + tid;
            int d = i >> 4;
            int kk = (i & 15) * 8;
            int atom_col = kk >> 6;
            int inner_col = kk & 63;
            uint32_t off = (uint32_t)(((d >> 3) + atom_col * 8) * 1024 + (d & 7) * 128 + inner_col * 2);
            uint32_t sw = SW128(off);
            *(uint4*)((char*)sV + sw) = *(const uint4*)(vT + (size_t)d * L_ + ch * 128 + kk);
        }

        // ---- softmax (no max-sub), overlapped with S(ch+1) on tensor pipe ----
        uint32_t p[64];
        #pragma unroll
        for (int j = 0; j < 64; j++) {
            float e0 = exp2f(__uint_as_float(sr[2 * j + 0]) * SCALE_LOG2E);
            float e1 = exp2f(__uint_as_float(sr[2 * j + 1]) * SCALE_LOG2E);
            lsum += e0 + e1;
            __nv_bfloat162 pk = __floats2bfloat162_rn(e0, e1);
            p[j] = *(uint32_t*)&pk;
        }

        // ---- P to TMEM, O += P @ V^T ----
        {
            tc_st_x32(P0 + woff, p);
            tc_st_x32(P0 + 32 + woff, p + 32);
            TC_WAIT_ST();
        }
        FENCE_ASYNC_SHARED();
        TC_FENCE_BEFORE();
        __syncthreads();
        if (wid == 0 && elect_one()) {
            TC_FENCE_AFTER();
            #pragma unroll
            for (int s8 = 0; s8 < 8; s8++) {
                uint64_t boff = (uint64_t)((s8 >> 2) * 512 + (s8 & 3) * 2);
                tc_mma_f16_ts(O0, P0 + s8 * 8, v_desc + boff, IDESC_O,
                              (ch > 0 || s8 > 0));
            }
            TC_COMMIT(mbarO);
        }
        __syncthreads();
    }

    // ---- epilogue ----
    mbar_wait(mbarO, 1u);
    TC_FENCE_AFTER();
    {
        uint32_t d0[32], d1[32];
        tc_ld_x32(d0, O0);
        tc_ld_x32(d1, O0 + 32);
        TC_WAIT_LD();
        float inv = 1.f / lsum;
        bf16* op = g_att_bf + (size_t)(b * L_ + bm + tid) * C_ + h * HD_;
        #pragma unroll
        for (int j = 0; j < 16; j++) {
            __nv_bfloat162 a = __floats2bfloat162_rn(
                __uint_as_float(d0[2 * j]) * inv, __uint_as_float(d0[2 * j + 1]) * inv);
            ((__nv_bfloat162*)op)[j] = a;
        }
        #pragma unroll
        for (int j = 0; j < 16; j++) {
            __nv_bfloat162 a = __floats2bfloat162_rn(
                __uint_as_float(d1[2 * j]) * inv, __uint_as_float(d1[2 * j + 1]) * inv);
            ((__nv_bfloat162*)op)[16 + j] = a;
        }
    }
    TC_FENCE_BEFORE();
    __syncthreads();
    if (tid == 0) { MBAR_INVAL(mbarS); MBAR_INVAL(mbarO); }
    __syncthreads();
    if (wid == 0) {
        TC_RELINQ();
        TC_DEALLOC(tmem_base, 256);
    }
#else
    // ============ scalar fallback (R3-proven) ============
    __shared__ float Ks[32 * 64];
    __shared__ float Vs[32 * 64];

    int qrow = blockIdx.x * 128 + tid;

    const float* base = g_qkv + (size_t)b * L_ * N3C;
    const float* qptr = base + (size_t)qrow * N3C + h * (3 * HD_);
    const float* kbase = base + h * (3 * HD_) + HD_;
    const float* vbase = base + h * (3 * HD_) + 2 * HD_;

    float q[HD_];
    #pragma unroll
    for (int d4 = 0; d4 < HD_ / 4; d4++) {
        float4 t = *(const float4*)(qptr + d4 * 4);
        q[4 * d4 + 0] = t.x * 0.125f;
        q[4 * d4 + 1] = t.y * 0.125f;
        q[4 * d4 + 2] = t.z * 0.125f;
        q[4 * d4 + 3] = t.w * 0.125f;
    }
    float o[HD_];
    #pragma unroll
    for (int d = 0; d < HD_; d++) o[d] = 0.f;
    float m = -1e30f, l = 0.f;

    for (int kb = 0; kb < L_ / 32; kb++) {
        __syncthreads();
        #pragma unroll
        for (int t = 0; t < 4; t++) {
            int idx = t * 128 + tid;
            int r = idx >> 4;
            int c4 = (idx & 15) * 4;
            size_t goff = (size_t)(kb * 32 + r) * N3C + c4;
            *(float4*)&Ks[r * 64 + c4] = *(const float4*)(kbase + goff);
            *(float4*)&Vs[r * 64 + c4] = *(const float4*)(vbase + goff);
        }
        __syncthreads();

        float s[32];
        #pragma unroll
        for (int j = 0; j < 32; j++) {
            float accv = 0.f;
            #pragma unroll
            for (int d = 0; d < HD_; d++) accv += q[d] * Ks[j * 64 + d];
            s[j] = accv;
        }
        float mnew = m;
        #pragma unroll
        for (int j = 0; j < 32; j++) mnew = fmaxf(mnew, s[j]);
        float corr = __expf(m - mnew);
        l *= corr;
        #pragma unroll
        for (int d = 0; d < HD_; d++) o[d] *= corr;
        #pragma unroll
        for (int j = 0; j < 32; j++) {
            float pp = __expf(s[j] - mnew);
            l += pp;
            #pragma unroll
            for (int d = 0; d < HD_; d++) o[d] += pp * Vs[j * 64 + d];
        }
        m = mnew;
    }

    float inv = 1.f / l;
    size_t obase = (size_t)(b * L_ + qrow) * C_ + h * HD_;
    float* opf = g_att + obase;
    bf16* opb = g_att_bf + obase;
    #pragma unroll
    for (int d4 = 0; d4 < HD_ / 4; d4++) {
        float4 t;
        t.x = o[4 * d4 + 0] * inv;
        t.y = o[4 * d4 + 1] * inv;
        t.z = o[4 * d4 + 2] * inv;
        t.w = o[4 * d4 + 3] * inv;
        *(float4*)(opf + 4 * d4) = t;
        ((__nv_bfloat162*)opb)[2 * d4]     = __floats2bfloat162_rn(t.x, t.y);
        ((__nv_bfloat162*)opb)[2 * d4 + 1] = __floats2bfloat162_rn(t.z, t.w);
    }
#endif
}

// ---------------- launcher ----------------
extern "C" void kernel_launch(void* const* d_in, const int* in_sizes, int n_in,
                              void* d_out, int out_size) {
    const float* x        = (const float*)d_in[0];
    const float* gn_scale = (const float*)d_in[1];
    const float* gn_bias  = (const float*)d_in[2];
    const float* qkv_w    = (const float*)d_in[3];
    const float* qkv_b    = (const float*)d_in[4];
    const float* proj_w   = (const float*)d_in[5];
    const float* proj_b   = (const float*)d_in[6];
    float* out = (float*)d_out;

    // 0) merged weight transpose+convert (one launch)
    {
        dim3 blk(32, 8);
        dim3 gw(N3C / 32 + C_ / 32, C_ / 32);
        wtrans_kernel<<<gw, blk>>>(qkv_w, proj_w);
    }

    // 1) GroupNorm stats (partials + fused finalize)
    {
        dim3 gpart(B_ * G_, 8);
        gn_part_kernel<<<gpart, 256>>>(x);
    }

    // 2) apply GroupNorm
    {
        int total4 = ML * C_ / 4;
        gn_apply_kernel<<<(total4 + 255) / 256, 256>>>(x, gn_scale, gn_bias);
    }

    // 3) QKV GEMM
    {
        dim3 grid(N3C / 128, ML / 128);
        gemm_kernel<0><<<grid, 256>>>(qkv_w, qkv_b, nullptr, nullptr, N3C, C_);
    }

    // 3.5) V^T transpose (feature path)
    {
        dim3 blk(32, 8);
        dim3 gv(L_ / 32, HD_ / 32, B_ * H_);
        vtrans_kernel<<<gv, blk>>>();
    }

    // 4) flash attention
    {
        dim3 grid(L_ / 128, B_ * H_);
        flash_kernel<<<grid, 128>>>();
    }

    // 5) proj GEMM + residual
    {
        dim3 grid(C_ / 128, ML / 128);
        gemm_kernel<1><<<grid, 256>>>(proj_w, proj_b, x, out, C_, C_);
    }
}

// round 16
// speedup vs baseline: 1.2791x; 1.0827x over previous
#include <cuda_runtime.h>
#include <cuda_bf16.h>
#include <math.h>
#include <stdint.h>

#define B_  2
#define L_  2048
#define C_  1024
#define H_  16
#define HD_ 64
#define G_  32
#define CG_ 32
#define N3C (3 * C_)
#define ML  (B_ * L_)   // 4096 rows

typedef __nv_bfloat16 bf16;

// ---------------- scratch (static device globals) ----------------
__device__ float g_stats[B_ * G_ * 2];
__device__ float g_part[B_ * G_ * 8 * 2];         // two-phase GN partials
__device__ int   g_cnt[B_ * G_];                  // finalize counters (self-resetting)
__device__ float g_xn[(size_t)ML * C_];           // normalized input fp32 (fallback only)
__device__ bf16  g_xn_bf[(size_t)ML * C_];        // normalized input bf16
__device__ float g_qkv[(size_t)ML * N3C];         // qkv fp32 (fallback only)
__device__ bf16  g_qkv_bf[(size_t)ML * N3C];      // qkv bf16 (feature path)
__device__ float g_att[(size_t)ML * C_];          // attention out fp32 (fallback only)
__device__ bf16  g_att_bf[(size_t)ML * C_];       // attention out bf16
__device__ bf16  g_wqT[(size_t)N3C * C_];         // qkv_w^T bf16 [N,K]
__device__ bf16  g_wpT[(size_t)C_ * C_];          // proj_w^T bf16 [N,K]
__device__ bf16  g_vT[(size_t)B_ * H_ * HD_ * L_]; // V^T [bh][d][key] bf16

// ---------------- helpers ----------------
__device__ __forceinline__ uint32_t smem_u32(const void* p) {
    return (uint32_t)__cvta_generic_to_shared(p);
}

#ifdef __CUDA_ARCH_FEAT_SM103_ALL
__device__ __forceinline__ uint32_t elect_one() {
    uint32_t pred;
    asm volatile("{\n\t.reg .pred p;\n\telect.sync _|p, 0xFFFFFFFF;\n\t"
                 "selp.b32 %0, 1, 0, p;\n\t}" : "=r"(pred));
    return pred;
}
#define TC_ALLOC(smem_addr, ncols) \
    asm volatile("tcgen05.alloc.cta_group::1.sync.aligned.shared::cta.b32 [%0], %1;" \
                 :: "r"(smem_addr), "r"(ncols) : "memory")
#define TC_DEALLOC(tmem, ncols) \
    asm volatile("tcgen05.dealloc.cta_group::1.sync.aligned.b32 %0, %1;" :: "r"(tmem), "r"(ncols))
#define TC_RELINQ() \
    asm volatile("tcgen05.relinquish_alloc_permit.cta_group::1.sync.aligned;")
#define TC_COMMIT(mbar) \
    asm volatile("tcgen05.commit.cta_group::1.mbarrier::arrive::one.shared::cluster.b64 [%0];" \
                 :: "r"(mbar) : "memory")
#define TC_FENCE_AFTER()  asm volatile("tcgen05.fence::after_thread_sync;" ::: "memory")
#define TC_FENCE_BEFORE() asm volatile("tcgen05.fence::before_thread_sync;" ::: "memory")
#define TC_WAIT_LD()      asm volatile("tcgen05.wait::ld.sync.aligned;" ::: "memory")
#define TC_WAIT_ST()      asm volatile("tcgen05.wait::st.sync.aligned;" ::: "memory")
#define MBAR_INIT(mbar, cnt) \
    asm volatile("mbarrier.init.shared.b64 [%0], %1;" :: "r"(mbar), "r"(cnt) : "memory")
#define MBAR_INVAL(mbar) \
    asm volatile("mbarrier.inval.shared.b64 [%0];" :: "r"(mbar) : "memory")
#define FENCE_ASYNC_SHARED() asm volatile("fence.proxy.async.shared::cta;" ::: "memory")

__device__ __forceinline__ void mbar_wait(uint32_t mbar, uint32_t parity) {
    asm volatile(
        "{\n\t.reg .pred P1;\n\t"
        "WAIT_LOOP_%=:\n\t"
        "mbarrier.try_wait.parity.acquire.cta.shared::cta.b64 P1, [%0], %1, 0x989680;\n\t"
        "@P1 bra.uni WAIT_DONE_%=;\n\t"
        "bra.uni WAIT_LOOP_%=;\n\t"
        "WAIT_DONE_%=:\n\t}"
        :: "r"(mbar), "r"(parity) : "memory");
}

__device__ __forceinline__ void tc_mma_f16_ss(uint32_t d_tmem, uint64_t a_desc,
                                              uint64_t b_desc, uint32_t idesc,
                                              uint32_t enable) {
    asm volatile(
        "{\n\t.reg .pred p;\n\tsetp.ne.u32 p, %5, 0;\n\t"
        "tcgen05.mma.cta_group::1.kind::f16 [%0], %1, %2, %3, {%4,%4,%4,%4}, p;\n\t}"
        :: "r"(d_tmem), "l"(a_desc), "l"(b_desc), "r"(idesc), "r"(0u), "r"(enable)
        : "memory");
}
__device__ __forceinline__ void tc_mma_f16_ts(uint32_t d_tmem, uint32_t a_tmem,
                                              uint64_t b_desc, uint32_t idesc,
                                              uint32_t enable) {
    asm volatile(
        "{\n\t.reg .pred p;\n\tsetp.ne.u32 p, %5, 0;\n\t"
        "tcgen05.mma.cta_group::1.kind::f16 [%0], [%1], %2, %3, {%4,%4,%4,%4}, p;\n\t}"
        :: "r"(d_tmem), "r"(a_tmem), "l"(b_desc), "r"(idesc), "r"(0u), "r"(enable)
        : "memory");
}

__device__ __forceinline__ void tc_ld_x32(uint32_t* r, uint32_t tmem_addr) {
    asm volatile(
        "tcgen05.ld.sync.aligned.32x32b.x32.b32 "
        "{%0, %1, %2, %3, %4, %5, %6, %7, %8, %9, %10, %11, %12, %13, %14, %15, "
        " %16, %17, %18, %19, %20, %21, %22, %23, %24, %25, %26, %27, %28, %29, %30, %31}, [%32];"
        : "=r"(r[0]), "=r"(r[1]), "=r"(r[2]), "=r"(r[3]), "=r"(r[4]), "=r"(r[5]),
          "=r"(r[6]), "=r"(r[7]), "=r"(r[8]), "=r"(r[9]), "=r"(r[10]), "=r"(r[11]),
          "=r"(r[12]), "=r"(r[13]), "=r"(r[14]), "=r"(r[15]), "=r"(r[16]), "=r"(r[17]),
          "=r"(r[18]), "=r"(r[19]), "=r"(r[20]), "=r"(r[21]), "=r"(r[22]), "=r"(r[23]),
          "=r"(r[24]), "=r"(r[25]), "=r"(r[26]), "=r"(r[27]), "=r"(r[28]), "=r"(r[29]),
          "=r"(r[30]), "=r"(r[31])
        : "r"(tmem_addr));
}

__device__ __forceinline__ void tc_st_x32(uint32_t tmem_addr, const uint32_t* r) {
    asm volatile(
        "tcgen05.st.sync.aligned.32x32b.x32.b32 [%0], "
        "{%1, %2, %3, %4, %5, %6, %7, %8, %9, %10, %11, %12, %13, %14, %15, %16, "
        " %17, %18, %19, %20, %21, %22, %23, %24, %25, %26, %27, %28, %29, %30, %31, %32};"
        :: "r"(tmem_addr),
           "r"(r[0]), "r"(r[1]), "r"(r[2]), "r"(r[3]), "r"(r[4]), "r"(r[5]),
           "r"(r[6]), "r"(r[7]), "r"(r[8]), "r"(r[9]), "r"(r[10]), "r"(r[11]),
           "r"(r[12]), "r"(r[13]), "r"(r[14]), "r"(r[15]), "r"(r[16]), "r"(r[17]),
           "r"(r[18]), "r"(r[19]), "r"(r[20]), "r"(r[21]), "r"(r[22]), "r"(r[23]),
           "r"(r[24]), "r"(r[25]), "r"(r[26]), "r"(r[27]), "r"(r[28]), "r"(r[29]),
           "r"(r[30]), "r"(r[31])
        : "memory");
}

#define SW128(off) ((off) ^ (((off) >> 3) & 0x70))
__device__ __forceinline__ uint64_t make_desc_sw128(uint32_t base_addr) {
    const uint64_t BASE =
        (uint64_t(2) << 61) | (uint64_t(1) << 46) | (uint64_t(64) << 32) | (uint64_t(1) << 16);
    return BASE | ((uint64_t)(base_addr >> 4) & 0x3FFF);
}
#define IDESC_F16(Mv, Nv) ((1u << 4) | (1u << 7) | (1u << 10) | (((Nv) / 8) << 17) | (((Mv) / 16) << 24))
#define IDESC_128x128 IDESC_F16(128, 128)
#endif  // __CUDA_ARCH_FEAT_SM103_ALL

// ---------------- kernel 1: GroupNorm partial sums + fused finalize ----------------
__global__ void gn_part_kernel(const float* __restrict__ x) {
    int bg = blockIdx.x;
    int part = blockIdx.y;
    int b = bg / G_;
    int g = bg % G_;
    const float* xp = x + (size_t)b * L_ * C_ + g * CG_;

    float s = 0.f, s2 = 0.f;
    #pragma unroll
    for (int t = 0; t < 8; t++) {
        int i = t * 256 + threadIdx.x;
        int l = part * 256 + (i >> 3);
        int c4 = (i & 7) * 4;
        float4 v = *(const float4*)(xp + (size_t)l * C_ + c4);
        s  += v.x + v.y + v.z + v.w;
        s2 += v.x * v.x + v.y * v.y + v.z * v.z + v.w * v.w;
    }
    #pragma unroll
    for (int o = 16; o > 0; o >>= 1) {
        s  += __shfl_down_sync(0xFFFFFFFFu, s, o);
        s2 += __shfl_down_sync(0xFFFFFFFFu, s2, o);
    }
    __shared__ float sh[2][8];
    int w = threadIdx.x >> 5, ln = threadIdx.x & 31;
    if (ln == 0) { sh[0][w] = s; sh[1][w] = s2; }
    __syncthreads();
    if (w == 0 && ln < 8) {
        s = sh[0][ln]; s2 = sh[1][ln];
        #pragma unroll
        for (int o = 4; o > 0; o >>= 1) {
            s  += __shfl_down_sync(0x000000FFu, s, o);
            s2 += __shfl_down_sync(0x000000FFu, s2, o);
        }
        if (ln == 0) {
            g_part[(bg * 8 + part) * 2 + 0] = s;
            g_part[(bg * 8 + part) * 2 + 1] = s2;
            __threadfence();
            int done = atomicAdd(&g_cnt[bg], 1);
            if (done == 7) {
                __threadfence();
                float ts = 0.f, ts2 = 0.f;
                #pragma unroll
                for (int p2 = 0; p2 < 8; p2++) {
                    ts  += g_part[(bg * 8 + p2) * 2 + 0];
                    ts2 += g_part[(bg * 8 + p2) * 2 + 1];
                }
                const float inv_n = 1.0f / (float)(L_ * CG_);
                float mu  = ts * inv_n;
                float var = ts2 * inv_n - mu * mu;
                g_stats[bg * 2 + 0] = mu;
                g_stats[bg * 2 + 1] = rsqrtf(var + 1e-6f);
                g_cnt[bg] = 0;     // reset for graph replay
            }
        }
    }
}

// ---------------- kernel 2: apply GroupNorm ----------------
__global__ void gn_apply_kernel(const float* __restrict__ x,
                                const float* __restrict__ gamma,
                                const float* __restrict__ beta) {
    size_t i = (size_t)blockIdx.x * blockDim.x + threadIdx.x;
    size_t base = i * 4;
    if (base >= (size_t)ML * C_) return;
    int c  = (int)(base % C_);
    int bl = (int)(base / C_);
    int b  = bl >> 11;
    int g  = c >> 5;
    float mu = g_stats[(b * G_ + g) * 2 + 0];
    float rs = g_stats[(b * G_ + g) * 2 + 1];
    float4 xv = *(const float4*)(x + base);
    float4 gv = *(const float4*)(gamma + c);
    float4 bv = *(const float4*)(beta + c);
    float4 r;
    r.x = (xv.x - mu) * rs * gv.x + bv.x;
    r.y = (xv.y - mu) * rs * gv.y + bv.y;
    r.z = (xv.z - mu) * rs * gv.z + bv.z;
    r.w = (xv.w - mu) * rs * gv.w + bv.w;
#ifndef __CUDA_ARCH_FEAT_SM103_ALL
    *(float4*)(g_xn + base) = r;     // fallback GEMM input only
#endif
    ((__nv_bfloat162*)g_xn_bf)[2 * i]     = __floats2bfloat162_rn(r.x, r.y);
    ((__nv_bfloat162*)g_xn_bf)[2 * i + 1] = __floats2bfloat162_rn(r.z, r.w);
}

// ---------------- merged weight transpose + convert ----------------
__global__ void wtrans_kernel(const float* __restrict__ wq, const float* __restrict__ wp) {
    __shared__ float tile[32][33];
    int bx = blockIdx.x;
    const float* src;
    bf16* dst;
    int N, n0;
    if (bx < N3C / 32) { src = wq; dst = g_wqT; N = N3C; n0 = bx * 32; }
    else               { src = wp; dst = g_wpT; N = C_;  n0 = (bx - N3C / 32) * 32; }
    int k0 = blockIdx.y * 32;
    int tx = threadIdx.x, ty = threadIdx.y;
    #pragma unroll
    for (int i = 0; i < 32; i += 8)
        tile[ty + i][tx] = src[(size_t)(k0 + ty + i) * N + n0 + tx];
    __syncthreads();
    #pragma unroll
    for (int i = 0; i < 32; i += 8)
        dst[(size_t)(n0 + ty + i) * C_ + k0 + tx] = __float2bfloat16(tile[tx][ty + i]);
}

// ---------------- V^T transpose (feature path) ----------------
__global__ void vtrans_kernel() {
#ifdef __CUDA_ARCH_FEAT_SM103_ALL
    __shared__ unsigned short tile[32][33];
    int l0 = blockIdx.x * 32;
    int d0 = blockIdx.y * 32;
    int bh = blockIdx.z;
    int b = bh >> 4, h = bh & 15;
    int tx = threadIdx.x, ty = threadIdx.y;
    const unsigned short* src = (const unsigned short*)g_qkv_bf
        + (size_t)b * L_ * N3C + h * (3 * HD_) + 2 * HD_;
    #pragma unroll
    for (int i = 0; i < 32; i += 8)
        tile[ty + i][tx] = src[(size_t)(l0 + ty + i) * N3C + d0 + tx];
    __syncthreads();
    unsigned short* dst = (unsigned short*)g_vT + (size_t)bh * HD_ * L_;
    #pragma unroll
    for (int i = 0; i < 32; i += 8)
        dst[(size_t)(d0 + ty + i) * L_ + l0 + tx] = tile[tx][ty + i];
#endif
}

// ---------------- kernel 3/5: GEMM, dual path ----------------
template <int EPI>
__global__ __launch_bounds__(256) void gemm_kernel(
    const float* __restrict__ W,
    const float* __restrict__ bias,
    const float* __restrict__ resid,
    float*       __restrict__ OutParam,
    int N, int K)
{
    const float rsqrt2 = 0.70710678118654752f;
    int tid = threadIdx.x;
    int bm = blockIdx.y * 128;
    int bn = blockIdx.x * 128;

#ifdef __CUDA_ARCH_FEAT_SM103_ALL
    __shared__ __align__(1024) bf16 sA[2][128 * 64];
    __shared__ __align__(1024) bf16 sB[2][128 * 64];
    __shared__ float bias_s[128];
    __shared__ __align__(8) uint64_t mbar_store[2];
    __shared__ uint32_t tmem_ptr_store;

    const bf16* A  = (EPI == 0) ? g_xn_bf : g_att_bf;
    const bf16* WT = (EPI == 0) ? g_wqT   : g_wpT;

    int wid = tid >> 5;
    int lane = tid & 31;
    uint32_t mbar0 = smem_u32(&mbar_store[0]);
    uint32_t mbar1 = smem_u32(&mbar_store[1]);
    uint32_t tptr_addr = smem_u32(&tmem_ptr_store);

    if (wid == 0) TC_ALLOC(tptr_addr, 128);
    if (tid == 0) { MBAR_INIT(mbar0, 1); MBAR_INIT(mbar1, 1); }
    if (tid < 128) bias_s[tid] = bias[bn + tid];
    __syncthreads();
    uint32_t tmem_base;
    asm volatile("ld.shared.b32 %0, [%1];" : "=r"(tmem_base) : "r"(tptr_addr));

    uint64_t a_desc[2] = { make_desc_sw128(smem_u32(sA[0])), make_desc_sw128(smem_u32(sA[1])) };
    uint64_t b_desc[2] = { make_desc_sw128(smem_u32(sB[0])), make_desc_sw128(smem_u32(sB[1])) };

    // per-thread load coords (fixed across chunks)
    int lr = tid >> 3;                // row 0..127 (two rows per 8 threads... see below)
    // actually: i = t*256+tid, r = i>>3, c8 = (i&7)*8; keep identical mapping via loop.

    const int NCHUNK = K / 64;

    // ---- prefetch chunk 0 into registers ----
    uint4 ra[4], rb[4];
    #pragma unroll
    for (int t = 0; t < 4; t++) {
        int i = t * 256 + tid;
        int r = i >> 3;
        int c8 = (i & 7) * 8;
        ra[t] = *(const uint4*)(A  + (size_t)(bm + r) * K + c8);
        rb[t] = *(const uint4*)(WT + (size_t)(bn + r) * K + c8);
    }

    for (int ch = 0; ch < NCHUNK; ch++) {
        int buf = ch & 1;
        uint32_t mb = buf ? mbar1 : mbar0;
        if (ch >= 2) mbar_wait(mb, (uint32_t)(((ch >> 1) - 1) & 1));

        // store prefetched registers into smem
        #pragma unroll
        for (int t = 0; t < 4; t++) {
            int i = t * 256 + tid;
            int r = i >> 3;
            int c8 = (i & 7) * 8;
            uint32_t sw = SW128((uint32_t)(r * 128 + c8 * 2));
            *(uint4*)((char*)sA[buf] + sw) = ra[t];
            *(uint4*)((char*)sB[buf] + sw) = rb[t];
        }

        // issue prefetch LDGs for chunk ch+1 (latency overlaps fence/sync/MMA/wait)
        if (ch + 1 < NCHUNK) {
            int k0 = (ch + 1) * 64;
            #pragma unroll
            for (int t = 0; t < 4; t++) {
                int i = t * 256 + tid;
                int r = i >> 3;
                int c8 = (i & 7) * 8;
                ra[t] = *(const uint4*)(A  + (size_t)(bm + r) * K + k0 + c8);
                rb[t] = *(const uint4*)(WT + (size_t)(bn + r) * K + k0 + c8);
            }
        }

        FENCE_ASYNC_SHARED();
        __syncthreads();

        if (wid == 0 && elect_one()) {
            #pragma unroll
            for (int ks = 0; ks < 4; ks++) {
                uint32_t en = (ch > 0 || ks > 0) ? 1u : 0u;
                tc_mma_f16_ss(tmem_base, a_desc[buf] + ks * 2, b_desc[buf] + ks * 2,
                              IDESC_128x128, en);
            }
            TC_COMMIT(mb);
        }
    }

    mbar_wait(mbar1, 1u);
    TC_FENCE_AFTER();

    {
        int row = bm + (wid & 3) * 32 + lane;
        int chalf = (wid >> 2) * 64;
        #pragma unroll
        for (int cc = 0; cc < 2; cc++) {
            uint32_t d[32];
            tc_ld_x32(d, tmem_base + chalf + cc * 32);
            TC_WAIT_LD();
            int colbase = bn + chalf + cc * 32;
            #pragma unroll
            for (int j = 0; j < 8; j++) {
                float4 v;
                v.x = __uint_as_float(d[4 * j + 0]) + bias_s[chalf + cc * 32 + 4 * j + 0];
                v.y = __uint_as_float(d[4 * j + 1]) + bias_s[chalf + cc * 32 + 4 * j + 1];
                v.z = __uint_as_float(d[4 * j + 2]) + bias_s[chalf + cc * 32 + 4 * j + 2];
                v.w = __uint_as_float(d[4 * j + 3]) + bias_s[chalf + cc * 32 + 4 * j + 3];
                if (EPI == 1) {
                    float4 rv = *(const float4*)(resid + (size_t)row * N + colbase + 4 * j);
                    v.x = (v.x + rv.x) * rsqrt2;
                    v.y = (v.y + rv.y) * rsqrt2;
                    v.z = (v.z + rv.z) * rsqrt2;
                    v.w = (v.w + rv.w) * rsqrt2;
                    *(float4*)(OutParam + (size_t)row * N + colbase + 4 * j) = v;
                } else {
                    __nv_bfloat162 lo = __floats2bfloat162_rn(v.x, v.y);
                    __nv_bfloat162 hi = __floats2bfloat162_rn(v.z, v.w);
                    uint2 pk = make_uint2(*(uint32_t*)&lo, *(uint32_t*)&hi);
                    *(uint2*)(g_qkv_bf + (size_t)row * N + colbase + 4 * j) = pk;
                }
            }
        }
    }
    TC_FENCE_BEFORE();
    __syncthreads();
    if (tid == 0) { MBAR_INVAL(mbar0); MBAR_INVAL(mbar1); }
    __syncthreads();
    if (wid == 0) {
        TC_RELINQ();
        TC_DEALLOC(tmem_base, 128);
    }
#else
    // fp32 FFMA fallback (R3-proven)
    const float* A = (EPI == 0) ? g_xn : g_att;
    float* Cout    = (EPI == 0) ? g_qkv : OutParam;

    __shared__ float As[8][128];
    __shared__ float Bs[8][128];

    int tx = tid & 15;
    int ty = tid >> 4;

    float acc[8][8];
    #pragma unroll
    for (int i = 0; i < 8; i++)
        #pragma unroll
        for (int j = 0; j < 8; j++) acc[i][j] = 0.f;

    int arow = tid >> 1;
    int acol = (tid & 1) * 4;
    int brow = tid >> 5;
    int bcol = (tid & 31) * 4;

    const float* Aptr = A + (size_t)(bm + arow) * K + acol;
    const float* Bptr = W + (size_t)brow * N + bn + bcol;

    for (int k0 = 0; k0 < K; k0 += 8) {
        float4 av = *(const float4*)(Aptr + k0);
        float4 bv = *(const float4*)(Bptr + (size_t)k0 * N);
        As[acol + 0][arow] = av.x;
        As[acol + 1][arow] = av.y;
        As[acol + 2][arow] = av.z;
        As[acol + 3][arow] = av.w;
        *(float4*)&Bs[brow][bcol] = bv;
        __syncthreads();
        #pragma unroll
        for (int kk = 0; kk < 8; kk++) {
            float a[8], bfv[8];
            #pragma unroll
            for (int i = 0; i < 8; i++) a[i] = As[kk][ty * 8 + i];
            #pragma unroll
            for (int i = 0; i < 8; i++) bfv[i] = Bs[kk][tx * 8 + i];
            #pragma unroll
            for (int i = 0; i < 8; i++)
                #pragma unroll
                for (int j = 0; j < 8; j++)
                    acc[i][j] += a[i] * bfv[j];
        }
        __syncthreads();
    }

    #pragma unroll
    for (int i = 0; i < 8; i++) {
        int row = bm + ty * 8 + i;
        #pragma unroll
        for (int j = 0; j < 8; j += 4) {
            int col = bn + tx * 8 + j;
            float4 bb = *(const float4*)(bias + col);
            float4 v;
            v.x = acc[i][j + 0] + bb.x;
            v.y = acc[i][j + 1] + bb.y;
            v.z = acc[i][j + 2] + bb.z;
            v.w = acc[i][j + 3] + bb.w;
            if (EPI == 1) {
                float4 rv = *(const float4*)(resid + (size_t)row * N + col);
                v.x = (v.x + rv.x) * rsqrt2;
                v.y = (v.y + rv.y) * rsqrt2;
                v.z = (v.z + rv.z) * rsqrt2;
                v.w = (v.w + rv.w) * rsqrt2;
            }
            *(float4*)(Cout + (size_t)row * N + col) = v;
        }
    }
#endif
}

// ---------------- kernel 4: flash attention, dual path (R15 champion config) ----------------
__global__ __launch_bounds__(128) void flash_kernel() {
    int bh = blockIdx.y;
    int b = bh >> 4;
    int h = bh & 15;
    int tid = threadIdx.x;

#ifdef __CUDA_ARCH_FEAT_SM103_ALL
    __shared__ __align__(1024) bf16 sQ[128 * 64];    // Q [rows][dims] SW128
    __shared__ __align__(1024) bf16 sK[128 * 64];    // K chunk [keys][dims] SW128
    __shared__ __align__(1024) bf16 sV[64 * 128];    // V^T chunk [dims][keys] blocked SW128
    __shared__ __align__(8) uint64_t mbar_store[2];  // S, O
    __shared__ uint32_t tmem_ptr_store;

    int wid = tid >> 5;
    int bm = blockIdx.x * 128;

    uint32_t mbarS = smem_u32(&mbar_store[0]);
    uint32_t mbarO = smem_u32(&mbar_store[1]);
    uint32_t tptr_addr = smem_u32(&tmem_ptr_store);

    if (wid == 0) TC_ALLOC(tptr_addr, 256);
    if (tid == 0) { MBAR_INIT(mbarS, 1); MBAR_INIT(mbarO, 1); }
    __syncthreads();
    uint32_t tmem_base;
    asm volatile("ld.shared.b32 %0, [%1];" : "=r"(tmem_base) : "r"(tptr_addr));

    const uint32_t S0 = tmem_base + 0;      // S: 128 cols fp32
    const uint32_t P0 = tmem_base + 128;    // P: 64 cols bf16x2
    const uint32_t O0 = tmem_base + 192;    // O: 64 cols fp32

    const bf16* qkvb = g_qkv_bf + (size_t)b * L_ * N3C + h * (3 * HD_);

    uint64_t q_desc = make_desc_sw128(smem_u32(sQ));
    uint64_t k_desc = make_desc_sw128(smem_u32(sK));
    uint64_t v_desc = make_desc_sw128(smem_u32(sV));
    const uint32_t IDESC_S = IDESC_F16(128, 128);
    const uint32_t IDESC_O = IDESC_F16(128, 64);

    // ---- prologue: load Q + K[0], issue S(0) ----
    #pragma unroll
    for (int t = 0; t < 8; t++) {
        int i = t * 128 + tid;
        int r = i >> 3;
        int c8 = (i & 7) * 8;
        uint32_t sw = SW128((uint32_t)(r * 128 + c8 * 2));
        *(uint4*)((char*)sQ + sw) = *(const uint4*)(qkvb + (size_t)(bm + r) * N3C + c8);
        *(uint4*)((char*)sK + sw) = *(const uint4*)(qkvb + HD_ + (size_t)r * N3C + c8);
    }
    FENCE_ASYNC_SHARED();
    __syncthreads();
    if (wid == 0 && elect_one()) {
        #pragma unroll
        for (int ks = 0; ks < 4; ks++)
            tc_mma_f16_ss(S0, q_desc + ks * 2, k_desc + ks * 2, IDESC_S, ks > 0);
        TC_COMMIT(mbarS);
    }

    float lsum = 0.f;
    const unsigned short* vT = (const unsigned short*)g_vT + (size_t)bh * HD_ * L_;
    const float SCALE_LOG2E = 0.125f * 1.44269504088896f;
    uint32_t woff = (uint32_t)wid << 21;

    for (int ch = 0; ch < 16; ch++) {
        // ---- S(ch) ready? read it ----
        mbar_wait(mbarS, (uint32_t)(ch & 1));
        TC_FENCE_AFTER();
        uint32_t sr[128];
        #pragma unroll
        for (int cc = 0; cc < 4; cc++) tc_ld_x32(sr + cc * 32, S0 + cc * 32);
        TC_WAIT_LD();

        // ---- load K[ch+1] and issue S(ch+1): overlaps softmax below ----
        if (ch < 15) {
            #pragma unroll
            for (int t = 0; t < 8; t++) {
                int i = t * 128 + tid;
                int r = i >> 3;
                int c8 = (i & 7) * 8;
                uint32_t sw = SW128((uint32_t)(r * 128 + c8 * 2));
                *(uint4*)((char*)sK + sw) =
                    *(const uint4*)(qkvb + HD_ + (size_t)((ch + 1) * 128 + r) * N3C + c8);
            }
            FENCE_ASYNC_SHARED();
            __syncthreads();            // all warps done LDTM + K stores
            if (wid == 0 && elect_one()) {
                #pragma unroll
                for (int ks = 0; ks < 4; ks++)
                    tc_mma_f16_ss(S0, q_desc + ks * 2, k_desc + ks * 2, IDESC_S, ks > 0);
                TC_COMMIT(mbarS);
            }
        }

        // ---- wait O(ch-1) (short), then load V[ch] ----
        if (ch > 0) mbar_wait(mbarO, (uint32_t)((ch - 1) & 1));
        #pragma unroll
        for (int t = 0; t < 8; t++) {
            int i = t * 128 + tid;
            int d = i >> 4;
            int kk = (i & 15) * 8;
            int atom_col = kk >> 6;
            int inner_col = kk & 63;
            uint32_t off = (uint32_t)(((d >> 3) + atom_col * 8) * 1024 + (d & 7) * 128 + inner_col * 2);
            uint32_t sw = SW128(off);
            *(uint4*)((char*)sV + sw) = *(const uint4*)(vT + (size_t)d * L_ + ch * 128 + kk);
        }

        // ---- softmax (no max-sub), overlapped with S(ch+1) on tensor pipe ----
        uint32_t p[64];
        #pragma unroll
        for (int j = 0; j < 64; j++) {
            float e0 = exp2f(__uint_as_float(sr[2 * j + 0]) * SCALE_LOG2E);
            float e1 = exp2f(__uint_as_float(sr[2 * j + 1]) * SCALE_LOG2E);
            lsum += e0 + e1;
            __nv_bfloat162 pk = __floats2bfloat162_rn(e0, e1);
            p[j] = *(uint32_t*)&pk;
        }

        // ---- P to TMEM, O += P @ V^T ----
        {
            tc_st_x32(P0 + woff, p);
            tc_st_x32(P0 + 32 + woff, p + 32);
            TC_WAIT_ST();
        }
        FENCE_ASYNC_SHARED();
        TC_FENCE_BEFORE();
        __syncthreads();
        if (wid == 0 && elect_one()) {
            TC_FENCE_AFTER();
            #pragma unroll
            for (int s8 = 0; s8 < 8; s8++) {
                uint64_t boff = (uint64_t)((s8 >> 2) * 512 + (s8 & 3) * 2);
                tc_mma_f16_ts(O0, P0 + s8 * 8, v_desc + boff, IDESC_O,
                              (ch > 0 || s8 > 0));
            }
            TC_COMMIT(mbarO);
        }
        __syncthreads();
    }

    // ---- epilogue ----
    mbar_wait(mbarO, 1u);
    TC_FENCE_AFTER();
    {
        uint32_t d0[32], d1[32];
        tc_ld_x32(d0, O0);
        tc_ld_x32(d1, O0 + 32);
        TC_WAIT_LD();
        float inv = 1.f / lsum;
        bf16* op = g_att_bf + (size_t)(b * L_ + bm + tid) * C_ + h * HD_;
        #pragma unroll
        for (int j = 0; j < 16; j++) {
            __nv_bfloat162 a = __floats2bfloat162_rn(
                __uint_as_float(d0[2 * j]) * inv, __uint_as_float(d0[2 * j + 1]) * inv);
            ((__nv_bfloat162*)op)[j] = a;
        }
        #pragma unroll
        for (int j = 0; j < 16; j++) {
            __nv_bfloat162 a = __floats2bfloat162_rn(
                __uint_as_float(d1[2 * j]) * inv, __uint_as_float(d1[2 * j + 1]) * inv);
            ((__nv_bfloat162*)op)[16 + j] = a;
        }
    }
    TC_FENCE_BEFORE();
    __syncthreads();
    if (tid == 0) { MBAR_INVAL(mbarS); MBAR_INVAL(mbarO); }
    __syncthreads();
    if (wid == 0) {
        TC_RELINQ();
        TC_DEALLOC(tmem_base, 256);
    }
#else
    // ============ scalar fallback (R3-proven) ============
    __shared__ float Ks[32 * 64];
    __shared__ float Vs[32 * 64];

    int qrow = blockIdx.x * 128 + tid;

    const float* base = g_qkv + (size_t)b * L_ * N3C;
    const float* qptr = base + (size_t)qrow * N3C + h * (3 * HD_);
    const float* kbase = base + h * (3 * HD_) + HD_;
    const float* vbase = base + h * (3 * HD_) + 2 * HD_;

    float q[HD_];
    #pragma unroll
    for (int d4 = 0; d4 < HD_ / 4; d4++) {
        float4 t = *(const float4*)(qptr + d4 * 4);
        q[4 * d4 + 0] = t.x * 0.125f;
        q[4 * d4 + 1] = t.y * 0.125f;
        q[4 * d4 + 2] = t.z * 0.125f;
        q[4 * d4 + 3] = t.w * 0.125f;
    }
    float o[HD_];
    #pragma unroll
    for (int d = 0; d < HD_; d++) o[d] = 0.f;
    float m = -1e30f, l = 0.f;

    for (int kb = 0; kb < L_ / 32; kb++) {
        __syncthreads();
        #pragma unroll
        for (int t = 0; t < 4; t++) {
            int idx = t * 128 + tid;
            int r = idx >> 4;
            int c4 = (idx & 15) * 4;
            size_t goff = (size_t)(kb * 32 + r) * N3C + c4;
            *(float4*)&Ks[r * 64 + c4] = *(const float4*)(kbase + goff);
            *(float4*)&Vs[r * 64 + c4] = *(const float4*)(vbase + goff);
        }
        __syncthreads();

        float s[32];
        #pragma unroll
        for (int j = 0; j < 32; j++) {
            float accv = 0.f;
            #pragma unroll
            for (int d = 0; d < HD_; d++) accv += q[d] * Ks[j * 64 + d];
            s[j] = accv;
        }
        float mnew = m;
        #pragma unroll
        for (int j = 0; j < 32; j++) mnew = fmaxf(mnew, s[j]);
        float corr = __expf(m - mnew);
        l *= corr;
        #pragma unroll
        for (int d = 0; d < HD_; d++) o[d] *= corr;
        #pragma unroll
        for (int j = 0; j < 32; j++) {
            float pp = __expf(s[j] - mnew);
            l += pp;
            #pragma unroll
            for (int d = 0; d < HD_; d++) o[d] += pp * Vs[j * 64 + d];
        }
        m = mnew;
    }

    float inv = 1.f / l;
    size_t obase = (size_t)(b * L_ + qrow) * C_ + h * HD_;
    float* opf = g_att + obase;
    bf16* opb = g_att_bf + obase;
    #pragma unroll
    for (int d4 = 0; d4 < HD_ / 4; d4++) {
        float4 t;
        t.x = o[4 * d4 + 0] * inv;
        t.y = o[4 * d4 + 1] * inv;
        t.z = o[4 * d4 + 2] * inv;
        t.w = o[4 * d4 + 3] * inv;
        *(float4*)(opf + 4 * d4) = t;
        ((__nv_bfloat162*)opb)[2 * d4]     = __floats2bfloat162_rn(t.x, t.y);
        ((__nv_bfloat162*)opb)[2 * d4 + 1] = __floats2bfloat162_rn(t.z, t.w);
    }
#endif
}

// ---------------- launcher ----------------
extern "C" void kernel_launch(void* const* d_in, const int* in_sizes, int n_in,
                              void* d_out, int out_size) {
    const float* x        = (const float*)d_in[0];
    const float* gn_scale = (const float*)d_in[1];
    const float* gn_bias  = (const float*)d_in[2];
    const float* qkv_w    = (const float*)d_in[3];
    const float* qkv_b    = (const float*)d_in[4];
    const float* proj_w   = (const float*)d_in[5];
    const float* proj_b   = (const float*)d_in[6];
    float* out = (float*)d_out;

    // 0) merged weight transpose+convert (one launch)
    {
        dim3 blk(32, 8);
        dim3 gw(N3C / 32 + C_ / 32, C_ / 32);
        wtrans_kernel<<<gw, blk>>>(qkv_w, proj_w);
    }

    // 1) GroupNorm stats (partials + fused finalize)
    {
        dim3 gpart(B_ * G_, 8);
        gn_part_kernel<<<gpart, 256>>>(x);
    }

    // 2) apply GroupNorm
    {
        int total4 = ML * C_ / 4;
        gn_apply_kernel<<<(total4 + 255) / 256, 256>>>(x, gn_scale, gn_bias);
    }

    // 3) QKV GEMM
    {
        dim3 grid(N3C / 128, ML / 128);
        gemm_kernel<0><<<grid, 256>>>(qkv_w, qkv_b, nullptr, nullptr, N3C, C_);
    }

    // 3.5) V^T transpose (feature path)
    {
        dim3 blk(32, 8);
        dim3 gv(L_ / 32, HD_ / 32, B_ * H_);
        vtrans_kernel<<<gv, blk>>>();
    }

    // 4) flash attention
    {
        dim3 grid(L_ / 128, B_ * H_);
        flash_kernel<<<grid, 128>>>();
    }

    // 5) proj GEMM + residual
    {
        dim3 grid(C_ / 128, ML / 128);
        gemm_kernel<1><<<grid, 256>>>(proj_w, proj_b, x, out, C_, C_);
    }
}

// round 17
// speedup vs baseline: 1.3537x; 1.0583x over previous
#include <cuda_runtime.h>
#include <cuda_bf16.h>
#include <math.h>
#include <stdint.h>

#define B_  2
#define L_  2048
#define C_  1024
#define H_  16
#define HD_ 64
#define G_  32
#define CG_ 32
#define N3C (3 * C_)
#define ML  (B_ * L_)   // 4096 rows

typedef __nv_bfloat16 bf16;

// ---------------- scratch (static device globals) ----------------
__device__ float g_stats[B_ * G_ * 2];
__device__ float g_part[B_ * G_ * 8 * 2];
__device__ int   g_cnt[B_ * G_];
__device__ float g_xn[(size_t)ML * C_];           // fallback only
__device__ bf16  g_xn_bf[(size_t)ML * C_];
__device__ float g_qkv[(size_t)ML * N3C];         // fallback only
__device__ bf16  g_qkv_bf[(size_t)ML * N3C];
__device__ float g_att[(size_t)ML * C_];          // fallback only
__device__ bf16  g_att_bf[(size_t)ML * C_];
__device__ bf16  g_wqT[(size_t)N3C * C_];
__device__ bf16  g_wpT[(size_t)C_ * C_];
__device__ bf16  g_vT[(size_t)B_ * H_ * HD_ * L_];

// ---------------- helpers ----------------
__device__ __forceinline__ uint32_t smem_u32(const void* p) {
    return (uint32_t)__cvta_generic_to_shared(p);
}

#ifdef __CUDA_ARCH_FEAT_SM103_ALL
__device__ __forceinline__ uint32_t elect_one() {
    uint32_t pred;
    asm volatile("{\n\t.reg .pred p;\n\telect.sync _|p, 0xFFFFFFFF;\n\t"
                 "selp.b32 %0, 1, 0, p;\n\t}" : "=r"(pred));
    return pred;
}
#define TC_ALLOC(smem_addr, ncols) \
    asm volatile("tcgen05.alloc.cta_group::1.sync.aligned.shared::cta.b32 [%0], %1;" \
                 :: "r"(smem_addr), "r"(ncols) : "memory")
#define TC_DEALLOC(tmem, ncols) \
    asm volatile("tcgen05.dealloc.cta_group::1.sync.aligned.b32 %0, %1;" :: "r"(tmem), "r"(ncols))
#define TC_RELINQ() \
    asm volatile("tcgen05.relinquish_alloc_permit.cta_group::1.sync.aligned;")
#define TC_COMMIT(mbar) \
    asm volatile("tcgen05.commit.cta_group::1.mbarrier::arrive::one.shared::cluster.b64 [%0];" \
                 :: "r"(mbar) : "memory")
#define TC_FENCE_AFTER()  asm volatile("tcgen05.fence::after_thread_sync;" ::: "memory")
#define TC_FENCE_BEFORE() asm volatile("tcgen05.fence::before_thread_sync;" ::: "memory")
#define TC_WAIT_LD()      asm volatile("tcgen05.wait::ld.sync.aligned;" ::: "memory")
#define TC_WAIT_ST()      asm volatile("tcgen05.wait::st.sync.aligned;" ::: "memory")
#define MBAR_INIT(mbar, cnt) \
    asm volatile("mbarrier.init.shared.b64 [%0], %1;" :: "r"(mbar), "r"(cnt) : "memory")
#define MBAR_INVAL(mbar) \
    asm volatile("mbarrier.inval.shared.b64 [%0];" :: "r"(mbar) : "memory")
#define FENCE_ASYNC_SHARED() asm volatile("fence.proxy.async.shared::cta;" ::: "memory")

__device__ __forceinline__ void mbar_wait(uint32_t mbar, uint32_t parity) {
    asm volatile(
        "{\n\t.reg .pred P1;\n\t"
        "WAIT_LOOP_%=:\n\t"
        "mbarrier.try_wait.parity.acquire.cta.shared::cta.b64 P1, [%0], %1, 0x989680;\n\t"
        "@P1 bra.uni WAIT_DONE_%=;\n\t"
        "bra.uni WAIT_LOOP_%=;\n\t"
        "WAIT_DONE_%=:\n\t}"
        :: "r"(mbar), "r"(parity) : "memory");
}

__device__ __forceinline__ void tc_mma_f16_ss(uint32_t d_tmem, uint64_t a_desc,
                                              uint64_t b_desc, uint32_t idesc,
                                              uint32_t enable) {
    asm volatile(
        "{\n\t.reg .pred p;\n\tsetp.ne.u32 p, %5, 0;\n\t"
        "tcgen05.mma.cta_group::1.kind::f16 [%0], %1, %2, %3, {%4,%4,%4,%4}, p;\n\t}"
        :: "r"(d_tmem), "l"(a_desc), "l"(b_desc), "r"(idesc), "r"(0u), "r"(enable)
        : "memory");
}
__device__ __forceinline__ void tc_mma_f16_ts(uint32_t d_tmem, uint32_t a_tmem,
                                              uint64_t b_desc, uint32_t idesc,
                                              uint32_t enable) {
    asm volatile(
        "{\n\t.reg .pred p;\n\tsetp.ne.u32 p, %5, 0;\n\t"
        "tcgen05.mma.cta_group::1.kind::f16 [%0], [%1], %2, %3, {%4,%4,%4,%4}, p;\n\t}"
        :: "r"(d_tmem), "r"(a_tmem), "l"(b_desc), "r"(idesc), "r"(0u), "r"(enable)
        : "memory");
}

__device__ __forceinline__ void tc_ld_x32(uint32_t* r, uint32_t tmem_addr) {
    asm volatile(
        "tcgen05.ld.sync.aligned.32x32b.x32.b32 "
        "{%0, %1, %2, %3, %4, %5, %6, %7, %8, %9, %10, %11, %12, %13, %14, %15, "
        " %16, %17, %18, %19, %20, %21, %22, %23, %24, %25, %26, %27, %28, %29, %30, %31}, [%32];"
        : "=r"(r[0]), "=r"(r[1]), "=r"(r[2]), "=r"(r[3]), "=r"(r[4]), "=r"(r[5]),
          "=r"(r[6]), "=r"(r[7]), "=r"(r[8]), "=r"(r[9]), "=r"(r[10]), "=r"(r[11]),
          "=r"(r[12]), "=r"(r[13]), "=r"(r[14]), "=r"(r[15]), "=r"(r[16]), "=r"(r[17]),
          "=r"(r[18]), "=r"(r[19]), "=r"(r[20]), "=r"(r[21]), "=r"(r[22]), "=r"(r[23]),
          "=r"(r[24]), "=r"(r[25]), "=r"(r[26]), "=r"(r[27]), "=r"(r[28]), "=r"(r[29]),
          "=r"(r[30]), "=r"(r[31])
        : "r"(tmem_addr));
}

__device__ __forceinline__ void tc_st_x32(uint32_t tmem_addr, const uint32_t* r) {
    asm volatile(
        "tcgen05.st.sync.aligned.32x32b.x32.b32 [%0], "
        "{%1, %2, %3, %4, %5, %6, %7, %8, %9, %10, %11, %12, %13, %14, %15, %16, "
        " %17, %18, %19, %20, %21, %22, %23, %24, %25, %26, %27, %28, %29, %30, %31, %32};"
        :: "r"(tmem_addr),
           "r"(r[0]), "r"(r[1]), "r"(r[2]), "r"(r[3]), "r"(r[4]), "r"(r[5]),
           "r"(r[6]), "r"(r[7]), "r"(r[8]), "r"(r[9]), "r"(r[10]), "r"(r[11]),
           "r"(r[12]), "r"(r[13]), "r"(r[14]), "r"(r[15]), "r"(r[16]), "r"(r[17]),
           "r"(r[18]), "r"(r[19]), "r"(r[20]), "r"(r[21]), "r"(r[22]), "r"(r[23]),
           "r"(r[24]), "r"(r[25]), "r"(r[26]), "r"(r[27]), "r"(r[28]), "r"(r[29]),
           "r"(r[30]), "r"(r[31])
        : "memory");
}

#define SW128(off) ((off) ^ (((off) >> 3) & 0x70))
__device__ __forceinline__ uint64_t make_desc_sw128(uint32_t base_addr) {
    const uint64_t BASE =
        (uint64_t(2) << 61) | (uint64_t(1) << 46) | (uint64_t(64) << 32) | (uint64_t(1) << 16);
    return BASE | ((uint64_t)(base_addr >> 4) & 0x3FFF);
}
#define IDESC_F16(Mv, Nv) ((1u << 4) | (1u << 7) | (1u << 10) | (((Nv) / 8) << 17) | (((Mv) / 16) << 24))
#define IDESC_128x128 IDESC_F16(128, 128)
#endif  // __CUDA_ARCH_FEAT_SM103_ALL

// ---------------- kernel 1: GroupNorm partial sums + fused finalize ----------------
__global__ void gn_part_kernel(const float* __restrict__ x) {
    int bg = blockIdx.x;
    int part = blockIdx.y;
    int b = bg / G_;
    int g = bg % G_;
    const float* xp = x + (size_t)b * L_ * C_ + g * CG_;

    float s = 0.f, s2 = 0.f;
    #pragma unroll
    for (int t = 0; t < 8; t++) {
        int i = t * 256 + threadIdx.x;
        int l = part * 256 + (i >> 3);
        int c4 = (i & 7) * 4;
        float4 v = *(const float4*)(xp + (size_t)l * C_ + c4);
        s  += v.x + v.y + v.z + v.w;
        s2 += v.x * v.x + v.y * v.y + v.z * v.z + v.w * v.w;
    }
    #pragma unroll
    for (int o = 16; o > 0; o >>= 1) {
        s  += __shfl_down_sync(0xFFFFFFFFu, s, o);
        s2 += __shfl_down_sync(0xFFFFFFFFu, s2, o);
    }
    __shared__ float sh[2][8];
    int w = threadIdx.x >> 5, ln = threadIdx.x & 31;
    if (ln == 0) { sh[0][w] = s; sh[1][w] = s2; }
    __syncthreads();
    if (w == 0 && ln < 8) {
        s = sh[0][ln]; s2 = sh[1][ln];
        #pragma unroll
        for (int o = 4; o > 0; o >>= 1) {
            s  += __shfl_down_sync(0x000000FFu, s, o);
            s2 += __shfl_down_sync(0x000000FFu, s2, o);
        }
        if (ln == 0) {
            g_part[(bg * 8 + part) * 2 + 0] = s;
            g_part[(bg * 8 + part) * 2 + 1] = s2;
            __threadfence();
            int done = atomicAdd(&g_cnt[bg], 1);
            if (done == 7) {
                __threadfence();
                float ts = 0.f, ts2 = 0.f;
                #pragma unroll
                for (int p2 = 0; p2 < 8; p2++) {
                    ts  += g_part[(bg * 8 + p2) * 2 + 0];
                    ts2 += g_part[(bg * 8 + p2) * 2 + 1];
                }
                const float inv_n = 1.0f / (float)(L_ * CG_);
                float mu  = ts * inv_n;
                float var = ts2 * inv_n - mu * mu;
                g_stats[bg * 2 + 0] = mu;
                g_stats[bg * 2 + 1] = rsqrtf(var + 1e-6f);
                g_cnt[bg] = 0;
            }
        }
    }
}

// ---------------- kernel 2: apply GroupNorm ----------------
__global__ void gn_apply_kernel(const float* __restrict__ x,
                                const float* __restrict__ gamma,
                                const float* __restrict__ beta) {
    size_t i = (size_t)blockIdx.x * blockDim.x + threadIdx.x;
    size_t base = i * 4;
    if (base >= (size_t)ML * C_) return;
    int c  = (int)(base % C_);
    int bl = (int)(base / C_);
    int b  = bl >> 11;
    int g  = c >> 5;
    float mu = g_stats[(b * G_ + g) * 2 + 0];
    float rs = g_stats[(b * G_ + g) * 2 + 1];
    float4 xv = *(const float4*)(x + base);
    float4 gv = *(const float4*)(gamma + c);
    float4 bv = *(const float4*)(beta + c);
    float4 r;
    r.x = (xv.x - mu) * rs * gv.x + bv.x;
    r.y = (xv.y - mu) * rs * gv.y + bv.y;
    r.z = (xv.z - mu) * rs * gv.z + bv.z;
    r.w = (xv.w - mu) * rs * gv.w + bv.w;
#ifndef __CUDA_ARCH_FEAT_SM103_ALL
    *(float4*)(g_xn + base) = r;
#endif
    ((__nv_bfloat162*)g_xn_bf)[2 * i]     = __floats2bfloat162_rn(r.x, r.y);
    ((__nv_bfloat162*)g_xn_bf)[2 * i + 1] = __floats2bfloat162_rn(r.z, r.w);
}

// ---------------- merged weight transpose + convert ----------------
__global__ void wtrans_kernel(const float* __restrict__ wq, const float* __restrict__ wp) {
    __shared__ float tile[32][33];
    int bx = blockIdx.x;
    const float* src;
    bf16* dst;
    int N, n0;
    if (bx < N3C / 32) { src = wq; dst = g_wqT; N = N3C; n0 = bx * 32; }
    else               { src = wp; dst = g_wpT; N = C_;  n0 = (bx - N3C / 32) * 32; }
    int k0 = blockIdx.y * 32;
    int tx = threadIdx.x, ty = threadIdx.y;
    #pragma unroll
    for (int i = 0; i < 32; i += 8)
        tile[ty + i][tx] = src[(size_t)(k0 + ty + i) * N + n0 + tx];
    __syncthreads();
    #pragma unroll
    for (int i = 0; i < 32; i += 8)
        dst[(size_t)(n0 + ty + i) * C_ + k0 + tx] = __float2bfloat16(tile[tx][ty + i]);
}

// ---------------- V^T transpose (feature path) ----------------
__global__ void vtrans_kernel() {
#ifdef __CUDA_ARCH_FEAT_SM103_ALL
    __shared__ unsigned short tile[32][33];
    int l0 = blockIdx.x * 32;
    int d0 = blockIdx.y * 32;
    int bh = blockIdx.z;
    int b = bh >> 4, h = bh & 15;
    int tx = threadIdx.x, ty = threadIdx.y;
    const unsigned short* src = (const unsigned short*)g_qkv_bf
        + (size_t)b * L_ * N3C + h * (3 * HD_) + 2 * HD_;
    #pragma unroll
    for (int i = 0; i < 32; i += 8)
        tile[ty + i][tx] = src[(size_t)(l0 + ty + i) * N3C + d0 + tx];
    __syncthreads();
    unsigned short* dst = (unsigned short*)g_vT + (size_t)bh * HD_ * L_;
    #pragma unroll
    for (int i = 0; i < 32; i += 8)
        dst[(size_t)(d0 + ty + i) * L_ + l0 + tx] = tile[tx][ty + i];
#endif
}

// ---------------- kernel 3/5: GEMM, dual path. CTA tile 128x256 (feature path) ----------------
// grid = (N/256, M/128)
template <int EPI>
__global__ __launch_bounds__(256) void gemm_kernel(
    const float* __restrict__ W,
    const float* __restrict__ bias,
    const float* __restrict__ resid,
    float*       __restrict__ OutParam,
    int N, int K)
{
    const float rsqrt2 = 0.70710678118654752f;
    int tid = threadIdx.x;
    int bm = blockIdx.y * 128;

#ifdef __CUDA_ARCH_FEAT_SM103_ALL
    int bn = blockIdx.x * 256;
    __shared__ __align__(1024) bf16 sA[2][128 * 64];        // 32 KB
    __shared__ __align__(1024) bf16 sB[2][2][128 * 64];     // 64 KB
    __shared__ float bias_s[256];
    __shared__ __align__(8) uint64_t mbar_store[2];
    __shared__ uint32_t tmem_ptr_store;

    const bf16* A  = (EPI == 0) ? g_xn_bf : g_att_bf;
    const bf16* WT = (EPI == 0) ? g_wqT   : g_wpT;

    int wid = tid >> 5;
    int lane = tid & 31;
    uint32_t mbar0 = smem_u32(&mbar_store[0]);
    uint32_t mbar1 = smem_u32(&mbar_store[1]);
    uint32_t tptr_addr = smem_u32(&tmem_ptr_store);

    if (wid == 0) TC_ALLOC(tptr_addr, 256);
    if (tid == 0) { MBAR_INIT(mbar0, 1); MBAR_INIT(mbar1, 1); }
    bias_s[tid] = bias[bn + tid];
    __syncthreads();
    uint32_t tmem_base;
    asm volatile("ld.shared.b32 %0, [%1];" : "=r"(tmem_base) : "r"(tptr_addr));

    uint64_t a_desc[2] = { make_desc_sw128(smem_u32(sA[0])), make_desc_sw128(smem_u32(sA[1])) };
    uint64_t b_desc[2][2] = {
        { make_desc_sw128(smem_u32(sB[0][0])), make_desc_sw128(smem_u32(sB[0][1])) },
        { make_desc_sw128(smem_u32(sB[1][0])), make_desc_sw128(smem_u32(sB[1][1])) } };

    const int NCHUNK = K / 64;

    // ---- prefetch chunk 0 ----
    uint4 ra[4], rb[8];
    #pragma unroll
    for (int t = 0; t < 4; t++) {
        int i = t * 256 + tid;
        int r = i >> 3;
        int c8 = (i & 7) * 8;
        ra[t] = *(const uint4*)(A + (size_t)(bm + r) * K + c8);
    }
    #pragma unroll
    for (int t = 0; t < 8; t++) {
        int i = t * 256 + tid;
        int r = i >> 3;                 // 0..255
        int c8 = (i & 7) * 8;
        rb[t] = *(const uint4*)(WT + (size_t)(bn + r) * K + c8);
    }

    for (int ch = 0; ch < NCHUNK; ch++) {
        int buf = ch & 1;
        uint32_t mb = buf ? mbar1 : mbar0;
        if (ch >= 2) mbar_wait(mb, (uint32_t)(((ch >> 1) - 1) & 1));

        // store prefetched regs into smem
        #pragma unroll
        for (int t = 0; t < 4; t++) {
            int i = t * 256 + tid;
            int r = i >> 3;
            int c8 = (i & 7) * 8;
            uint32_t sw = SW128((uint32_t)((r & 127) * 128 + c8 * 2));
            *(uint4*)((char*)sA[buf] + sw) = ra[t];
        }
        #pragma unroll
        for (int t = 0; t < 8; t++) {
            int i = t * 256 + tid;
            int r = i >> 3;
            int c8 = (i & 7) * 8;
            uint32_t sw = SW128((uint32_t)((r & 127) * 128 + c8 * 2));
            *(uint4*)((char*)sB[buf][r >> 7] + sw) = rb[t];
        }

        // prefetch chunk ch+1
        if (ch + 1 < NCHUNK) {
            int k0 = (ch + 1) * 64;
            #pragma unroll
            for (int t = 0; t < 4; t++) {
                int i = t * 256 + tid;
                int r = i >> 3;
                int c8 = (i & 7) * 8;
                ra[t] = *(const uint4*)(A + (size_t)(bm + r) * K + k0 + c8);
            }
            #pragma unroll
            for (int t = 0; t < 8; t++) {
                int i = t * 256 + tid;
                int r = i >> 3;
                int c8 = (i & 7) * 8;
                rb[t] = *(const uint4*)(WT + (size_t)(bn + r) * K + k0 + c8);
            }
        }

        FENCE_ASYNC_SHARED();
        __syncthreads();

        if (wid == 0 && elect_one()) {
            #pragma unroll
            for (int half = 0; half < 2; half++) {
                #pragma unroll
                for (int ks = 0; ks < 4; ks++) {
                    uint32_t en = (ch > 0 || ks > 0) ? 1u : 0u;
                    tc_mma_f16_ss(tmem_base + half * 128,
                                  a_desc[buf] + ks * 2, b_desc[buf][half] + ks * 2,
                                  IDESC_128x128, en);
                }
            }
            TC_COMMIT(mb);
        }
    }

    mbar_wait(mbar1, 1u);
    TC_FENCE_AFTER();

    // epilogue: two 128-col tiles
    {
        int row = bm + (wid & 3) * 32 + lane;
        int chalf = (wid >> 2) * 64;
        #pragma unroll
        for (int half = 0; half < 2; half++) {
            #pragma unroll
            for (int cc = 0; cc < 2; cc++) {
                uint32_t d[32];
                tc_ld_x32(d, tmem_base + half * 128 + chalf + cc * 32);
                TC_WAIT_LD();
                int bcol = half * 128 + chalf + cc * 32;
                int colbase = bn + bcol;
                #pragma unroll
                for (int j = 0; j < 8; j++) {
                    float4 v;
                    v.x = __uint_as_float(d[4 * j + 0]) + bias_s[bcol + 4 * j + 0];
                    v.y = __uint_as_float(d[4 * j + 1]) + bias_s[bcol + 4 * j + 1];
                    v.z = __uint_as_float(d[4 * j + 2]) + bias_s[bcol + 4 * j + 2];
                    v.w = __uint_as_float(d[4 * j + 3]) + bias_s[bcol + 4 * j + 3];
                    if (EPI == 1) {
                        float4 rv = *(const float4*)(resid + (size_t)row * N + colbase + 4 * j);
                        v.x = (v.x + rv.x) * rsqrt2;
                        v.y = (v.y + rv.y) * rsqrt2;
                        v.z = (v.z + rv.z) * rsqrt2;
                        v.w = (v.w + rv.w) * rsqrt2;
                        *(float4*)(OutParam + (size_t)row * N + colbase + 4 * j) = v;
                    } else {
                        __nv_bfloat162 lo = __floats2bfloat162_rn(v.x, v.y);
                        __nv_bfloat162 hi = __floats2bfloat162_rn(v.z, v.w);
                        uint2 pk = make_uint2(*(uint32_t*)&lo, *(uint32_t*)&hi);
                        *(uint2*)(g_qkv_bf + (size_t)row * N + colbase + 4 * j) = pk;
                    }
                }
            }
        }
    }
    TC_FENCE_BEFORE();
    __syncthreads();
    if (tid == 0) { MBAR_INVAL(mbar0); MBAR_INVAL(mbar1); }
    __syncthreads();
    if (wid == 0) {
        TC_RELINQ();
        TC_DEALLOC(tmem_base, 256);
    }
#else
    // fp32 FFMA fallback (R3-proven body, looped over two 128-col halves)
    const float* A = (EPI == 0) ? g_xn : g_att;
    float* Cout    = (EPI == 0) ? g_qkv : OutParam;

    __shared__ float As[8][128];
    __shared__ float Bs[8][128];

    int tx = tid & 15;
    int ty = tid >> 4;

    for (int nh = 0; nh < 2; nh++) {
        int bn = blockIdx.x * 256 + nh * 128;

        float acc[8][8];
        #pragma unroll
        for (int i = 0; i < 8; i++)
            #pragma unroll
            for (int j = 0; j < 8; j++) acc[i][j] = 0.f;

        int arow = tid >> 1;
        int acol = (tid & 1) * 4;
        int brow = tid >> 5;
        int bcol = (tid & 31) * 4;

        const float* Aptr = A + (size_t)(bm + arow) * K + acol;
        const float* Bptr = W + (size_t)brow * N + bn + bcol;

        for (int k0 = 0; k0 < K; k0 += 8) {
            float4 av = *(const float4*)(Aptr + k0);
            float4 bv = *(const float4*)(Bptr + (size_t)k0 * N);
            As[acol + 0][arow] = av.x;
            As[acol + 1][arow] = av.y;
            As[acol + 2][arow] = av.z;
            As[acol + 3][arow] = av.w;
            *(float4*)&Bs[brow][bcol] = bv;
            __syncthreads();
            #pragma unroll
            for (int kk = 0; kk < 8; kk++) {
                float a[8], bfv[8];
                #pragma unroll
                for (int i = 0; i < 8; i++) a[i] = As[kk][ty * 8 + i];
                #pragma unroll
                for (int i = 0; i < 8; i++) bfv[i] = Bs[kk][tx * 8 + i];
                #pragma unroll
                for (int i = 0; i < 8; i++)
                    #pragma unroll
                    for (int j = 0; j < 8; j++)
                        acc[i][j] += a[i] * bfv[j];
            }
            __syncthreads();
        }

        #pragma unroll
        for (int i = 0; i < 8; i++) {
            int row = bm + ty * 8 + i;
            #pragma unroll
            for (int j = 0; j < 8; j += 4) {
                int col = bn + tx * 8 + j;
                float4 bb = *(const float4*)(bias + col);
                float4 v;
                v.x = acc[i][j + 0] + bb.x;
                v.y = acc[i][j + 1] + bb.y;
                v.z = acc[i][j + 2] + bb.z;
                v.w = acc[i][j + 3] + bb.w;
                if (EPI == 1) {
                    float4 rv = *(const float4*)(resid + (size_t)row * N + col);
                    v.x = (v.x + rv.x) * rsqrt2;
                    v.y = (v.y + rv.y) * rsqrt2;
                    v.z = (v.z + rv.z) * rsqrt2;
                    v.w = (v.w + rv.w) * rsqrt2;
                }
                *(float4*)(Cout + (size_t)row * N + col) = v;
            }
        }
        __syncthreads();
    }
#endif
}

// ---------------- kernel 4: flash attention, dual path (R15/R16 champion config) ----------------
__global__ __launch_bounds__(128) void flash_kernel() {
    int bh = blockIdx.y;
    int b = bh >> 4;
    int h = bh & 15;
    int tid = threadIdx.x;

#ifdef __CUDA_ARCH_FEAT_SM103_ALL
    __shared__ __align__(1024) bf16 sQ[128 * 64];
    __shared__ __align__(1024) bf16 sK[128 * 64];
    __shared__ __align__(1024) bf16 sV[64 * 128];
    __shared__ __align__(8) uint64_t mbar_store[2];
    __shared__ uint32_t tmem_ptr_store;

    int wid = tid >> 5;
    int bm = blockIdx.x * 128;

    uint32_t mbarS = smem_u32(&mbar_store[0]);
    uint32_t mbarO = smem_u32(&mbar_store[1]);
    uint32_t tptr_addr = smem_u32(&tmem_ptr_store);

    if (wid == 0) TC_ALLOC(tptr_addr, 256);
    if (tid == 0) { MBAR_INIT(mbarS, 1); MBAR_INIT(mbarO, 1); }
    __syncthreads();
    uint32_t tmem_base;
    asm volatile("ld.shared.b32 %0, [%1];" : "=r"(tmem_base) : "r"(tptr_addr));

    const uint32_t S0 = tmem_base + 0;
    const uint32_t P0 = tmem_base + 128;
    const uint32_t O0 = tmem_base + 192;

    const bf16* qkvb = g_qkv_bf + (size_t)b * L_ * N3C + h * (3 * HD_);

    uint64_t q_desc = make_desc_sw128(smem_u32(sQ));
    uint64_t k_desc = make_desc_sw128(smem_u32(sK));
    uint64_t v_desc = make_desc_sw128(smem_u32(sV));
    const uint32_t IDESC_S = IDESC_F16(128, 128);
    const uint32_t IDESC_O = IDESC_F16(128, 64);

    // ---- prologue: load Q + K[0], issue S(0) ----
    #pragma unroll
    for (int t = 0; t < 8; t++) {
        int i = t * 128 + tid;
        int r = i >> 3;
        int c8 = (i & 7) * 8;
        uint32_t sw = SW128((uint32_t)(r * 128 + c8 * 2));
        *(uint4*)((char*)sQ + sw) = *(const uint4*)(qkvb + (size_t)(bm + r) * N3C + c8);
        *(uint4*)((char*)sK + sw) = *(const uint4*)(qkvb + HD_ + (size_t)r * N3C + c8);
    }
    FENCE_ASYNC_SHARED();
    __syncthreads();
    if (wid == 0 && elect_one()) {
        #pragma unroll
        for (int ks = 0; ks < 4; ks++)
            tc_mma_f16_ss(S0, q_desc + ks * 2, k_desc + ks * 2, IDESC_S, ks > 0);
        TC_COMMIT(mbarS);
    }

    float lsum = 0.f;
    const unsigned short* vT = (const unsigned short*)g_vT + (size_t)bh * HD_ * L_;
    const float SCALE_LOG2E = 0.125f * 1.44269504088896f;
    uint32_t woff = (uint32_t)wid << 21;

    for (int ch = 0; ch < 16; ch++) {
        mbar_wait(mbarS, (uint32_t)(ch & 1));
        TC_FENCE_AFTER();
        uint32_t sr[128];
        #pragma unroll
        for (int cc = 0; cc < 4; cc++) tc_ld_x32(sr + cc * 32, S0 + cc * 32);
        TC_WAIT_LD();

        if (ch < 15) {
            #pragma unroll
            for (int t = 0; t < 8; t++) {
                int i = t * 128 + tid;
                int r = i >> 3;
                int c8 = (i & 7) * 8;
                uint32_t sw = SW128((uint32_t)(r * 128 + c8 * 2));
                *(uint4*)((char*)sK + sw) =
                    *(const uint4*)(qkvb + HD_ + (size_t)((ch + 1) * 128 + r) * N3C + c8);
            }
            FENCE_ASYNC_SHARED();
            __syncthreads();
            if (wid == 0 && elect_one()) {
                #pragma unroll
                for (int ks = 0; ks < 4; ks++)
                    tc_mma_f16_ss(S0, q_desc + ks * 2, k_desc + ks * 2, IDESC_S, ks > 0);
                TC_COMMIT(mbarS);
            }
        }

        if (ch > 0) mbar_wait(mbarO, (uint32_t)((ch - 1) & 1));
        #pragma unroll
        for (int t = 0; t < 8; t++) {
            int i = t * 128 + tid;
            int d = i >> 4;
            int kk = (i & 15) * 8;
            int atom_col = kk >> 6;
            int inner_col = kk & 63;
            uint32_t off = (uint32_t)(((d >> 3) + atom_col * 8) * 1024 + (d & 7) * 128 + inner_col * 2);
            uint32_t sw = SW128(off);
            *(uint4*)((char*)sV + sw) = *(const uint4*)(vT + (size_t)d * L_ + ch * 128 + kk);
        }

        uint32_t p[64];
        #pragma unroll
        for (int j = 0; j < 64; j++) {
            float e0 = exp2f(__uint_as_float(sr[2 * j + 0]) * SCALE_LOG2E);
            float e1 = exp2f(__uint_as_float(sr[2 * j + 1]) * SCALE_LOG2E);
            lsum += e0 + e1;
            __nv_bfloat162 pk = __floats2bfloat162_rn(e0, e1);
            p[j] = *(uint32_t*)&pk;
        }

        {
            tc_st_x32(P0 + woff, p);
            tc_st_x32(P0 + 32 + woff, p + 32);
            TC_WAIT_ST();
        }
        FENCE_ASYNC_SHARED();
        TC_FENCE_BEFORE();
        __syncthreads();
        if (wid == 0 && elect_one()) {
            TC_FENCE_AFTER();
            #pragma unroll
            for (int s8 = 0; s8 < 8; s8++) {
                uint64_t boff = (uint64_t)((s8 >> 2) * 512 + (s8 & 3) * 2);
                tc_mma_f16_ts(O0, P0 + s8 * 8, v_desc + boff, IDESC_O,
                              (ch > 0 || s8 > 0));
            }
            TC_COMMIT(mbarO);
        }
        __syncthreads();
    }

    // ---- epilogue ----
    mbar_wait(mbarO, 1u);
    TC_FENCE_AFTER();
    {
        uint32_t d0[32], d1[32];
        tc_ld_x32(d0, O0);
        tc_ld_x32(d1, O0 + 32);
        TC_WAIT_LD();
        float inv = 1.f / lsum;
        bf16* op = g_att_bf + (size_t)(b * L_ + bm + tid) * C_ + h * HD_;
        #pragma unroll
        for (int j = 0; j < 16; j++) {
            __nv_bfloat162 a = __floats2bfloat162_rn(
                __uint_as_float(d0[2 * j]) * inv, __uint_as_float(d0[2 * j + 1]) * inv);
            ((__nv_bfloat162*)op)[j] = a;
        }
        #pragma unroll
        for (int j = 0; j < 16; j++) {
            __nv_bfloat162 a = __floats2bfloat162_rn(
                __uint_as_float(d1[2 * j]) * inv, __uint_as_float(d1[2 * j + 1]) * inv);
            ((__nv_bfloat162*)op)[16 + j] = a;
        }
    }
    TC_FENCE_BEFORE();
    __syncthreads();
    if (tid == 0) { MBAR_INVAL(mbarS); MBAR_INVAL(mbarO); }
    __syncthreads();
    if (wid == 0) {
        TC_RELINQ();
        TC_DEALLOC(tmem_base, 256);
    }
#else
    // ============ scalar fallback (R3-proven) ============
    __shared__ float Ks[32 * 64];
    __shared__ float Vs[32 * 64];

    int qrow = blockIdx.x * 128 + tid;

    const float* base = g_qkv + (size_t)b * L_ * N3C;
    const float* qptr = base + (size_t)qrow * N3C + h * (3 * HD_);
    const float* kbase = base + h * (3 * HD_) + HD_;
    const float* vbase = base + h * (3 * HD_) + 2 * HD_;

    float q[HD_];
    #pragma unroll
    for (int d4 = 0; d4 < HD_ / 4; d4++) {
        float4 t = *(const float4*)(qptr + d4 * 4);
        q[4 * d4 + 0] = t.x * 0.125f;
        q[4 * d4 + 1] = t.y * 0.125f;
        q[4 * d4 + 2] = t.z * 0.125f;
        q[4 * d4 + 3] = t.w * 0.125f;
    }
    float o[HD_];
    #pragma unroll
    for (int d = 0; d < HD_; d++) o[d] = 0.f;
    float m = -1e30f, l = 0.f;

    for (int kb = 0; kb < L_ / 32; kb++) {
        __syncthreads();
        #pragma unroll
        for (int t = 0; t < 4; t++) {
            int idx = t * 128 + tid;
            int r = idx >> 4;
            int c4 = (idx & 15) * 4;
            size_t goff = (size_t)(kb * 32 + r) * N3C + c4;
            *(float4*)&Ks[r * 64 + c4] = *(const float4*)(kbase + goff);
            *(float4*)&Vs[r * 64 + c4] = *(const float4*)(vbase + goff);
        }
        __syncthreads();

        float s[32];
        #pragma unroll
        for (int j = 0; j < 32; j++) {
            float accv = 0.f;
            #pragma unroll
            for (int d = 0; d < HD_; d++) accv += q[d] * Ks[j * 64 + d];
            s[j] = accv;
        }
        float mnew = m;
        #pragma unroll
        for (int j = 0; j < 32; j++) mnew = fmaxf(mnew, s[j]);
        float corr = __expf(m - mnew);
        l *= corr;
        #pragma unroll
        for (int d = 0; d < HD_; d++) o[d] *= corr;
        #pragma unroll
        for (int j = 0; j < 32; j++) {
            float pp = __expf(s[j] - mnew);
            l += pp;
            #pragma unroll
            for (int d = 0; d < HD_; d++) o[d] += pp * Vs[j * 64 + d];
        }
        m = mnew;
    }

    float inv = 1.f / l;
    size_t obase = (size_t)(b * L_ + qrow) * C_ + h * HD_;
    float* opf = g_att + obase;
    bf16* opb = g_att_bf + obase;
    #pragma unroll
    for (int d4 = 0; d4 < HD_ / 4; d4++) {
        float4 t;
        t.x = o[4 * d4 + 0] * inv;
        t.y = o[4 * d4 + 1] * inv;
        t.z = o[4 * d4 + 2] * inv;
        t.w = o[4 * d4 + 3] * inv;
        *(float4*)(opf + 4 * d4) = t;
        ((__nv_bfloat162*)opb)[2 * d4]     = __floats2bfloat162_rn(t.x, t.y);
        ((__nv_bfloat162*)opb)[2 * d4 + 1] = __floats2bfloat162_rn(t.z, t.w);
    }
#endif
}

// ---------------- launcher ----------------
extern "C" void kernel_launch(void* const* d_in, const int* in_sizes, int n_in,
                              void* d_out, int out_size) {
    const float* x        = (const float*)d_in[0];
    const float* gn_scale = (const float*)d_in[1];
    const float* gn_bias  = (const float*)d_in[2];
    const float* qkv_w    = (const float*)d_in[3];
    const float* qkv_b    = (const float*)d_in[4];
    const float* proj_w   = (const float*)d_in[5];
    const float* proj_b   = (const float*)d_in[6];
    float* out = (float*)d_out;

    // 0) merged weight transpose+convert
    {
        dim3 blk(32, 8);
        dim3 gw(N3C / 32 + C_ / 32, C_ / 32);
        wtrans_kernel<<<gw, blk>>>(qkv_w, proj_w);
    }

    // 1) GroupNorm stats
    {
        dim3 gpart(B_ * G_, 8);
        gn_part_kernel<<<gpart, 256>>>(x);
    }

    // 2) apply GroupNorm
    {
        int total4 = ML * C_ / 4;
        gn_apply_kernel<<<(total4 + 255) / 256, 256>>>(x, gn_scale, gn_bias);
    }

    // 3) QKV GEMM (CTA tile 128x256)
    {
        dim3 grid(N3C / 256, ML / 128);
        gemm_kernel<0><<<grid, 256>>>(qkv_w, qkv_b, nullptr, nullptr, N3C, C_);
    }

    // 3.5) V^T transpose
    {
        dim3 blk(32, 8);
        dim3 gv(L_ / 32, HD_ / 32, B_ * H_);
        vtrans_kernel<<<gv, blk>>>();
    }

    // 4) flash attention
    {
        dim3 grid(L_ / 128, B_ * H_);
        flash_kernel<<<grid, 128>>>();
    }

    // 5) proj GEMM + residual (CTA tile 128x256)
    {
        dim3 grid(C_ / 256, ML / 128);
        gemm_kernel<1><<<grid, 256>>>(proj_w, proj_b, x, out, C_, C_);
    }
}